// round 2
// baseline (speedup 1.0000x reference)
#include <cuda_runtime.h>
#include <math.h>

#define BB 8
#define NN 1024
#define CC 768
#define HH 12
#define ZZ 64
#define BH (BB*HH)
#define SCALE 0.125f

// ---------------- scratch (no allocations allowed) ----------------
__device__ float g_Q [BB*NN*CC];
__device__ float g_K [BB*NN*CC];
__device__ float g_U1[CC*CC];        // U1t[e][c] = sum_d Wp[e,d]*Wq[c,d]
__device__ float g_U2[CC*CC];        // U2t[e][c] = sum_d Wp[e,d]*Wk[c,d]
__device__ float g_Ck[BB*NN*CC];     // (A^T K) flattened  [b][t][h*64+z]
__device__ float g_Cq[BB*NN*CC];     // (A^T Q) flattened
__device__ float g_m [BH*NN];        // softmax row max
__device__ float g_il[BH*NN];        // softmax 1/row-sum

// =============================================================================
// Generic C = A(MxK) * B(NxK)^T, 128x128x8 tiles, 8x8 interleaved micro-tile
// =============================================================================
__global__ __launch_bounds__(256) void gemm_abt128(
    const float* __restrict__ A, const float* __restrict__ B,
    float* __restrict__ C, int M, int N, int K)
{
    __shared__ float As[128][9];
    __shared__ float Bs[128][9];
    const int tid = threadIdx.x;
    const int tx = tid & 15, ty = tid >> 4;
    const int m0 = blockIdx.x * 128, n0 = blockIdx.y * 128;
    const int lr = tid >> 1, lc = (tid & 1) << 2;

    float acc[8][8];
#pragma unroll
    for (int i = 0; i < 8; i++)
#pragma unroll
        for (int j = 0; j < 8; j++) acc[i][j] = 0.0f;

    for (int k0 = 0; k0 < K; k0 += 8) {
        float4 va = *reinterpret_cast<const float4*>(A + (size_t)(m0 + lr) * K + k0 + lc);
        float4 vb = *reinterpret_cast<const float4*>(B + (size_t)(n0 + lr) * K + k0 + lc);
        As[lr][lc] = va.x; As[lr][lc+1] = va.y; As[lr][lc+2] = va.z; As[lr][lc+3] = va.w;
        Bs[lr][lc] = vb.x; Bs[lr][lc+1] = vb.y; Bs[lr][lc+2] = vb.z; Bs[lr][lc+3] = vb.w;
        __syncthreads();
#pragma unroll
        for (int k = 0; k < 8; k++) {
            float a[8], b[8];
#pragma unroll
            for (int i = 0; i < 8; i++) a[i] = As[ty + i*16][k];
#pragma unroll
            for (int j = 0; j < 8; j++) b[j] = Bs[tx + j*16][k];
#pragma unroll
            for (int i = 0; i < 8; i++)
#pragma unroll
                for (int j = 0; j < 8; j++) acc[i][j] += a[i] * b[j];
        }
        __syncthreads();
    }
#pragma unroll
    for (int i = 0; i < 8; i++)
#pragma unroll
        for (int j = 0; j < 8; j++)
            C[(size_t)(m0 + ty + i*16) * N + n0 + tx + j*16] = acc[i][j];
}

// =============================================================================
// Small-tile version (64x64x16) for the 768x768 weight precompute GEMMs
// =============================================================================
__global__ __launch_bounds__(256) void gemm_abt64(
    const float* __restrict__ A, const float* __restrict__ B,
    float* __restrict__ C, int M, int N, int K)
{
    __shared__ float As[64][17];
    __shared__ float Bs[64][17];
    const int tid = threadIdx.x;
    const int tx = tid & 15, ty = tid >> 4;
    const int m0 = blockIdx.x * 64, n0 = blockIdx.y * 64;
    const int lr = tid >> 2, lc = (tid & 3) << 2;

    float acc[4][4];
#pragma unroll
    for (int i = 0; i < 4; i++)
#pragma unroll
        for (int j = 0; j < 4; j++) acc[i][j] = 0.0f;

    for (int k0 = 0; k0 < K; k0 += 16) {
        float4 va = *reinterpret_cast<const float4*>(A + (size_t)(m0 + lr) * K + k0 + lc);
        float4 vb = *reinterpret_cast<const float4*>(B + (size_t)(n0 + lr) * K + k0 + lc);
        As[lr][lc] = va.x; As[lr][lc+1] = va.y; As[lr][lc+2] = va.z; As[lr][lc+3] = va.w;
        Bs[lr][lc] = vb.x; Bs[lr][lc+1] = vb.y; Bs[lr][lc+2] = vb.z; Bs[lr][lc+3] = vb.w;
        __syncthreads();
#pragma unroll
        for (int k = 0; k < 16; k++) {
            float a[4], b[4];
#pragma unroll
            for (int i = 0; i < 4; i++) a[i] = As[ty + i*16][k];
#pragma unroll
            for (int j = 0; j < 4; j++) b[j] = Bs[tx + j*16][k];
#pragma unroll
            for (int i = 0; i < 4; i++)
#pragma unroll
                for (int j = 0; j < 4; j++) acc[i][j] += a[i] * b[j];
        }
        __syncthreads();
    }
#pragma unroll
    for (int i = 0; i < 4; i++)
#pragma unroll
        for (int j = 0; j < 4; j++)
            C[(size_t)(m0 + ty + i*16) * N + n0 + tx + j*16] = acc[i][j];
}

// =============================================================================
// Fused output: out = A1*B1^T + A2*B2^T + bias  (128x128x8 tiles)
// =============================================================================
__global__ __launch_bounds__(256) void gemm_dual128(
    const float* __restrict__ A1, const float* __restrict__ B1,
    const float* __restrict__ A2, const float* __restrict__ B2,
    const float* __restrict__ bias, float* __restrict__ C,
    int M, int N, int K)
{
    __shared__ float A1s[128][9], B1s[128][9], A2s[128][9], B2s[128][9];
    const int tid = threadIdx.x;
    const int tx = tid & 15, ty = tid >> 4;
    const int m0 = blockIdx.x * 128, n0 = blockIdx.y * 128;
    const int lr = tid >> 1, lc = (tid & 1) << 2;

    float acc[8][8];
#pragma unroll
    for (int i = 0; i < 8; i++)
#pragma unroll
        for (int j = 0; j < 8; j++) acc[i][j] = 0.0f;

    for (int k0 = 0; k0 < K; k0 += 8) {
        float4 v1 = *reinterpret_cast<const float4*>(A1 + (size_t)(m0 + lr) * K + k0 + lc);
        float4 w1 = *reinterpret_cast<const float4*>(B1 + (size_t)(n0 + lr) * K + k0 + lc);
        float4 v2 = *reinterpret_cast<const float4*>(A2 + (size_t)(m0 + lr) * K + k0 + lc);
        float4 w2 = *reinterpret_cast<const float4*>(B2 + (size_t)(n0 + lr) * K + k0 + lc);
        A1s[lr][lc] = v1.x; A1s[lr][lc+1] = v1.y; A1s[lr][lc+2] = v1.z; A1s[lr][lc+3] = v1.w;
        B1s[lr][lc] = w1.x; B1s[lr][lc+1] = w1.y; B1s[lr][lc+2] = w1.z; B1s[lr][lc+3] = w1.w;
        A2s[lr][lc] = v2.x; A2s[lr][lc+1] = v2.y; A2s[lr][lc+2] = v2.z; A2s[lr][lc+3] = v2.w;
        B2s[lr][lc] = w2.x; B2s[lr][lc+1] = w2.y; B2s[lr][lc+2] = w2.z; B2s[lr][lc+3] = w2.w;
        __syncthreads();
#pragma unroll
        for (int k = 0; k < 8; k++) {
            float a1[8], b1[8], a2[8], b2[8];
#pragma unroll
            for (int i = 0; i < 8; i++) { a1[i] = A1s[ty + i*16][k]; a2[i] = A2s[ty + i*16][k]; }
#pragma unroll
            for (int j = 0; j < 8; j++) { b1[j] = B1s[tx + j*16][k]; b2[j] = B2s[tx + j*16][k]; }
#pragma unroll
            for (int i = 0; i < 8; i++)
#pragma unroll
                for (int j = 0; j < 8; j++)
                    acc[i][j] += a1[i] * b1[j] + a2[i] * b2[j];
        }
        __syncthreads();
    }
#pragma unroll
    for (int i = 0; i < 8; i++)
#pragma unroll
        for (int j = 0; j < 8; j++)
            C[(size_t)(m0 + ty + i*16) * N + n0 + tx + j*16] =
                acc[i][j] + bias[n0 + tx + j*16];
}

// =============================================================================
// Pass A: per-row softmax stats m, 1/l over S = scale * Q K^T  (per b,h)
// Block: 64 q-rows, loops over all 1024 t in 64-tiles. 256 thr, 4x4 micro.
// =============================================================================
__global__ __launch_bounds__(256) void attn_stats()
{
    __shared__ float Qs[64][65];
    __shared__ float Ks[64][65];
    const int tid = threadIdx.x, tx = tid & 15, ty = tid >> 4;
    const int bh = blockIdx.y;
    const int b = bh / HH, h = bh - b * HH;
    const int q0 = blockIdx.x * 64;
    const float* Qbase = g_Q + (size_t)b * NN * CC + h * ZZ;
    const float* Kbase = g_K + (size_t)b * NN * CC + h * ZZ;

    for (int i = tid; i < 64 * 16; i += 256) {
        int r = i >> 4, c = (i & 15) << 2;
        float4 v = *reinterpret_cast<const float4*>(Qbase + (size_t)(q0 + r) * CC + c);
        Qs[r][c] = v.x; Qs[r][c+1] = v.y; Qs[r][c+2] = v.z; Qs[r][c+3] = v.w;
    }

    float rm[4], rl[4];
#pragma unroll
    for (int i = 0; i < 4; i++) { rm[i] = -INFINITY; rl[i] = 0.0f; }

    for (int t0 = 0; t0 < NN; t0 += 64) {
        for (int i = tid; i < 64 * 16; i += 256) {
            int r = i >> 4, c = (i & 15) << 2;
            float4 v = *reinterpret_cast<const float4*>(Kbase + (size_t)(t0 + r) * CC + c);
            Ks[r][c] = v.x; Ks[r][c+1] = v.y; Ks[r][c+2] = v.z; Ks[r][c+3] = v.w;
        }
        __syncthreads();

        float s[4][4];
#pragma unroll
        for (int i = 0; i < 4; i++)
#pragma unroll
            for (int j = 0; j < 4; j++) s[i][j] = 0.0f;
#pragma unroll 8
        for (int z = 0; z < 64; z++) {
            float a[4], bb[4];
#pragma unroll
            for (int i = 0; i < 4; i++) a[i] = Qs[ty + i*16][z];
#pragma unroll
            for (int j = 0; j < 4; j++) bb[j] = Ks[tx + j*16][z];
#pragma unroll
            for (int i = 0; i < 4; i++)
#pragma unroll
                for (int j = 0; j < 4; j++) s[i][j] += a[i] * bb[j];
        }

#pragma unroll
        for (int i = 0; i < 4; i++) {
            float tmax = s[i][0];
#pragma unroll
            for (int j = 1; j < 4; j++) tmax = fmaxf(tmax, s[i][j]);
            tmax *= SCALE;
#pragma unroll
            for (int o = 8; o > 0; o >>= 1)
                tmax = fmaxf(tmax, __shfl_xor_sync(0xffffffffu, tmax, o));
            float nm = fmaxf(rm[i], tmax);
            float ls = 0.0f;
#pragma unroll
            for (int j = 0; j < 4; j++) ls += __expf(s[i][j] * SCALE - nm);
#pragma unroll
            for (int o = 8; o > 0; o >>= 1)
                ls += __shfl_xor_sync(0xffffffffu, ls, o);
            rl[i] = rl[i] * __expf(rm[i] - nm) + ls;
            rm[i] = nm;
        }
        __syncthreads();
    }

    if (tx == 0) {
#pragma unroll
        for (int i = 0; i < 4; i++) {
            int q = bh * NN + q0 + ty + i * 16;
            g_m[q]  = rm[i];
            g_il[q] = 1.0f / rl[i];
        }
    }
}

// =============================================================================
// Pass B: Ck = A^T K, Cq = A^T Q  (per b,h; block owns a 64-wide t-tile,
// streams q in 32-row tiles, P tile staged through SMEM for the transpose)
// =============================================================================
__global__ __launch_bounds__(256) void attn_pass()
{
    __shared__ float Kt[64][65];
    __shared__ float Qq[32][65];
    __shared__ float Kq[32][65];
    __shared__ float Ps[32][65];
    __shared__ float ms[32], ils[32];
    const int tid = threadIdx.x, tx = tid & 15, ty = tid >> 4;
    const int bh = blockIdx.y;
    const int b = bh / HH, h = bh - b * HH;
    const int t0 = blockIdx.x * 64;
    const float* Qbase = g_Q + (size_t)b * NN * CC + h * ZZ;
    const float* Kbase = g_K + (size_t)b * NN * CC + h * ZZ;

    for (int i = tid; i < 64 * 16; i += 256) {
        int r = i >> 4, c = (i & 15) << 2;
        float4 v = *reinterpret_cast<const float4*>(Kbase + (size_t)(t0 + r) * CC + c);
        Kt[r][c] = v.x; Kt[r][c+1] = v.y; Kt[r][c+2] = v.z; Kt[r][c+3] = v.w;
    }

    float ck[4][4], cq[4][4];
#pragma unroll
    for (int i = 0; i < 4; i++)
#pragma unroll
        for (int j = 0; j < 4; j++) { ck[i][j] = 0.0f; cq[i][j] = 0.0f; }

    for (int q0 = 0; q0 < NN; q0 += 32) {
        for (int i = tid; i < 32 * 16; i += 256) {
            int r = i >> 4, c = (i & 15) << 2;
            float4 v = *reinterpret_cast<const float4*>(Qbase + (size_t)(q0 + r) * CC + c);
            float4 w = *reinterpret_cast<const float4*>(Kbase + (size_t)(q0 + r) * CC + c);
            Qq[r][c] = v.x; Qq[r][c+1] = v.y; Qq[r][c+2] = v.z; Qq[r][c+3] = v.w;
            Kq[r][c] = w.x; Kq[r][c+1] = w.y; Kq[r][c+2] = w.z; Kq[r][c+3] = w.w;
        }
        if (tid < 32) {
            ms[tid]  = g_m [bh * NN + q0 + tid];
            ils[tid] = g_il[bh * NN + q0 + tid];
        }
        __syncthreads();

        // S tile: 32 q x 64 t
        float s[2][4];
#pragma unroll
        for (int i = 0; i < 2; i++)
#pragma unroll
            for (int j = 0; j < 4; j++) s[i][j] = 0.0f;
#pragma unroll 8
        for (int z = 0; z < 64; z++) {
            float a[2], bb[4];
            a[0] = Qq[ty][z];
            a[1] = Qq[ty + 16][z];
#pragma unroll
            for (int j = 0; j < 4; j++) bb[j] = Kt[tx + j*16][z];
#pragma unroll
            for (int i = 0; i < 2; i++)
#pragma unroll
                for (int j = 0; j < 4; j++) s[i][j] += a[i] * bb[j];
        }
#pragma unroll
        for (int i = 0; i < 2; i++) {
            int q = ty + i * 16;
            float mq = ms[q], iq = ils[q];
#pragma unroll
            for (int j = 0; j < 4; j++)
                Ps[q][tx + j*16] = __expf(s[i][j] * SCALE - mq) * iq;
        }
        __syncthreads();

        // accumulate P^T K and P^T Q : thread owns t = ty+i*16, z = tx+j*16
#pragma unroll 4
        for (int q = 0; q < 32; q++) {
            float p[4], kv[4], qv[4];
#pragma unroll
            for (int i = 0; i < 4; i++) p[i] = Ps[q][ty + i*16];
#pragma unroll
            for (int j = 0; j < 4; j++) { kv[j] = Kq[q][tx + j*16]; qv[j] = Qq[q][tx + j*16]; }
#pragma unroll
            for (int i = 0; i < 4; i++)
#pragma unroll
                for (int j = 0; j < 4; j++) {
                    ck[i][j] += p[i] * kv[j];
                    cq[i][j] += p[i] * qv[j];
                }
        }
        __syncthreads();
    }

    float* CkB = g_Ck + (size_t)b * NN * CC + h * ZZ;
    float* CqB = g_Cq + (size_t)b * NN * CC + h * ZZ;
#pragma unroll
    for (int i = 0; i < 4; i++)
#pragma unroll
        for (int j = 0; j < 4; j++) {
            int t = t0 + ty + i * 16, z = tx + j * 16;
            CkB[(size_t)t * CC + z] = ck[i][j];
            CqB[(size_t)t * CC + z] = cq[i][j];
        }
}

// =============================================================================
// host
// =============================================================================
extern "C" void kernel_launch(void* const* d_in, const int* in_sizes, int n_in,
                              void* d_out, int out_size)
{
    (void)in_sizes; (void)n_in; (void)out_size;
    const float* x  = (const float*)d_in[0];
    const float* Wq = (const float*)d_in[1];
    const float* Wk = (const float*)d_in[2];
    const float* Wp = (const float*)d_in[3];
    const float* bp = (const float*)d_in[4];
    float* out = (float*)d_out;

    float *pQ, *pK, *pU1, *pU2, *pCk, *pCq;
    cudaGetSymbolAddress((void**)&pQ,  g_Q);
    cudaGetSymbolAddress((void**)&pK,  g_K);
    cudaGetSymbolAddress((void**)&pU1, g_U1);
    cudaGetSymbolAddress((void**)&pU2, g_U2);
    cudaGetSymbolAddress((void**)&pCk, g_Ck);
    cudaGetSymbolAddress((void**)&pCq, g_Cq);

    // U1t = Wp * Wq^T, U2t = Wp * Wk^T   (tiny)
    gemm_abt64<<<dim3(CC/64, CC/64), 256>>>(Wp, Wq, pU1, CC, CC, CC);
    gemm_abt64<<<dim3(CC/64, CC/64), 256>>>(Wp, Wk, pU2, CC, CC, CC);
    // Q = x Wq^T, K = x Wk^T
    gemm_abt128<<<dim3(BB*NN/128, CC/128), 256>>>(x, Wq, pQ, BB*NN, CC, CC);
    gemm_abt128<<<dim3(BB*NN/128, CC/128), 256>>>(x, Wk, pK, BB*NN, CC, CC);
    // softmax stats
    attn_stats<<<dim3(NN/64, BH), 256>>>();
    // Ck = A^T K, Cq = A^T Q
    attn_pass<<<dim3(NN/64, BH), 256>>>();
    // out = Ck U1t^T + Cq U2t^T + bp
    gemm_dual128<<<dim3(BB*NN/128, CC/128), 256>>>(pCk, pU1, pCq, pU2, bp, out,
                                                   BB*NN, CC, CC);
}

// round 4
// speedup vs baseline: 1.6233x; 1.6233x over previous
#include <cuda_runtime.h>
#include <cuda_bf16.h>
#include <cstdint>
#include <math.h>

#define BB 8
#define NN 1024
#define CC 768
#define HH 12
#define ZZ 64
#define BH (BB*HH)
#define SCALE 0.125f
typedef __nv_bfloat16 bf16;

// ---------------- scratch ----------------
__device__ bf16 g_xh[BB*NN*CC], g_xl[BB*NN*CC];
__device__ bf16 g_Wqh[CC*CC], g_Wql[CC*CC], g_Wkh[CC*CC], g_Wkl[CC*CC];
__device__ bf16 g_Wph[CC*CC], g_Wpl[CC*CC];
__device__ bf16 g_U1h[CC*CC], g_U1l[CC*CC], g_U2h[CC*CC], g_U2l[CC*CC];
__device__ bf16 g_Qh[BH*NN*ZZ], g_Ql[BH*NN*ZZ], g_Kh[BH*NN*ZZ], g_Kl[BH*NN*ZZ];
__device__ bf16 g_Qth[BH*ZZ*NN], g_Qtl[BH*ZZ*NN], g_Kth[BH*ZZ*NN], g_Ktl[BH*ZZ*NN];
__device__ float g_S[(size_t)BH*NN*NN];
__device__ float g_m[BH*NN], g_il[BH*NN];
__device__ bf16 g_Ph[(size_t)BH*NN*NN], g_Pl[(size_t)BH*NN*NN];
__device__ bf16 g_Ckh[BB*NN*CC], g_Ckl[BB*NN*CC], g_Cqh[BB*NN*CC], g_Cql[BB*NN*CC];

// ---------------- helpers ----------------
#define SW(o) ((o) ^ (((o)>>3)&0x70))
#define OFF_AH 0
#define OFF_AL 16384
#define OFF_BH 32768
#define OFF_BL 49152
#define SMEM_BYTES 65536

__device__ __forceinline__ uint32_t smem_u32(const void* p){
    uint32_t a;
    asm("{ .reg .u64 t; cvta.to.shared.u64 t, %1; cvt.u32.u64 %0, t; }" : "=r"(a) : "l"(p));
    return a;
}
__device__ __forceinline__ void ldsm_x4(uint32_t& r0, uint32_t& r1, uint32_t& r2, uint32_t& r3, uint32_t addr){
    asm volatile("ldmatrix.sync.aligned.m8n8.x4.shared.b16 {%0,%1,%2,%3}, [%4];"
        : "=r"(r0), "=r"(r1), "=r"(r2), "=r"(r3) : "r"(addr));
}
__device__ __forceinline__ void mma16816(float c[4], const uint32_t a[4], uint32_t b0, uint32_t b1){
    asm volatile("mma.sync.aligned.m16n8k16.row.col.f32.bf16.bf16.f32 "
        "{%0,%1,%2,%3}, {%4,%5,%6,%7}, {%8,%9}, {%0,%1,%2,%3};"
        : "+f"(c[0]), "+f"(c[1]), "+f"(c[2]), "+f"(c[3])
        : "r"(a[0]), "r"(a[1]), "r"(a[2]), "r"(a[3]), "r"(b0), "r"(b1));
}

__device__ __forceinline__ float fexp(float x){
    float y = x * 1.4426950408889634f;
    float n = rintf(y);
    float f = y - n;
    float p = 1.3333558146428443e-3f;
    p = fmaf(p, f, 9.6181291076284772e-3f);
    p = fmaf(p, f, 5.5504108664821580e-2f);
    p = fmaf(p, f, 2.4022650695910072e-1f);
    p = fmaf(p, f, 6.9314718055994531e-1f);
    p = fmaf(p, f, 1.0f);
    return __int_as_float(__float_as_int(p) + (((int)n) << 23));
}
__device__ __forceinline__ void split2(float v, bf16& hi, bf16& lo){
    hi = __float2bfloat16(v);
    lo = __float2bfloat16(v - __bfloat162float(hi));
}
// split a (a,b) pair into packed-hi u32 and packed-lo u32
__device__ __forceinline__ void split_pair(float a, float b, uint32_t& hi, uint32_t& lo){
    bf16 ah, al, bh_, bl;
    split2(a, ah, al); split2(b, bh_, bl);
    hi = (uint32_t)__bfloat16_as_ushort(ah) | ((uint32_t)__bfloat16_as_ushort(bh_) << 16);
    lo = (uint32_t)__bfloat16_as_ushort(al) | ((uint32_t)__bfloat16_as_ushort(bl) << 16);
}

// tile loader: rows x 64 bf16 (128B rows), swizzled; 256 threads
__device__ __forceinline__ void ld_tile(char* sm, int off, const bf16* __restrict__ g,
                                        int rows, int rstride, int tid){
    for (int i = tid; i < rows*8; i += 256){
        int r = i >> 3, c = i & 7;
        uint4 v = *reinterpret_cast<const uint4*>(g + (size_t)r*rstride + c*8);
        *reinterpret_cast<uint4*>(sm + off + SW(r*128 + c*16)) = v;
    }
}

// one K=64 chunk of split-bf16 MMA: c += Ah*Bh^T + Al*Bh^T + Ah*Bl^T
__device__ __forceinline__ void warp_mma_chunk(float c[2][8][4], uint32_t sbase,
                                               int wm0, int wn0, int lane){
    const int lr = lane & 15, lh = lane >> 4;
#pragma unroll
    for (int ks = 0; ks < 4; ks++){
        uint32_t ah[2][4], al[2][4];
#pragma unroll
        for (int ma = 0; ma < 2; ma++){
            uint32_t off = SW((wm0 + ma*16 + lr)*128 + (ks*2 + lh)*16);
            ldsm_x4(ah[ma][0], ah[ma][1], ah[ma][2], ah[ma][3], sbase + OFF_AH + off);
            ldsm_x4(al[ma][0], al[ma][1], al[ma][2], al[ma][3], sbase + OFF_AL + off);
        }
#pragma unroll
        for (int np = 0; np < 4; np++){
            uint32_t off = SW((wn0 + np*16 + lr)*128 + (ks*2 + lh)*16);
            uint32_t bh[4], bl[4];
            ldsm_x4(bh[0], bh[1], bh[2], bh[3], sbase + OFF_BH + off);
            ldsm_x4(bl[0], bl[1], bl[2], bl[3], sbase + OFF_BL + off);
#pragma unroll
            for (int ma = 0; ma < 2; ma++){
                mma16816(c[ma][np*2],   ah[ma], bh[0], bh[2]);
                mma16816(c[ma][np*2],   al[ma], bh[0], bh[2]);
                mma16816(c[ma][np*2],   ah[ma], bl[0], bl[2]);
                mma16816(c[ma][np*2+1], ah[ma], bh[1], bh[3]);
                mma16816(c[ma][np*2+1], al[ma], bh[1], bh[3]);
                mma16816(c[ma][np*2+1], ah[ma], bl[1], bl[3]);
            }
        }
    }
}

#define MMA_PRE() \
    extern __shared__ char sm[]; \
    const int tid = threadIdx.x, wid = tid >> 5, lane = tid & 31; \
    const uint32_t sbase = smem_u32(sm); \
    const int wm0 = (wid & 3) * 32, wn0 = (wid >> 2) * 64; \
    float c[2][8][4]; \
    _Pragma("unroll") for (int i = 0; i < 2; i++) \
    _Pragma("unroll") for (int j = 0; j < 8; j++) \
    _Pragma("unroll") for (int k = 0; k < 4; k++) c[i][j][k] = 0.0f;

// ============================ split-convert =================================
__global__ __launch_bounds__(256) void k_conv(const float* __restrict__ in,
                                              bf16* __restrict__ oh, bf16* __restrict__ ol, int n4){
    for (int i = blockIdx.x*blockDim.x + threadIdx.x; i < n4; i += gridDim.x*blockDim.x){
        float4 v = reinterpret_cast<const float4*>(in)[i];
        uint32_t h0, l0, h1, l1;
        split_pair(v.x, v.y, h0, l0);
        split_pair(v.z, v.w, h1, l1);
        reinterpret_cast<uint2*>(oh)[i] = make_uint2(h0, h1);
        reinterpret_cast<uint2*>(ol)[i] = make_uint2(l0, l1);
    }
}

// ============================ weight GEMM: U = A * B^T (768^3) ==============
__global__ __launch_bounds__(256, 2) void k_gemm_w(
    const bf16* __restrict__ Ah, const bf16* __restrict__ Al,
    const bf16* __restrict__ Bh, const bf16* __restrict__ Bl,
    bf16* __restrict__ Oh, bf16* __restrict__ Ol)
{
    MMA_PRE();
    const int m0 = blockIdx.x*128, n0 = blockIdx.y*128;
    for (int kc = 0; kc < 12; kc++){
        __syncthreads();
        ld_tile(sm, OFF_AH, Ah + (size_t)m0*CC + kc*64, 128, CC, tid);
        ld_tile(sm, OFF_AL, Al + (size_t)m0*CC + kc*64, 128, CC, tid);
        ld_tile(sm, OFF_BH, Bh + (size_t)n0*CC + kc*64, 128, CC, tid);
        ld_tile(sm, OFF_BL, Bl + (size_t)n0*CC + kc*64, 128, CC, tid);
        __syncthreads();
        warp_mma_chunk(c, sbase, wm0, wn0, lane);
    }
    const int gid = lane >> 2, tg = lane & 3;
#pragma unroll
    for (int ma = 0; ma < 2; ma++)
#pragma unroll
    for (int na = 0; na < 8; na++){
        int row = m0 + wm0 + ma*16 + gid;
        int col = n0 + wn0 + na*8 + tg*2;
        uint32_t hi, lo;
        split_pair(c[ma][na][0], c[ma][na][1], hi, lo);
        *reinterpret_cast<uint32_t*>(Oh + (size_t)row*CC + col) = hi;
        *reinterpret_cast<uint32_t*>(Ol + (size_t)row*CC + col) = lo;
        split_pair(c[ma][na][2], c[ma][na][3], hi, lo);
        *reinterpret_cast<uint32_t*>(Oh + (size_t)(row+8)*CC + col) = hi;
        *reinterpret_cast<uint32_t*>(Ol + (size_t)(row+8)*CC + col) = lo;
    }
}

// ============================ projection GEMM (per-head scatter) ============
__global__ __launch_bounds__(256, 2) void k_gemm_proj(
    const bf16* __restrict__ Ah, const bf16* __restrict__ Al,
    const bf16* __restrict__ Bh, const bf16* __restrict__ Bl,
    bf16* __restrict__ Oh, bf16* __restrict__ Ol)
{
    MMA_PRE();
    const int m0 = blockIdx.x*128, n0 = blockIdx.y*128;
    for (int kc = 0; kc < 12; kc++){
        __syncthreads();
        ld_tile(sm, OFF_AH, Ah + (size_t)m0*CC + kc*64, 128, CC, tid);
        ld_tile(sm, OFF_AL, Al + (size_t)m0*CC + kc*64, 128, CC, tid);
        ld_tile(sm, OFF_BH, Bh + (size_t)n0*CC + kc*64, 128, CC, tid);
        ld_tile(sm, OFF_BL, Bl + (size_t)n0*CC + kc*64, 128, CC, tid);
        __syncthreads();
        warp_mma_chunk(c, sbase, wm0, wn0, lane);
    }
    const int gid = lane >> 2, tg = lane & 3;
#pragma unroll
    for (int ma = 0; ma < 2; ma++)
#pragma unroll
    for (int na = 0; na < 8; na++){
        int col = n0 + wn0 + na*8 + tg*2;
        int h = col >> 6, z = col & 63;
#pragma unroll
        for (int half = 0; half < 2; half++){
            int row = m0 + wm0 + ma*16 + gid + half*8;
            int b = row >> 10, tk = row & (NN-1);
            size_t adr = ((size_t)(b*HH + h)*NN + tk)*ZZ + z;
            uint32_t hi, lo;
            split_pair(c[ma][na][half*2], c[ma][na][half*2+1], hi, lo);
            *reinterpret_cast<uint32_t*>(Oh + adr) = hi;
            *reinterpret_cast<uint32_t*>(Ol + adr) = lo;
        }
    }
}

// ============================ transpose [n][z]->[z][n] ======================
__global__ __launch_bounds__(256) void k_tr64(){
    __shared__ bf16 s[64][72];
    int bh = blockIdx.y, n0 = blockIdx.x*64, pl = blockIdx.z;
    const bf16* src = (pl==0)? g_Qh : (pl==1)? g_Ql : (pl==2)? g_Kh : g_Kl;
    bf16* dst       = (pl==0)? g_Qth: (pl==1)? g_Qtl: (pl==2)? g_Kth: g_Ktl;
    int tid = threadIdx.x;
    int r = tid >> 2, seg = (tid & 3)*16;
    const bf16* sp = src + ((size_t)bh*NN + n0 + r)*ZZ + seg;
    *reinterpret_cast<uint4*>(&s[r][seg])     = *reinterpret_cast<const uint4*>(sp);
    *reinterpret_cast<uint4*>(&s[r][seg + 8]) = *reinterpret_cast<const uint4*>(sp + 8);
    __syncthreads();
    bf16 o[16];
#pragma unroll
    for (int j = 0; j < 16; j++) o[j] = s[seg + j][r];
    bf16* dp = dst + ((size_t)bh*ZZ + r)*NN + n0 + seg;
    *reinterpret_cast<uint4*>(dp)     = *reinterpret_cast<uint4*>(o);
    *reinterpret_cast<uint4*>(dp + 8) = *reinterpret_cast<uint4*>(o + 8);
}

// ============================ S = Q K^T (fp32 out) ==========================
__global__ __launch_bounds__(256, 2) void k_gemm_s(){
    MMA_PRE();
    const int bh = blockIdx.z;
    const int t0 = blockIdx.x*128, q0 = blockIdx.y*128;
    ld_tile(sm, OFF_AH, g_Qh + ((size_t)bh*NN + q0)*ZZ, 128, ZZ, tid);
    ld_tile(sm, OFF_AL, g_Ql + ((size_t)bh*NN + q0)*ZZ, 128, ZZ, tid);
    ld_tile(sm, OFF_BH, g_Kh + ((size_t)bh*NN + t0)*ZZ, 128, ZZ, tid);
    ld_tile(sm, OFF_BL, g_Kl + ((size_t)bh*NN + t0)*ZZ, 128, ZZ, tid);
    __syncthreads();
    warp_mma_chunk(c, sbase, wm0, wn0, lane);
    const int gid = lane >> 2, tg = lane & 3;
#pragma unroll
    for (int ma = 0; ma < 2; ma++)
#pragma unroll
    for (int na = 0; na < 8; na++){
        int row = q0 + wm0 + ma*16 + gid;
        int col = t0 + wn0 + na*8 + tg*2;
        *reinterpret_cast<float2*>(g_S + ((size_t)bh*NN + row)*NN + col)
            = make_float2(c[ma][na][0], c[ma][na][1]);
        *reinterpret_cast<float2*>(g_S + ((size_t)bh*NN + row + 8)*NN + col)
            = make_float2(c[ma][na][2], c[ma][na][3]);
    }
}

// ============================ softmax stats =================================
__global__ __launch_bounds__(256) void k_stats(){
    int row = blockIdx.x*8 + (threadIdx.x >> 5);
    int l = threadIdx.x & 31;
    const float4* r = reinterpret_cast<const float4*>(g_S + (size_t)row*NN);
    float4 v[8];
#pragma unroll
    for (int j = 0; j < 8; j++) v[j] = r[l + 32*j];
    float mx = -1e30f;
#pragma unroll
    for (int j = 0; j < 8; j++)
        mx = fmaxf(mx, fmaxf(fmaxf(v[j].x, v[j].y), fmaxf(v[j].z, v[j].w)));
#pragma unroll
    for (int o = 16; o > 0; o >>= 1) mx = fmaxf(mx, __shfl_xor_sync(0xffffffffu, mx, o));
    float M = mx * SCALE;
    float s = 0.0f;
#pragma unroll
    for (int j = 0; j < 8; j++)
        s += fexp(v[j].x*SCALE - M) + fexp(v[j].y*SCALE - M)
           + fexp(v[j].z*SCALE - M) + fexp(v[j].w*SCALE - M);
#pragma unroll
    for (int o = 16; o > 0; o >>= 1) s += __shfl_xor_sync(0xffffffffu, s, o);
    if (l == 0){ g_m[row] = M; g_il[row] = 1.0f / s; }
}

// ============================ P^T split planes ==============================
__global__ __launch_bounds__(256) void k_pexp(){
    __shared__ float sp[64][65];
    int bh = blockIdx.z, t0 = blockIdx.x*64, q0 = blockIdx.y*64;
    int tid = threadIdx.x;
    int r = tid >> 2, cs = (tid & 3)*16;
    int q = q0 + r;
    float M = g_m[bh*NN + q], il = g_il[bh*NN + q];
    const float* src = g_S + ((size_t)bh*NN + q)*NN + t0 + cs;
#pragma unroll
    for (int j = 0; j < 4; j++){
        float4 v = reinterpret_cast<const float4*>(src)[j];
        sp[r][cs + j*4 + 0] = fexp(v.x*SCALE - M)*il;
        sp[r][cs + j*4 + 1] = fexp(v.y*SCALE - M)*il;
        sp[r][cs + j*4 + 2] = fexp(v.z*SCALE - M)*il;
        sp[r][cs + j*4 + 3] = fexp(v.w*SCALE - M)*il;
    }
    __syncthreads();
    bf16 hb[16], lb[16];
#pragma unroll
    for (int j = 0; j < 16; j++) split2(sp[cs + j][r], hb[j], lb[j]);
    size_t o = ((size_t)bh*NN + t0 + r)*NN + q0 + cs;
    *reinterpret_cast<uint4*>(g_Ph + o)     = *reinterpret_cast<uint4*>(hb);
    *reinterpret_cast<uint4*>(g_Ph + o + 8) = *reinterpret_cast<uint4*>(hb + 8);
    *reinterpret_cast<uint4*>(g_Pl + o)     = *reinterpret_cast<uint4*>(lb);
    *reinterpret_cast<uint4*>(g_Pl + o + 8) = *reinterpret_cast<uint4*>(lb + 8);
}

// ============================ Ck = P^T K, Cq = P^T Q ========================
// B tile rows 0-63: Kt (-> Ck), rows 64-127: Qt (-> Cq)
__global__ __launch_bounds__(256, 2) void k_gemm_ts(){
    MMA_PRE();
    const int bh = blockIdx.y, t0 = blockIdx.x*128;
    for (int kc = 0; kc < 16; kc++){
        __syncthreads();
        ld_tile(sm, OFF_AH, g_Ph + ((size_t)bh*NN + t0)*NN + kc*64, 128, NN, tid);
        ld_tile(sm, OFF_AL, g_Pl + ((size_t)bh*NN + t0)*NN + kc*64, 128, NN, tid);
        ld_tile(sm, OFF_BH,        g_Kth + (size_t)bh*ZZ*NN + kc*64, 64, NN, tid);
        ld_tile(sm, OFF_BH + 8192, g_Qth + (size_t)bh*ZZ*NN + kc*64, 64, NN, tid);
        ld_tile(sm, OFF_BL,        g_Ktl + (size_t)bh*ZZ*NN + kc*64, 64, NN, tid);
        ld_tile(sm, OFF_BL + 8192, g_Qtl + (size_t)bh*ZZ*NN + kc*64, 64, NN, tid);
        __syncthreads();
        warp_mma_chunk(c, sbase, wm0, wn0, lane);
    }
    const int gid = lane >> 2, tg = lane & 3;
    const int b = bh / HH, h = bh - b*HH;
    bf16* Oh = (wn0 == 0) ? g_Ckh : g_Cqh;
    bf16* Ol = (wn0 == 0) ? g_Ckl : g_Cql;
#pragma unroll
    for (int ma = 0; ma < 2; ma++)
#pragma unroll
    for (int na = 0; na < 8; na++){
        int z = na*8 + tg*2;
#pragma unroll
        for (int half = 0; half < 2; half++){
            int t = t0 + wm0 + ma*16 + gid + half*8;
            size_t adr = ((size_t)b*NN + t)*CC + h*ZZ + z;
            uint32_t hi, lo;
            split_pair(c[ma][na][half*2], c[ma][na][half*2+1], hi, lo);
            *reinterpret_cast<uint32_t*>(Oh + adr) = hi;
            *reinterpret_cast<uint32_t*>(Ol + adr) = lo;
        }
    }
}

// ============================ out = Ck U1^T + Cq U2^T + bp ==================
__global__ __launch_bounds__(256, 2) void k_gemm_out(const float* __restrict__ bp,
                                                     float* __restrict__ out){
    MMA_PRE();
    const int m0 = blockIdx.x*128, n0 = blockIdx.y*128;
    for (int it = 0; it < 24; it++){
        int pr = it & 1, kc = it >> 1;
        const bf16* Ah = pr ? g_Cqh : g_Ckh;
        const bf16* Al = pr ? g_Cql : g_Ckl;
        const bf16* Bh = pr ? g_U2h : g_U1h;
        const bf16* Bl = pr ? g_U2l : g_U1l;
        __syncthreads();
        ld_tile(sm, OFF_AH, Ah + (size_t)m0*CC + kc*64, 128, CC, tid);
        ld_tile(sm, OFF_AL, Al + (size_t)m0*CC + kc*64, 128, CC, tid);
        ld_tile(sm, OFF_BH, Bh + (size_t)n0*CC + kc*64, 128, CC, tid);
        ld_tile(sm, OFF_BL, Bl + (size_t)n0*CC + kc*64, 128, CC, tid);
        __syncthreads();
        warp_mma_chunk(c, sbase, wm0, wn0, lane);
    }
    const int gid = lane >> 2, tg = lane & 3;
#pragma unroll
    for (int ma = 0; ma < 2; ma++)
#pragma unroll
    for (int na = 0; na < 8; na++){
        int row = m0 + wm0 + ma*16 + gid;
        int col = n0 + wn0 + na*8 + tg*2;
        float b0 = bp[col], b1 = bp[col+1];
        *reinterpret_cast<float2*>(out + (size_t)row*CC + col)
            = make_float2(c[ma][na][0] + b0, c[ma][na][1] + b1);
        *reinterpret_cast<float2*>(out + (size_t)(row+8)*CC + col)
            = make_float2(c[ma][na][2] + b0, c[ma][na][3] + b1);
    }
}

// ============================ host ==========================================
extern "C" void kernel_launch(void* const* d_in, const int* in_sizes, int n_in,
                              void* d_out, int out_size)
{
    (void)in_sizes; (void)n_in; (void)out_size;
    const float* x  = (const float*)d_in[0];
    const float* Wq = (const float*)d_in[1];
    const float* Wk = (const float*)d_in[2];
    const float* Wp = (const float*)d_in[3];
    const float* bp = (const float*)d_in[4];
    float* out = (float*)d_out;

    bf16 *xh, *xl, *wqh, *wql, *wkh, *wkl, *wph, *wpl;
    cudaGetSymbolAddress((void**)&xh,  g_xh);  cudaGetSymbolAddress((void**)&xl,  g_xl);
    cudaGetSymbolAddress((void**)&wqh, g_Wqh); cudaGetSymbolAddress((void**)&wql, g_Wql);
    cudaGetSymbolAddress((void**)&wkh, g_Wkh); cudaGetSymbolAddress((void**)&wkl, g_Wkl);
    cudaGetSymbolAddress((void**)&wph, g_Wph); cudaGetSymbolAddress((void**)&wpl, g_Wpl);
    bf16 *u1h, *u1l, *u2h, *u2l, *qh, *ql, *kh, *kl;
    cudaGetSymbolAddress((void**)&u1h, g_U1h); cudaGetSymbolAddress((void**)&u1l, g_U1l);
    cudaGetSymbolAddress((void**)&u2h, g_U2h); cudaGetSymbolAddress((void**)&u2l, g_U2l);
    cudaGetSymbolAddress((void**)&qh,  g_Qh);  cudaGetSymbolAddress((void**)&ql,  g_Ql);
    cudaGetSymbolAddress((void**)&kh,  g_Kh);  cudaGetSymbolAddress((void**)&kl,  g_Kl);

    cudaFuncSetAttribute(k_gemm_w,    cudaFuncAttributeMaxDynamicSharedMemorySize, SMEM_BYTES);
    cudaFuncSetAttribute(k_gemm_proj, cudaFuncAttributeMaxDynamicSharedMemorySize, SMEM_BYTES);
    cudaFuncSetAttribute(k_gemm_s,    cudaFuncAttributeMaxDynamicSharedMemorySize, SMEM_BYTES);
    cudaFuncSetAttribute(k_gemm_ts,   cudaFuncAttributeMaxDynamicSharedMemorySize, SMEM_BYTES);
    cudaFuncSetAttribute(k_gemm_out,  cudaFuncAttributeMaxDynamicSharedMemorySize, SMEM_BYTES);

    // split conversions
    k_conv<<<256, 256>>>(x,  xh,  xl,  BB*NN*CC/4);
    k_conv<<<64,  256>>>(Wq, wqh, wql, CC*CC/4);
    k_conv<<<64,  256>>>(Wk, wkh, wkl, CC*CC/4);
    k_conv<<<64,  256>>>(Wp, wph, wpl, CC*CC/4);

    // U1 = Wp Wq^T, U2 = Wp Wk^T
    k_gemm_w<<<dim3(6,6), 256, SMEM_BYTES>>>(wph, wpl, wqh, wql, u1h, u1l);
    k_gemm_w<<<dim3(6,6), 256, SMEM_BYTES>>>(wph, wpl, wkh, wkl, u2h, u2l);

    // Q = x Wq^T, K = x Wk^T (per-head split planes)
    k_gemm_proj<<<dim3(64,6), 256, SMEM_BYTES>>>(xh, xl, wqh, wql, qh, ql);
    k_gemm_proj<<<dim3(64,6), 256, SMEM_BYTES>>>(xh, xl, wkh, wkl, kh, kl);

    // transposes for the later B operands
    k_tr64<<<dim3(16, BH, 4), 256>>>();

    // S = Q K^T
    k_gemm_s<<<dim3(8, 8, BH), 256, SMEM_BYTES>>>();

    // softmax stats
    k_stats<<<BH*NN/8, 256>>>();

    // P^T planes
    k_pexp<<<dim3(16, 16, BH), 256>>>();

    // Ck, Cq
    k_gemm_ts<<<dim3(8, BH), 256, SMEM_BYTES>>>();

    // out
    k_gemm_out<<<dim3(64, 6), 256, SMEM_BYTES>>>(bp, out);
}

// round 5
// speedup vs baseline: 1.6974x; 1.0456x over previous
#include <cuda_runtime.h>
#include <cuda_bf16.h>
#include <cstdint>
#include <math.h>

#define BB 8
#define NN 1024
#define CC 768
#define HH 12
#define ZZ 64
#define BH (BB*HH)
#define SCALE 0.125f
typedef __nv_bfloat16 bf16;

// ---------------- scratch ----------------
__device__ bf16 g_xh[BB*NN*CC], g_xl[BB*NN*CC];
__device__ bf16 g_Wqh[CC*CC], g_Wql[CC*CC], g_Wkh[CC*CC], g_Wkl[CC*CC];
__device__ bf16 g_Wph[CC*CC], g_Wpl[CC*CC];
__device__ bf16 g_U1h[CC*CC], g_U1l[CC*CC], g_U2h[CC*CC], g_U2l[CC*CC];
__device__ bf16 g_Qh[BH*NN*ZZ], g_Ql[BH*NN*ZZ], g_Kh[BH*NN*ZZ], g_Kl[BH*NN*ZZ];
__device__ float g_m[BH*NN], g_il[BH*NN];
__device__ bf16 g_Ckh[BB*NN*CC], g_Ckl[BB*NN*CC], g_Cqh[BB*NN*CC], g_Cql[BB*NN*CC];

// ---------------- helpers ----------------
#define SW(o) ((o) ^ (((o)>>3)&0x70))
#define OFF_AH 0
#define OFF_AL 16384
#define OFF_BH 32768
#define OFF_BL 49152
#define SMEM_BYTES 65536

__device__ __forceinline__ uint32_t smem_u32(const void* p){
    uint32_t a;
    asm("{ .reg .u64 t; cvta.to.shared.u64 t, %1; cvt.u32.u64 %0, t; }" : "=r"(a) : "l"(p));
    return a;
}
__device__ __forceinline__ void ldsm_x4(uint32_t& r0, uint32_t& r1, uint32_t& r2, uint32_t& r3, uint32_t addr){
    asm volatile("ldmatrix.sync.aligned.m8n8.x4.shared.b16 {%0,%1,%2,%3}, [%4];"
        : "=r"(r0), "=r"(r1), "=r"(r2), "=r"(r3) : "r"(addr));
}
__device__ __forceinline__ void ldsm_x4_t(uint32_t& r0, uint32_t& r1, uint32_t& r2, uint32_t& r3, uint32_t addr){
    asm volatile("ldmatrix.sync.aligned.m8n8.x4.trans.shared.b16 {%0,%1,%2,%3}, [%4];"
        : "=r"(r0), "=r"(r1), "=r"(r2), "=r"(r3) : "r"(addr));
}
__device__ __forceinline__ void mma16816(float c[4], const uint32_t a[4], uint32_t b0, uint32_t b1){
    asm volatile("mma.sync.aligned.m16n8k16.row.col.f32.bf16.bf16.f32 "
        "{%0,%1,%2,%3}, {%4,%5,%6,%7}, {%8,%9}, {%0,%1,%2,%3};"
        : "+f"(c[0]), "+f"(c[1]), "+f"(c[2]), "+f"(c[3])
        : "r"(a[0]), "r"(a[1]), "r"(a[2]), "r"(a[3]), "r"(b0), "r"(b1));
}

__device__ __forceinline__ float fexp(float x){
    float y = x * 1.4426950408889634f;
    float n = rintf(y);
    float f = y - n;
    float p = 1.3333558146428443e-3f;
    p = fmaf(p, f, 9.6181291076284772e-3f);
    p = fmaf(p, f, 5.5504108664821580e-2f);
    p = fmaf(p, f, 2.4022650695910072e-1f);
    p = fmaf(p, f, 6.9314718055994531e-1f);
    p = fmaf(p, f, 1.0f);
    return __int_as_float(__float_as_int(p) + (((int)n) << 23));
}
__device__ __forceinline__ void split2(float v, bf16& hi, bf16& lo){
    hi = __float2bfloat16(v);
    lo = __float2bfloat16(v - __bfloat162float(hi));
}
__device__ __forceinline__ void split_pair(float a, float b, uint32_t& hi, uint32_t& lo){
    bf16 ah, al, bh_, bl;
    split2(a, ah, al); split2(b, bh_, bl);
    hi = (uint32_t)__bfloat16_as_ushort(ah) | ((uint32_t)__bfloat16_as_ushort(bh_) << 16);
    lo = (uint32_t)__bfloat16_as_ushort(al) | ((uint32_t)__bfloat16_as_ushort(bl) << 16);
}

// tile loader: rows x 64 bf16 (128B rows), swizzled; 256 threads
__device__ __forceinline__ void ld_tile(char* sm, int off, const bf16* __restrict__ g,
                                        int rows, int rstride, int tid){
    for (int i = tid; i < rows*8; i += 256){
        int r = i >> 3, c = i & 7;
        uint4 v = *reinterpret_cast<const uint4*>(g + (size_t)r*rstride + c*8);
        *reinterpret_cast<uint4*>(sm + off + SW(r*128 + c*16)) = v;
    }
}

// one K=64 chunk of split-bf16 MMA (block 128x128, 8 warps 32x64)
__device__ __forceinline__ void warp_mma_chunk(float c[2][8][4], uint32_t sbase,
                                               int wm0, int wn0, int lane){
    const int lr = lane & 15, lh = lane >> 4;
#pragma unroll
    for (int ks = 0; ks < 4; ks++){
        uint32_t ah[2][4], al[2][4];
#pragma unroll
        for (int ma = 0; ma < 2; ma++){
            uint32_t off = SW((wm0 + ma*16 + lr)*128 + (ks*2 + lh)*16);
            ldsm_x4(ah[ma][0], ah[ma][1], ah[ma][2], ah[ma][3], sbase + OFF_AH + off);
            ldsm_x4(al[ma][0], al[ma][1], al[ma][2], al[ma][3], sbase + OFF_AL + off);
        }
#pragma unroll
        for (int np = 0; np < 4; np++){
            uint32_t off = SW((wn0 + np*16 + lr)*128 + (ks*2 + lh)*16);
            uint32_t bh[4], bl[4];
            ldsm_x4(bh[0], bh[1], bh[2], bh[3], sbase + OFF_BH + off);
            ldsm_x4(bl[0], bl[1], bl[2], bl[3], sbase + OFF_BL + off);
#pragma unroll
            for (int ma = 0; ma < 2; ma++){
                mma16816(c[ma][np*2],   ah[ma], bh[0], bh[2]);
                mma16816(c[ma][np*2],   al[ma], bh[0], bh[2]);
                mma16816(c[ma][np*2],   ah[ma], bl[0], bl[2]);
                mma16816(c[ma][np*2+1], ah[ma], bh[1], bh[3]);
                mma16816(c[ma][np*2+1], al[ma], bh[1], bh[3]);
                mma16816(c[ma][np*2+1], ah[ma], bl[1], bl[3]);
            }
        }
    }
}

#define MMA_PRE() \
    extern __shared__ char sm[]; \
    const int tid = threadIdx.x, wid = tid >> 5, lane = tid & 31; \
    const uint32_t sbase = smem_u32(sm); \
    const int wm0 = (wid & 3) * 32, wn0 = (wid >> 2) * 64; \
    float c[2][8][4]; \
    _Pragma("unroll") for (int i = 0; i < 2; i++) \
    _Pragma("unroll") for (int j = 0; j < 8; j++) \
    _Pragma("unroll") for (int k = 0; k < 4; k++) c[i][j][k] = 0.0f;

// ============================ split-convert =================================
__global__ __launch_bounds__(256) void k_conv(const float* __restrict__ in,
                                              bf16* __restrict__ oh, bf16* __restrict__ ol, int n4){
    for (int i = blockIdx.x*blockDim.x + threadIdx.x; i < n4; i += gridDim.x*blockDim.x){
        float4 v = reinterpret_cast<const float4*>(in)[i];
        uint32_t h0, l0, h1, l1;
        split_pair(v.x, v.y, h0, l0);
        split_pair(v.z, v.w, h1, l1);
        reinterpret_cast<uint2*>(oh)[i] = make_uint2(h0, h1);
        reinterpret_cast<uint2*>(ol)[i] = make_uint2(l0, l1);
    }
}

// ============================ weight GEMM: U = A * B^T ======================
__global__ __launch_bounds__(256, 2) void k_gemm_w(
    const bf16* __restrict__ Ah, const bf16* __restrict__ Al,
    const bf16* __restrict__ Bh, const bf16* __restrict__ Bl,
    bf16* __restrict__ Oh, bf16* __restrict__ Ol)
{
    MMA_PRE();
    const int m0 = blockIdx.x*128, n0 = blockIdx.y*128;
    for (int kc = 0; kc < 12; kc++){
        __syncthreads();
        ld_tile(sm, OFF_AH, Ah + (size_t)m0*CC + kc*64, 128, CC, tid);
        ld_tile(sm, OFF_AL, Al + (size_t)m0*CC + kc*64, 128, CC, tid);
        ld_tile(sm, OFF_BH, Bh + (size_t)n0*CC + kc*64, 128, CC, tid);
        ld_tile(sm, OFF_BL, Bl + (size_t)n0*CC + kc*64, 128, CC, tid);
        __syncthreads();
        warp_mma_chunk(c, sbase, wm0, wn0, lane);
    }
    const int gid = lane >> 2, tg = lane & 3;
#pragma unroll
    for (int ma = 0; ma < 2; ma++)
#pragma unroll
    for (int na = 0; na < 8; na++){
        int row = m0 + wm0 + ma*16 + gid;
        int col = n0 + wn0 + na*8 + tg*2;
        uint32_t hi, lo;
        split_pair(c[ma][na][0], c[ma][na][1], hi, lo);
        *reinterpret_cast<uint32_t*>(Oh + (size_t)row*CC + col) = hi;
        *reinterpret_cast<uint32_t*>(Ol + (size_t)row*CC + col) = lo;
        split_pair(c[ma][na][2], c[ma][na][3], hi, lo);
        *reinterpret_cast<uint32_t*>(Oh + (size_t)(row+8)*CC + col) = hi;
        *reinterpret_cast<uint32_t*>(Ol + (size_t)(row+8)*CC + col) = lo;
    }
}

// ============================ projection GEMM (per-head scatter) ============
__global__ __launch_bounds__(256, 2) void k_gemm_proj(
    const bf16* __restrict__ Ah, const bf16* __restrict__ Al,
    const bf16* __restrict__ Bh, const bf16* __restrict__ Bl,
    bf16* __restrict__ Oh, bf16* __restrict__ Ol)
{
    MMA_PRE();
    const int m0 = blockIdx.x*128, n0 = blockIdx.y*128;
    for (int kc = 0; kc < 12; kc++){
        __syncthreads();
        ld_tile(sm, OFF_AH, Ah + (size_t)m0*CC + kc*64, 128, CC, tid);
        ld_tile(sm, OFF_AL, Al + (size_t)m0*CC + kc*64, 128, CC, tid);
        ld_tile(sm, OFF_BH, Bh + (size_t)n0*CC + kc*64, 128, CC, tid);
        ld_tile(sm, OFF_BL, Bl + (size_t)n0*CC + kc*64, 128, CC, tid);
        __syncthreads();
        warp_mma_chunk(c, sbase, wm0, wn0, lane);
    }
    const int gid = lane >> 2, tg = lane & 3;
#pragma unroll
    for (int ma = 0; ma < 2; ma++)
#pragma unroll
    for (int na = 0; na < 8; na++){
        int col = n0 + wn0 + na*8 + tg*2;
        int h = col >> 6, z = col & 63;
#pragma unroll
        for (int half = 0; half < 2; half++){
            int row = m0 + wm0 + ma*16 + gid + half*8;
            int b = row >> 10, tk = row & (NN-1);
            size_t adr = ((size_t)(b*HH + h)*NN + tk)*ZZ + z;
            uint32_t hi, lo;
            split_pair(c[ma][na][half*2], c[ma][na][half*2+1], hi, lo);
            *reinterpret_cast<uint32_t*>(Oh + adr) = hi;
            *reinterpret_cast<uint32_t*>(Ol + adr) = lo;
        }
    }
}

// ============================ flash stats ===================================
// grid (8 qtiles, BH); block 256. Q tile 128 resident, loop K chunks of 128.
#define ST_QH 0
#define ST_QL 16384
#define ST_KH 32768
#define ST_KL 49152
#define ST_MM 65536
#define ST_LL 66560
#define ST_BYTES 67584
__global__ __launch_bounds__(256, 1) void k_statsf(){
    extern __shared__ char sm[];
    const int tid = threadIdx.x, wid = tid >> 5, lane = tid & 31;
    const uint32_t sbase = smem_u32(sm);
    const int bh = blockIdx.y, q0 = blockIdx.x*128;
    const int wq = (wid & 3)*32, wt = (wid >> 2)*64;
    const int gid = lane >> 2, tg = lane & 3;
    const int lr = lane & 15, lh = lane >> 4;

    ld_tile(sm, ST_QH, g_Qh + ((size_t)bh*NN + q0)*ZZ, 128, ZZ, tid);
    ld_tile(sm, ST_QL, g_Ql + ((size_t)bh*NN + q0)*ZZ, 128, ZZ, tid);

    float rm[2][2], rl[2][2];
#pragma unroll
    for (int i = 0; i < 2; i++)
#pragma unroll
    for (int j = 0; j < 2; j++){ rm[i][j] = -1e30f; rl[i][j] = 0.0f; }

    for (int t0 = 0; t0 < NN; t0 += 128){
        __syncthreads();
        ld_tile(sm, ST_KH, g_Kh + ((size_t)bh*NN + t0)*ZZ, 128, ZZ, tid);
        ld_tile(sm, ST_KL, g_Kl + ((size_t)bh*NN + t0)*ZZ, 128, ZZ, tid);
        __syncthreads();

        float s[2][8][4];
#pragma unroll
        for (int i = 0; i < 2; i++)
#pragma unroll
        for (int j = 0; j < 8; j++)
#pragma unroll
        for (int k = 0; k < 4; k++) s[i][j][k] = 0.0f;

#pragma unroll
        for (int ks = 0; ks < 4; ks++){
            uint32_t ah[2][4], al[2][4];
#pragma unroll
            for (int ma = 0; ma < 2; ma++){
                uint32_t off = SW((wq + ma*16 + lr)*128 + (ks*2 + lh)*16);
                ldsm_x4(ah[ma][0], ah[ma][1], ah[ma][2], ah[ma][3], sbase + ST_QH + off);
                ldsm_x4(al[ma][0], al[ma][1], al[ma][2], al[ma][3], sbase + ST_QL + off);
            }
#pragma unroll
            for (int np = 0; np < 4; np++){
                uint32_t off = SW((wt + np*16 + lr)*128 + (ks*2 + lh)*16);
                uint32_t bh4[4], bl4[4];
                ldsm_x4(bh4[0], bh4[1], bh4[2], bh4[3], sbase + ST_KH + off);
                ldsm_x4(bl4[0], bl4[1], bl4[2], bl4[3], sbase + ST_KL + off);
#pragma unroll
                for (int ma = 0; ma < 2; ma++){
                    mma16816(s[ma][np*2],   ah[ma], bh4[0], bh4[2]);
                    mma16816(s[ma][np*2],   al[ma], bh4[0], bh4[2]);
                    mma16816(s[ma][np*2],   ah[ma], bl4[0], bl4[2]);
                    mma16816(s[ma][np*2+1], ah[ma], bh4[1], bh4[3]);
                    mma16816(s[ma][np*2+1], al[ma], bh4[1], bh4[3]);
                    mma16816(s[ma][np*2+1], ah[ma], bl4[1], bl4[3]);
                }
            }
        }
        // flash merge per row
#pragma unroll
        for (int ma = 0; ma < 2; ma++)
#pragma unroll
        for (int half = 0; half < 2; half++){
            float cm = -1e30f;
#pragma unroll
            for (int na = 0; na < 8; na++)
                cm = fmaxf(cm, fmaxf(s[ma][na][half*2], s[ma][na][half*2+1]));
            cm *= SCALE;
            cm = fmaxf(cm, __shfl_xor_sync(0xffffffffu, cm, 1));
            cm = fmaxf(cm, __shfl_xor_sync(0xffffffffu, cm, 2));
            float nm = fmaxf(rm[ma][half], cm);
            float ls = 0.0f;
#pragma unroll
            for (int na = 0; na < 8; na++)
                ls += fexp(s[ma][na][half*2]*SCALE - nm) + fexp(s[ma][na][half*2+1]*SCALE - nm);
            ls += __shfl_xor_sync(0xffffffffu, ls, 1);
            ls += __shfl_xor_sync(0xffffffffu, ls, 2);
            float d = fmaxf(rm[ma][half] - nm, -60.0f);
            rl[ma][half] = rl[ma][half]*fexp(d) + ls;
            rm[ma][half] = nm;
        }
    }
    // cross-warp (2 t-warps) merge via smem
    float* smm = reinterpret_cast<float*>(sm + ST_MM);
    float* sml = reinterpret_cast<float*>(sm + ST_LL);
    __syncthreads();
    if (tg == 0){
#pragma unroll
        for (int ma = 0; ma < 2; ma++)
#pragma unroll
        for (int half = 0; half < 2; half++){
            int q = wq + ma*16 + gid + half*8;
            int wti = wid >> 2;
            smm[wti*128 + q] = rm[ma][half];
            sml[wti*128 + q] = rl[ma][half];
        }
    }
    __syncthreads();
    if (tid < 128){
        float m0 = smm[tid], m1 = smm[128 + tid];
        float l0 = sml[tid], l1 = sml[128 + tid];
        float m = fmaxf(m0, m1);
        float l = l0*fexp(fmaxf(m0 - m, -60.0f)) + l1*fexp(fmaxf(m1 - m, -60.0f));
        g_m [bh*NN + q0 + tid] = m;
        g_il[bh*NN + q0 + tid] = 1.0f / l;
    }
}

// ============================ fused attention pass ==========================
// grid (8 t-tiles, BH); block 256.
// Phase1: S chunk (64q x 128t) via HMMA -> exp -> P in smem (split bf16).
// Phase2: Ck += P^T K, Cq += P^T Q via ldmatrix.trans.
#define AT_KTH 0
#define AT_KTL 16384
#define AT_QCH 32768
#define AT_QCL 40960
#define AT_KCH 49152
#define AT_KCL 57344
#define AT_PH  65536
#define AT_PL  81920
#define AT_MS  98304
#define AT_IL  98560
#define AT_BYTES 98816
__global__ __launch_bounds__(256, 1) void k_attn_f(){
    extern __shared__ char sm[];
    const int tid = threadIdx.x, wid = tid >> 5, lane = tid & 31;
    const uint32_t sbase = smem_u32(sm);
    const int bh = blockIdx.y, t0 = blockIdx.x*128;
    const int gid = lane >> 2, tg = lane & 3;
    const int lr = lane & 15, lh = lane >> 4;
    // trans-ldmatrix lane addressing
    const int srow_off = (lane & 7) + ((lane & 16) ? 8 : 0);
    const int scol8 = ((lane >> 3) & 1) * 8;
    float* ms = reinterpret_cast<float*>(sm + AT_MS);
    float* il = reinterpret_cast<float*>(sm + AT_IL);

    // persistent output accumulators: warp tile 32t x 64z
    const int wt2 = (wid & 3)*32, wz = wid >> 2;
    float c[2][8][4];
#pragma unroll
    for (int i = 0; i < 2; i++)
#pragma unroll
    for (int j = 0; j < 8; j++)
#pragma unroll
    for (int k = 0; k < 4; k++) c[i][j][k] = 0.0f;

    // K tile for this block's t rows (S-phase B operand), resident
    ld_tile(sm, AT_KTH, g_Kh + ((size_t)bh*NN + t0)*ZZ, 128, ZZ, tid);
    ld_tile(sm, AT_KTL, g_Kl + ((size_t)bh*NN + t0)*ZZ, 128, ZZ, tid);

    // phase1 warp layout: 2 q-warps x 4 t-warps (64q x 128t)
    const int wq1 = (wid & 1)*32, wt1 = (wid >> 1)*32;

    for (int q0c = 0; q0c < NN; q0c += 64){
        __syncthreads();
        ld_tile(sm, AT_QCH, g_Qh + ((size_t)bh*NN + q0c)*ZZ, 64, ZZ, tid);
        ld_tile(sm, AT_QCL, g_Ql + ((size_t)bh*NN + q0c)*ZZ, 64, ZZ, tid);
        ld_tile(sm, AT_KCH, g_Kh + ((size_t)bh*NN + q0c)*ZZ, 64, ZZ, tid);
        ld_tile(sm, AT_KCL, g_Kl + ((size_t)bh*NN + q0c)*ZZ, 64, ZZ, tid);
        if (tid < 64)       ms[tid]      = g_m [bh*NN + q0c + tid];
        else if (tid < 128) il[tid - 64] = g_il[bh*NN + q0c + tid - 64];
        __syncthreads();

        // ---- phase 1: S chunk -> P smem ----
        {
            float s1[2][4][4];
#pragma unroll
            for (int i = 0; i < 2; i++)
#pragma unroll
            for (int j = 0; j < 4; j++)
#pragma unroll
            for (int k = 0; k < 4; k++) s1[i][j][k] = 0.0f;
#pragma unroll
            for (int ks = 0; ks < 4; ks++){
                uint32_t ah[2][4], al[2][4];
#pragma unroll
                for (int ma = 0; ma < 2; ma++){
                    uint32_t off = SW((wq1 + ma*16 + lr)*128 + (ks*2 + lh)*16);
                    ldsm_x4(ah[ma][0], ah[ma][1], ah[ma][2], ah[ma][3], sbase + AT_QCH + off);
                    ldsm_x4(al[ma][0], al[ma][1], al[ma][2], al[ma][3], sbase + AT_QCL + off);
                }
#pragma unroll
                for (int np = 0; np < 2; np++){
                    uint32_t off = SW((wt1 + np*16 + lr)*128 + (ks*2 + lh)*16);
                    uint32_t bh4[4], bl4[4];
                    ldsm_x4(bh4[0], bh4[1], bh4[2], bh4[3], sbase + AT_KTH + off);
                    ldsm_x4(bl4[0], bl4[1], bl4[2], bl4[3], sbase + AT_KTL + off);
#pragma unroll
                    for (int ma = 0; ma < 2; ma++){
                        mma16816(s1[ma][np*2],   ah[ma], bh4[0], bh4[2]);
                        mma16816(s1[ma][np*2],   al[ma], bh4[0], bh4[2]);
                        mma16816(s1[ma][np*2],   ah[ma], bl4[0], bl4[2]);
                        mma16816(s1[ma][np*2+1], ah[ma], bh4[1], bh4[3]);
                        mma16816(s1[ma][np*2+1], al[ma], bh4[1], bh4[3]);
                        mma16816(s1[ma][np*2+1], ah[ma], bl4[1], bl4[3]);
                    }
                }
            }
            // exp + store split P [q][t] (two 64-col subtiles)
#pragma unroll
            for (int ma = 0; ma < 2; ma++)
#pragma unroll
            for (int na = 0; na < 4; na++)
#pragma unroll
            for (int half = 0; half < 2; half++){
                int qloc = wq1 + ma*16 + gid + half*8;
                float M = ms[qloc], I = il[qloc];
                int tloc = wt1 + na*8 + tg*2;
                float p0 = fexp(s1[ma][na][half*2]  *SCALE - M)*I;
                float p1 = fexp(s1[ma][na][half*2+1]*SCALE - M)*I;
                uint32_t hi, lo; split_pair(p0, p1, hi, lo);
                uint32_t off = (uint32_t)(tloc >> 6)*8192 + SW(qloc*128 + (tloc & 63)*2);
                *reinterpret_cast<uint32_t*>(sm + AT_PH + off) = hi;
                *reinterpret_cast<uint32_t*>(sm + AT_PL + off) = lo;
            }
        }
        __syncthreads();

        // ---- phase 2: Ck/Cq += P^T [K|Q] ----
        {
            const int bsh = wz ? AT_QCH : AT_KCH;
            const int bsl = wz ? AT_QCL : AT_KCL;
#pragma unroll
            for (int ks = 0; ks < 4; ks++){
                int qk = ks*16;
                uint32_t ah[2][4], al[2][4];
#pragma unroll
                for (int ma = 0; ma < 2; ma++){
                    int tcol = wt2 + ma*16;
                    uint32_t off = (uint32_t)(tcol >> 6)*8192
                                 + SW((qk + srow_off)*128 + ((tcol & 63) + scol8)*2);
                    ldsm_x4_t(ah[ma][0], ah[ma][1], ah[ma][2], ah[ma][3], sbase + AT_PH + off);
                    ldsm_x4_t(al[ma][0], al[ma][1], al[ma][2], al[ma][3], sbase + AT_PL + off);
                }
#pragma unroll
                for (int zn = 0; zn < 4; zn++){
                    uint32_t off = SW((qk + srow_off)*128 + (zn*16 + scol8)*2);
                    uint32_t bh4[4], bl4[4];
                    ldsm_x4_t(bh4[0], bh4[1], bh4[2], bh4[3], sbase + bsh + off);
                    ldsm_x4_t(bl4[0], bl4[1], bl4[2], bl4[3], sbase + bsl + off);
#pragma unroll
                    for (int ma = 0; ma < 2; ma++){
                        mma16816(c[ma][zn*2],   ah[ma], bh4[0], bh4[2]);
                        mma16816(c[ma][zn*2],   al[ma], bh4[0], bh4[2]);
                        mma16816(c[ma][zn*2],   ah[ma], bl4[0], bl4[2]);
                        mma16816(c[ma][zn*2+1], ah[ma], bh4[1], bh4[3]);
                        mma16816(c[ma][zn*2+1], al[ma], bh4[1], bh4[3]);
                        mma16816(c[ma][zn*2+1], ah[ma], bl4[1], bl4[3]);
                    }
                }
            }
        }
    }
    // epilogue: split-bf16 to Ck/Cq planes
    const int b = bh / HH, h = bh - b*HH;
    bf16* Oh = wz ? g_Cqh : g_Ckh;
    bf16* Ol = wz ? g_Cql : g_Ckl;
#pragma unroll
    for (int ma = 0; ma < 2; ma++)
#pragma unroll
    for (int na = 0; na < 8; na++){
        int z = na*8 + tg*2;
#pragma unroll
        for (int half = 0; half < 2; half++){
            int t = t0 + wt2 + ma*16 + gid + half*8;
            size_t adr = ((size_t)b*NN + t)*CC + h*ZZ + z;
            uint32_t hi, lo;
            split_pair(c[ma][na][half*2], c[ma][na][half*2+1], hi, lo);
            *reinterpret_cast<uint32_t*>(Oh + adr) = hi;
            *reinterpret_cast<uint32_t*>(Ol + adr) = lo;
        }
    }
}

// ============================ out = Ck U1^T + Cq U2^T + bp ==================
__global__ __launch_bounds__(256, 2) void k_gemm_out(const float* __restrict__ bp,
                                                     float* __restrict__ out){
    MMA_PRE();
    const int m0 = blockIdx.x*128, n0 = blockIdx.y*128;
    for (int it = 0; it < 24; it++){
        int pr = it & 1, kc = it >> 1;
        const bf16* Ah = pr ? g_Cqh : g_Ckh;
        const bf16* Al = pr ? g_Cql : g_Ckl;
        const bf16* Bh = pr ? g_U2h : g_U1h;
        const bf16* Bl = pr ? g_U2l : g_U1l;
        __syncthreads();
        ld_tile(sm, OFF_AH, Ah + (size_t)m0*CC + kc*64, 128, CC, tid);
        ld_tile(sm, OFF_AL, Al + (size_t)m0*CC + kc*64, 128, CC, tid);
        ld_tile(sm, OFF_BH, Bh + (size_t)n0*CC + kc*64, 128, CC, tid);
        ld_tile(sm, OFF_BL, Bl + (size_t)n0*CC + kc*64, 128, CC, tid);
        __syncthreads();
        warp_mma_chunk(c, sbase, wm0, wn0, lane);
    }
    const int gid = lane >> 2, tg = lane & 3;
#pragma unroll
    for (int ma = 0; ma < 2; ma++)
#pragma unroll
    for (int na = 0; na < 8; na++){
        int row = m0 + wm0 + ma*16 + gid;
        int col = n0 + wn0 + na*8 + tg*2;
        float b0 = bp[col], b1 = bp[col+1];
        *reinterpret_cast<float2*>(out + (size_t)row*CC + col)
            = make_float2(c[ma][na][0] + b0, c[ma][na][1] + b1);
        *reinterpret_cast<float2*>(out + (size_t)(row+8)*CC + col)
            = make_float2(c[ma][na][2] + b0, c[ma][na][3] + b1);
    }
}

// ============================ host ==========================================
extern "C" void kernel_launch(void* const* d_in, const int* in_sizes, int n_in,
                              void* d_out, int out_size)
{
    (void)in_sizes; (void)n_in; (void)out_size;
    const float* x  = (const float*)d_in[0];
    const float* Wq = (const float*)d_in[1];
    const float* Wk = (const float*)d_in[2];
    const float* Wp = (const float*)d_in[3];
    const float* bp = (const float*)d_in[4];
    float* out = (float*)d_out;

    bf16 *xh, *xl, *wqh, *wql, *wkh, *wkl, *wph, *wpl;
    cudaGetSymbolAddress((void**)&xh,  g_xh);  cudaGetSymbolAddress((void**)&xl,  g_xl);
    cudaGetSymbolAddress((void**)&wqh, g_Wqh); cudaGetSymbolAddress((void**)&wql, g_Wql);
    cudaGetSymbolAddress((void**)&wkh, g_Wkh); cudaGetSymbolAddress((void**)&wkl, g_Wkl);
    cudaGetSymbolAddress((void**)&wph, g_Wph); cudaGetSymbolAddress((void**)&wpl, g_Wpl);
    bf16 *u1h, *u1l, *u2h, *u2l, *qh, *ql, *kh, *kl;
    cudaGetSymbolAddress((void**)&u1h, g_U1h); cudaGetSymbolAddress((void**)&u1l, g_U1l);
    cudaGetSymbolAddress((void**)&u2h, g_U2h); cudaGetSymbolAddress((void**)&u2l, g_U2l);
    cudaGetSymbolAddress((void**)&qh,  g_Qh);  cudaGetSymbolAddress((void**)&ql,  g_Ql);
    cudaGetSymbolAddress((void**)&kh,  g_Kh);  cudaGetSymbolAddress((void**)&kl,  g_Kl);

    cudaFuncSetAttribute(k_gemm_w,    cudaFuncAttributeMaxDynamicSharedMemorySize, SMEM_BYTES);
    cudaFuncSetAttribute(k_gemm_proj, cudaFuncAttributeMaxDynamicSharedMemorySize, SMEM_BYTES);
    cudaFuncSetAttribute(k_gemm_out,  cudaFuncAttributeMaxDynamicSharedMemorySize, SMEM_BYTES);
    cudaFuncSetAttribute(k_statsf,    cudaFuncAttributeMaxDynamicSharedMemorySize, ST_BYTES);
    cudaFuncSetAttribute(k_attn_f,    cudaFuncAttributeMaxDynamicSharedMemorySize, AT_BYTES);

    // split conversions
    k_conv<<<256, 256>>>(x,  xh,  xl,  BB*NN*CC/4);
    k_conv<<<64,  256>>>(Wq, wqh, wql, CC*CC/4);
    k_conv<<<64,  256>>>(Wk, wkh, wkl, CC*CC/4);
    k_conv<<<64,  256>>>(Wp, wph, wpl, CC*CC/4);

    // U1 = Wp Wq^T, U2 = Wp Wk^T
    k_gemm_w<<<dim3(6,6), 256, SMEM_BYTES>>>(wph, wpl, wqh, wql, u1h, u1l);
    k_gemm_w<<<dim3(6,6), 256, SMEM_BYTES>>>(wph, wpl, wkh, wkl, u2h, u2l);

    // Q = x Wq^T, K = x Wk^T (per-head split planes)
    k_gemm_proj<<<dim3(64,6), 256, SMEM_BYTES>>>(xh, xl, wqh, wql, qh, ql);
    k_gemm_proj<<<dim3(64,6), 256, SMEM_BYTES>>>(xh, xl, wkh, wkl, kh, kl);

    // flash softmax stats (m, 1/l) — S never hits HBM
    k_statsf<<<dim3(8, BH), 256, ST_BYTES>>>();

    // fused S -> P -> Ck/Cq
    k_attn_f<<<dim3(8, BH), 256, AT_BYTES>>>();

    // out = Ck U1^T + Cq U2^T + bp
    k_gemm_out<<<dim3(64, 6), 256, SMEM_BYTES>>>(bp, out);
}

// round 7
// speedup vs baseline: 2.2035x; 1.2982x over previous
#include <cuda_runtime.h>
#include <cuda_bf16.h>
#include <cstdint>
#include <math.h>

#define BB 8
#define NN 1024
#define CC 768
#define HH 12
#define ZZ 64
#define BH (BB*HH)
#define SCALE 0.125f
typedef __nv_bfloat16 bf16;

// ---------------- scratch ----------------
__device__ bf16 g_xh[BB*NN*CC], g_xl[BB*NN*CC];
__device__ bf16 g_Wqh[CC*CC], g_Wql[CC*CC], g_Wkh[CC*CC], g_Wkl[CC*CC];
__device__ bf16 g_Wph[CC*CC], g_Wpl[CC*CC];
__device__ bf16 g_U1h[CC*CC], g_U1l[CC*CC], g_U2h[CC*CC], g_U2l[CC*CC];
__device__ bf16 g_Qh[BH*NN*ZZ], g_Ql[BH*NN*ZZ], g_Kh[BH*NN*ZZ], g_Kl[BH*NN*ZZ];
__device__ float g_m[BH*NN], g_il[BH*NN];
__device__ bf16 g_Ckh[BB*NN*CC], g_Ckl[BB*NN*CC], g_Cqh[BB*NN*CC], g_Cql[BB*NN*CC];

// ---------------- helpers ----------------
#define SW(o) ((o) ^ (((o)>>3)&0x70))
#define OFF_AH 0
#define OFF_AL 16384
#define OFF_BH 32768
#define OFF_BL 49152
#define STG 65536
#define SMEM_BYTES 131072

__device__ __forceinline__ uint32_t smem_u32(const void* p){
    uint32_t a;
    asm("{ .reg .u64 t; cvta.to.shared.u64 t, %1; cvt.u32.u64 %0, t; }" : "=r"(a) : "l"(p));
    return a;
}
__device__ __forceinline__ void ldsm_x4(uint32_t& r0, uint32_t& r1, uint32_t& r2, uint32_t& r3, uint32_t addr){
    asm volatile("ldmatrix.sync.aligned.m8n8.x4.shared.b16 {%0,%1,%2,%3}, [%4];"
        : "=r"(r0), "=r"(r1), "=r"(r2), "=r"(r3) : "r"(addr));
}
__device__ __forceinline__ void ldsm_x4_t(uint32_t& r0, uint32_t& r1, uint32_t& r2, uint32_t& r3, uint32_t addr){
    asm volatile("ldmatrix.sync.aligned.m8n8.x4.trans.shared.b16 {%0,%1,%2,%3}, [%4];"
        : "=r"(r0), "=r"(r1), "=r"(r2), "=r"(r3) : "r"(addr));
}
__device__ __forceinline__ void mma16816(float c[4], const uint32_t a[4], uint32_t b0, uint32_t b1){
    asm volatile("mma.sync.aligned.m16n8k16.row.col.f32.bf16.bf16.f32 "
        "{%0,%1,%2,%3}, {%4,%5,%6,%7}, {%8,%9}, {%0,%1,%2,%3};"
        : "+f"(c[0]), "+f"(c[1]), "+f"(c[2]), "+f"(c[3])
        : "r"(a[0]), "r"(a[1]), "r"(a[2]), "r"(a[3]), "r"(b0), "r"(b1));
}
__device__ __forceinline__ void cp16(uint32_t saddr, const void* g){
    asm volatile("cp.async.cg.shared.global [%0], [%1], 16;" :: "r"(saddr), "l"(g));
}
#define CP_COMMIT() asm volatile("cp.async.commit_group;" ::: "memory")
#define CP_WAIT1()  asm volatile("cp.async.wait_group 1;" ::: "memory")

__device__ __forceinline__ float fexp(float x){
    float y = x * 1.4426950408889634f;
    float n = rintf(y);
    float f = y - n;
    float p = 1.3333558146428443e-3f;
    p = fmaf(p, f, 9.6181291076284772e-3f);
    p = fmaf(p, f, 5.5504108664821580e-2f);
    p = fmaf(p, f, 2.4022650695910072e-1f);
    p = fmaf(p, f, 6.9314718055994531e-1f);
    p = fmaf(p, f, 1.0f);
    return __int_as_float(__float_as_int(p) + (((int)n) << 23));
}
__device__ __forceinline__ void split2(float v, bf16& hi, bf16& lo){
    hi = __float2bfloat16(v);
    lo = __float2bfloat16(v - __bfloat162float(hi));
}
__device__ __forceinline__ void split_pair(float a, float b, uint32_t& hi, uint32_t& lo){
    bf16 ah, al, bh_, bl;
    split2(a, ah, al); split2(b, bh_, bl);
    hi = (uint32_t)__bfloat16_as_ushort(ah) | ((uint32_t)__bfloat16_as_ushort(bh_) << 16);
    lo = (uint32_t)__bfloat16_as_ushort(al) | ((uint32_t)__bfloat16_as_ushort(bl) << 16);
}

// sync tile loader: rows x 64 bf16 (128B rows), swizzled
__device__ __forceinline__ void ld_tile(char* sm, int off, const bf16* __restrict__ g,
                                        int rows, int rstride, int tid){
    for (int i = tid; i < rows*8; i += 256){
        int r = i >> 3, c = i & 7;
        uint4 v = *reinterpret_cast<const uint4*>(g + (size_t)r*rstride + c*8);
        *reinterpret_cast<uint4*>(sm + off + SW(r*128 + c*16)) = v;
    }
}
// async tile loader (128 rows x 64 bf16)
__device__ __forceinline__ void ld_tile_a(uint32_t sbase, int off, const bf16* __restrict__ g,
                                          int rstride, int tid){
    for (int i = tid; i < 128*8; i += 256){
        int r = i >> 3, c = i & 7;
        cp16(sbase + off + SW(r*128 + c*16), g + (size_t)r*rstride + c*8);
    }
}

// ---- re-scheduled split-bf16 block MMA: 3 term-passes, 16 indep accumulators
__device__ __forceinline__ void mma_block_chunk(float c[2][8][4],
        uint32_t aH, uint32_t aL, uint32_t bH, uint32_t bL, int wm0, int wn0, int lane){
    const int lr = lane & 15, lh = lane >> 4;
#pragma unroll
    for (int ks = 0; ks < 4; ks++){
        uint32_t ah[2][4], al[2][4];
#pragma unroll
        for (int ma = 0; ma < 2; ma++){
            uint32_t off = SW((wm0 + ma*16 + lr)*128 + (ks*2 + lh)*16);
            ldsm_x4(ah[ma][0], ah[ma][1], ah[ma][2], ah[ma][3], aH + off);
            ldsm_x4(al[ma][0], al[ma][1], al[ma][2], al[ma][3], aL + off);
        }
        uint32_t bh[4][4], bl[4][4];
#pragma unroll
        for (int np = 0; np < 4; np++){
            uint32_t off = SW((wn0 + np*16 + lr)*128 + (ks*2 + lh)*16);
            ldsm_x4(bh[np][0], bh[np][1], bh[np][2], bh[np][3], bH + off);
            ldsm_x4(bl[np][0], bl[np][1], bl[np][2], bl[np][3], bL + off);
        }
#pragma unroll
        for (int np = 0; np < 4; np++)
#pragma unroll
        for (int ma = 0; ma < 2; ma++){
            mma16816(c[ma][np*2],   ah[ma], bh[np][0], bh[np][2]);
            mma16816(c[ma][np*2+1], ah[ma], bh[np][1], bh[np][3]);
        }
#pragma unroll
        for (int np = 0; np < 4; np++)
#pragma unroll
        for (int ma = 0; ma < 2; ma++){
            mma16816(c[ma][np*2],   al[ma], bh[np][0], bh[np][2]);
            mma16816(c[ma][np*2+1], al[ma], bh[np][1], bh[np][3]);
        }
#pragma unroll
        for (int np = 0; np < 4; np++)
#pragma unroll
        for (int ma = 0; ma < 2; ma++){
            mma16816(c[ma][np*2],   ah[ma], bl[np][0], bl[np][2]);
            mma16816(c[ma][np*2+1], ah[ma], bl[np][1], bl[np][3]);
        }
    }
}

#define MMA_PRE() \
    extern __shared__ char sm[]; \
    const int tid = threadIdx.x, wid = tid >> 5, lane = tid & 31; \
    const uint32_t sbase = smem_u32(sm); \
    const int wm0 = (wid & 3) * 32, wn0 = (wid >> 2) * 64; \
    float c[2][8][4]; \
    _Pragma("unroll") for (int i = 0; i < 2; i++) \
    _Pragma("unroll") for (int j = 0; j < 8; j++) \
    _Pragma("unroll") for (int k = 0; k < 4; k++) c[i][j][k] = 0.0f;

// ============================ split-convert =================================
__global__ __launch_bounds__(256) void k_conv(const float* __restrict__ in,
                                              bf16* __restrict__ oh, bf16* __restrict__ ol, int n4){
    for (int i = blockIdx.x*blockDim.x + threadIdx.x; i < n4; i += gridDim.x*blockDim.x){
        float4 v = reinterpret_cast<const float4*>(in)[i];
        uint32_t h0, l0, h1, l1;
        split_pair(v.x, v.y, h0, l0);
        split_pair(v.z, v.w, h1, l1);
        reinterpret_cast<uint2*>(oh)[i] = make_uint2(h0, h1);
        reinterpret_cast<uint2*>(ol)[i] = make_uint2(l0, l1);
    }
}

// ============================ weight GEMM: U = A * B^T ======================
__global__ __launch_bounds__(256) void k_gemm_w(
    const bf16* __restrict__ Ah, const bf16* __restrict__ Al,
    const bf16* __restrict__ Bh, const bf16* __restrict__ Bl,
    bf16* __restrict__ Oh, bf16* __restrict__ Ol)
{
    MMA_PRE();
    const int m0 = blockIdx.x*128, n0 = blockIdx.y*128;
    ld_tile_a(sbase, OFF_AH, Ah + (size_t)m0*CC, CC, tid);
    ld_tile_a(sbase, OFF_AL, Al + (size_t)m0*CC, CC, tid);
    ld_tile_a(sbase, OFF_BH, Bh + (size_t)n0*CC, CC, tid);
    ld_tile_a(sbase, OFF_BL, Bl + (size_t)n0*CC, CC, tid);
    CP_COMMIT();
    for (int kc = 0; kc < 12; kc++){
        int st = (kc & 1) * STG;
        if (kc + 1 < 12){
            int s2 = ((kc+1) & 1) * STG;
            ld_tile_a(sbase, s2 + OFF_AH, Ah + (size_t)m0*CC + (kc+1)*64, CC, tid);
            ld_tile_a(sbase, s2 + OFF_AL, Al + (size_t)m0*CC + (kc+1)*64, CC, tid);
            ld_tile_a(sbase, s2 + OFF_BH, Bh + (size_t)n0*CC + (kc+1)*64, CC, tid);
            ld_tile_a(sbase, s2 + OFF_BL, Bl + (size_t)n0*CC + (kc+1)*64, CC, tid);
        }
        CP_COMMIT();
        CP_WAIT1();
        __syncthreads();
        mma_block_chunk(c, sbase+st+OFF_AH, sbase+st+OFF_AL, sbase+st+OFF_BH, sbase+st+OFF_BL, wm0, wn0, lane);
        __syncthreads();
    }
    const int gid = lane >> 2, tg = lane & 3;
#pragma unroll
    for (int ma = 0; ma < 2; ma++)
#pragma unroll
    for (int na = 0; na < 8; na++){
        int row = m0 + wm0 + ma*16 + gid;
        int col = n0 + wn0 + na*8 + tg*2;
        uint32_t hi, lo;
        split_pair(c[ma][na][0], c[ma][na][1], hi, lo);
        *reinterpret_cast<uint32_t*>(Oh + (size_t)row*CC + col) = hi;
        *reinterpret_cast<uint32_t*>(Ol + (size_t)row*CC + col) = lo;
        split_pair(c[ma][na][2], c[ma][na][3], hi, lo);
        *reinterpret_cast<uint32_t*>(Oh + (size_t)(row+8)*CC + col) = hi;
        *reinterpret_cast<uint32_t*>(Ol + (size_t)(row+8)*CC + col) = lo;
    }
}

// ============================ projection GEMM (per-head scatter) ============
__global__ __launch_bounds__(256) void k_gemm_proj(
    const bf16* __restrict__ Ah, const bf16* __restrict__ Al,
    const bf16* __restrict__ Bh, const bf16* __restrict__ Bl,
    bf16* __restrict__ Oh, bf16* __restrict__ Ol)
{
    MMA_PRE();
    const int m0 = blockIdx.x*128, n0 = blockIdx.y*128;
    ld_tile_a(sbase, OFF_AH, Ah + (size_t)m0*CC, CC, tid);
    ld_tile_a(sbase, OFF_AL, Al + (size_t)m0*CC, CC, tid);
    ld_tile_a(sbase, OFF_BH, Bh + (size_t)n0*CC, CC, tid);
    ld_tile_a(sbase, OFF_BL, Bl + (size_t)n0*CC, CC, tid);
    CP_COMMIT();
    for (int kc = 0; kc < 12; kc++){
        int st = (kc & 1) * STG;
        if (kc + 1 < 12){
            int s2 = ((kc+1) & 1) * STG;
            ld_tile_a(sbase, s2 + OFF_AH, Ah + (size_t)m0*CC + (kc+1)*64, CC, tid);
            ld_tile_a(sbase, s2 + OFF_AL, Al + (size_t)m0*CC + (kc+1)*64, CC, tid);
            ld_tile_a(sbase, s2 + OFF_BH, Bh + (size_t)n0*CC + (kc+1)*64, CC, tid);
            ld_tile_a(sbase, s2 + OFF_BL, Bl + (size_t)n0*CC + (kc+1)*64, CC, tid);
        }
        CP_COMMIT();
        CP_WAIT1();
        __syncthreads();
        mma_block_chunk(c, sbase+st+OFF_AH, sbase+st+OFF_AL, sbase+st+OFF_BH, sbase+st+OFF_BL, wm0, wn0, lane);
        __syncthreads();
    }
    const int gid = lane >> 2, tg = lane & 3;
#pragma unroll
    for (int ma = 0; ma < 2; ma++)
#pragma unroll
    for (int na = 0; na < 8; na++){
        int col = n0 + wn0 + na*8 + tg*2;
        int h = col >> 6, z = col & 63;
#pragma unroll
        for (int half = 0; half < 2; half++){
            int row = m0 + wm0 + ma*16 + gid + half*8;
            int b = row >> 10, tk = row & (NN-1);
            size_t adr = ((size_t)(b*HH + h)*NN + tk)*ZZ + z;
            uint32_t hi, lo;
            split_pair(c[ma][na][half*2], c[ma][na][half*2+1], hi, lo);
            *reinterpret_cast<uint32_t*>(Oh + adr) = hi;
            *reinterpret_cast<uint32_t*>(Ol + adr) = lo;
        }
    }
}

// ============================ flash stats ===================================
#define ST_QH 0
#define ST_QL 16384
#define ST_KH 32768
#define ST_KL 49152
#define ST_MM 65536
#define ST_LL 66560
#define ST_BYTES 67584
__global__ __launch_bounds__(256, 1) void k_statsf(){
    extern __shared__ char sm[];
    const int tid = threadIdx.x, wid = tid >> 5, lane = tid & 31;
    const uint32_t sbase = smem_u32(sm);
    const int bh = blockIdx.y, q0 = blockIdx.x*128;
    const int wq = (wid & 3)*32, wt = (wid >> 2)*64;
    const int gid = lane >> 2, tg = lane & 3;

    ld_tile(sm, ST_QH, g_Qh + ((size_t)bh*NN + q0)*ZZ, 128, ZZ, tid);
    ld_tile(sm, ST_QL, g_Ql + ((size_t)bh*NN + q0)*ZZ, 128, ZZ, tid);

    float rm[2][2], rl[2][2];
#pragma unroll
    for (int i = 0; i < 2; i++)
#pragma unroll
    for (int j = 0; j < 2; j++){ rm[i][j] = -1e30f; rl[i][j] = 0.0f; }

    for (int t0 = 0; t0 < NN; t0 += 128){
        __syncthreads();
        ld_tile(sm, ST_KH, g_Kh + ((size_t)bh*NN + t0)*ZZ, 128, ZZ, tid);
        ld_tile(sm, ST_KL, g_Kl + ((size_t)bh*NN + t0)*ZZ, 128, ZZ, tid);
        __syncthreads();

        float s[2][8][4];
#pragma unroll
        for (int i = 0; i < 2; i++)
#pragma unroll
        for (int j = 0; j < 8; j++)
#pragma unroll
        for (int k = 0; k < 4; k++) s[i][j][k] = 0.0f;

        mma_block_chunk(s, sbase+ST_QH, sbase+ST_QL, sbase+ST_KH, sbase+ST_KL, wq, wt, lane);

#pragma unroll
        for (int ma = 0; ma < 2; ma++)
#pragma unroll
        for (int half = 0; half < 2; half++){
            float cm = -1e30f;
#pragma unroll
            for (int na = 0; na < 8; na++)
                cm = fmaxf(cm, fmaxf(s[ma][na][half*2], s[ma][na][half*2+1]));
            cm *= SCALE;
            cm = fmaxf(cm, __shfl_xor_sync(0xffffffffu, cm, 1));
            cm = fmaxf(cm, __shfl_xor_sync(0xffffffffu, cm, 2));
            float nm = fmaxf(rm[ma][half], cm);
            float ls = 0.0f;
#pragma unroll
            for (int na = 0; na < 8; na++)
                ls += fexp(s[ma][na][half*2]*SCALE - nm) + fexp(s[ma][na][half*2+1]*SCALE - nm);
            ls += __shfl_xor_sync(0xffffffffu, ls, 1);
            ls += __shfl_xor_sync(0xffffffffu, ls, 2);
            float d = fmaxf(rm[ma][half] - nm, -60.0f);
            rl[ma][half] = rl[ma][half]*fexp(d) + ls;
            rm[ma][half] = nm;
        }
    }
    float* smm = reinterpret_cast<float*>(sm + ST_MM);
    float* sml = reinterpret_cast<float*>(sm + ST_LL);
    __syncthreads();
    if (tg == 0){
#pragma unroll
        for (int ma = 0; ma < 2; ma++)
#pragma unroll
        for (int half = 0; half < 2; half++){
            int q = wq + ma*16 + gid + half*8;
            int wti = wid >> 2;
            smm[wti*128 + q] = rm[ma][half];
            sml[wti*128 + q] = rl[ma][half];
        }
    }
    __syncthreads();
    if (tid < 128){
        float m0 = smm[tid], m1 = smm[128 + tid];
        float l0 = sml[tid], l1 = sml[128 + tid];
        float m = fmaxf(m0, m1);
        float l = l0*fexp(fmaxf(m0 - m, -60.0f)) + l1*fexp(fmaxf(m1 - m, -60.0f));
        g_m [bh*NN + q0 + tid] = m;
        g_il[bh*NN + q0 + tid] = 1.0f / l;
    }
}

// ============================ fused attention pass ==========================
#define AT_KTH 0
#define AT_KTL 16384
#define AT_QCH 32768
#define AT_QCL 40960
#define AT_KCH 49152
#define AT_KCL 57344
#define AT_PH  65536
#define AT_PL  81920
#define AT_MS  98304
#define AT_IL  98560
#define AT_BYTES 98816
__global__ __launch_bounds__(256, 1) void k_attn_f(){
    extern __shared__ char sm[];
    const int tid = threadIdx.x, wid = tid >> 5, lane = tid & 31;
    const uint32_t sbase = smem_u32(sm);
    const int bh = blockIdx.y, t0 = blockIdx.x*128;
    const int gid = lane >> 2, tg = lane & 3;
    const int lr = lane & 15, lh = lane >> 4;
    const int srow_off = (lane & 7) + ((lane & 16) ? 8 : 0);
    const int scol8 = ((lane >> 3) & 1) * 8;
    float* ms = reinterpret_cast<float*>(sm + AT_MS);
    float* il = reinterpret_cast<float*>(sm + AT_IL);

    const int wt2 = (wid & 3)*32, wz = wid >> 2;
    float c[2][8][4];
#pragma unroll
    for (int i = 0; i < 2; i++)
#pragma unroll
    for (int j = 0; j < 8; j++)
#pragma unroll
    for (int k = 0; k < 4; k++) c[i][j][k] = 0.0f;

    ld_tile(sm, AT_KTH, g_Kh + ((size_t)bh*NN + t0)*ZZ, 128, ZZ, tid);
    ld_tile(sm, AT_KTL, g_Kl + ((size_t)bh*NN + t0)*ZZ, 128, ZZ, tid);

    const int wq1 = (wid & 1)*32, wt1 = (wid >> 1)*32;

    for (int q0c = 0; q0c < NN; q0c += 64){
        __syncthreads();
        ld_tile(sm, AT_QCH, g_Qh + ((size_t)bh*NN + q0c)*ZZ, 64, ZZ, tid);
        ld_tile(sm, AT_QCL, g_Ql + ((size_t)bh*NN + q0c)*ZZ, 64, ZZ, tid);
        ld_tile(sm, AT_KCH, g_Kh + ((size_t)bh*NN + q0c)*ZZ, 64, ZZ, tid);
        ld_tile(sm, AT_KCL, g_Kl + ((size_t)bh*NN + q0c)*ZZ, 64, ZZ, tid);
        if (tid < 64)       ms[tid]      = g_m [bh*NN + q0c + tid];
        else if (tid < 128) il[tid - 64] = g_il[bh*NN + q0c + tid - 64];
        __syncthreads();

        // ---- phase 1: S chunk -> P smem ----
        {
            float s1[2][4][4];
#pragma unroll
            for (int i = 0; i < 2; i++)
#pragma unroll
            for (int j = 0; j < 4; j++)
#pragma unroll
            for (int k = 0; k < 4; k++) s1[i][j][k] = 0.0f;
#pragma unroll
            for (int ks = 0; ks < 4; ks++){
                uint32_t ah[2][4], al[2][4];
#pragma unroll
                for (int ma = 0; ma < 2; ma++){
                    uint32_t off = SW((wq1 + ma*16 + lr)*128 + (ks*2 + lh)*16);
                    ldsm_x4(ah[ma][0], ah[ma][1], ah[ma][2], ah[ma][3], sbase + AT_QCH + off);
                    ldsm_x4(al[ma][0], al[ma][1], al[ma][2], al[ma][3], sbase + AT_QCL + off);
                }
                uint32_t bh4[2][4], bl4[2][4];
#pragma unroll
                for (int np = 0; np < 2; np++){
                    uint32_t off = SW((wt1 + np*16 + lr)*128 + (ks*2 + lh)*16);
                    ldsm_x4(bh4[np][0], bh4[np][1], bh4[np][2], bh4[np][3], sbase + AT_KTH + off);
                    ldsm_x4(bl4[np][0], bl4[np][1], bl4[np][2], bl4[np][3], sbase + AT_KTL + off);
                }
#pragma unroll
                for (int np = 0; np < 2; np++)
#pragma unroll
                for (int ma = 0; ma < 2; ma++){
                    mma16816(s1[ma][np*2],   ah[ma], bh4[np][0], bh4[np][2]);
                    mma16816(s1[ma][np*2+1], ah[ma], bh4[np][1], bh4[np][3]);
                }
#pragma unroll
                for (int np = 0; np < 2; np++)
#pragma unroll
                for (int ma = 0; ma < 2; ma++){
                    mma16816(s1[ma][np*2],   al[ma], bh4[np][0], bh4[np][2]);
                    mma16816(s1[ma][np*2+1], al[ma], bh4[np][1], bh4[np][3]);
                }
#pragma unroll
                for (int np = 0; np < 2; np++)
#pragma unroll
                for (int ma = 0; ma < 2; ma++){
                    mma16816(s1[ma][np*2],   ah[ma], bl4[np][0], bl4[np][2]);
                    mma16816(s1[ma][np*2+1], ah[ma], bl4[np][1], bl4[np][3]);
                }
            }
#pragma unroll
            for (int ma = 0; ma < 2; ma++)
#pragma unroll
            for (int na = 0; na < 4; na++)
#pragma unroll
            for (int half = 0; half < 2; half++){
                int qloc = wq1 + ma*16 + gid + half*8;
                float M = ms[qloc], I = il[qloc];
                int tloc = wt1 + na*8 + tg*2;
                float p0 = fexp(s1[ma][na][half*2]  *SCALE - M)*I;
                float p1 = fexp(s1[ma][na][half*2+1]*SCALE - M)*I;
                uint32_t hi, lo; split_pair(p0, p1, hi, lo);
                uint32_t off = (uint32_t)(tloc >> 6)*8192 + SW(qloc*128 + (tloc & 63)*2);
                *reinterpret_cast<uint32_t*>(sm + AT_PH + off) = hi;
                *reinterpret_cast<uint32_t*>(sm + AT_PL + off) = lo;
            }
        }
        __syncthreads();

        // ---- phase 2: Ck/Cq += P^T [K|Q] ----
        {
            const int bsh = wz ? AT_QCH : AT_KCH;
            const int bsl = wz ? AT_QCL : AT_KCL;
#pragma unroll
            for (int ks = 0; ks < 4; ks++){
                int qk = ks*16;
                uint32_t ah[2][4], al[2][4];
#pragma unroll
                for (int ma = 0; ma < 2; ma++){
                    int tcol = wt2 + ma*16;
                    uint32_t off = (uint32_t)(tcol >> 6)*8192
                                 + SW((qk + srow_off)*128 + ((tcol & 63) + scol8)*2);
                    ldsm_x4_t(ah[ma][0], ah[ma][1], ah[ma][2], ah[ma][3], sbase + AT_PH + off);
                    ldsm_x4_t(al[ma][0], al[ma][1], al[ma][2], al[ma][3], sbase + AT_PL + off);
                }
                uint32_t bh4[4][4], bl4[4][4];
#pragma unroll
                for (int zn = 0; zn < 4; zn++){
                    uint32_t off = SW((qk + srow_off)*128 + (zn*16 + scol8)*2);
                    ldsm_x4_t(bh4[zn][0], bh4[zn][1], bh4[zn][2], bh4[zn][3], sbase + bsh + off);
                    ldsm_x4_t(bl4[zn][0], bl4[zn][1], bl4[zn][2], bl4[zn][3], sbase + bsl + off);
                }
#pragma unroll
                for (int zn = 0; zn < 4; zn++)
#pragma unroll
                for (int ma = 0; ma < 2; ma++){
                    mma16816(c[ma][zn*2],   ah[ma], bh4[zn][0], bh4[zn][2]);
                    mma16816(c[ma][zn*2+1], ah[ma], bh4[zn][1], bh4[zn][3]);
                }
#pragma unroll
                for (int zn = 0; zn < 4; zn++)
#pragma unroll
                for (int ma = 0; ma < 2; ma++){
                    mma16816(c[ma][zn*2],   al[ma], bh4[zn][0], bh4[zn][2]);
                    mma16816(c[ma][zn*2+1], al[ma], bh4[zn][1], bh4[zn][3]);
                }
#pragma unroll
                for (int zn = 0; zn < 4; zn++)
#pragma unroll
                for (int ma = 0; ma < 2; ma++){
                    mma16816(c[ma][zn*2],   ah[ma], bl4[zn][0], bl4[zn][2]);
                    mma16816(c[ma][zn*2+1], ah[ma], bl4[zn][1], bl4[zn][3]);
                }
            }
        }
    }
    const int b = bh / HH, h = bh - b*HH;
    bf16* Oh = wz ? g_Cqh : g_Ckh;
    bf16* Ol = wz ? g_Cql : g_Ckl;
#pragma unroll
    for (int ma = 0; ma < 2; ma++)
#pragma unroll
    for (int na = 0; na < 8; na++){
        int z = na*8 + tg*2;
#pragma unroll
        for (int half = 0; half < 2; half++){
            int t = t0 + wt2 + ma*16 + gid + half*8;
            size_t adr = ((size_t)b*NN + t)*CC + h*ZZ + z;
            uint32_t hi, lo;
            split_pair(c[ma][na][half*2], c[ma][na][half*2+1], hi, lo);
            *reinterpret_cast<uint32_t*>(Oh + adr) = hi;
            *reinterpret_cast<uint32_t*>(Ol + adr) = lo;
        }
    }
}

// ============================ out = Ck U1^T + Cq U2^T + bp ==================
__global__ __launch_bounds__(256) void k_gemm_out(const float* __restrict__ bp,
                                                  float* __restrict__ out){
    MMA_PRE();
    const int m0 = blockIdx.x*128, n0 = blockIdx.y*128;
    ld_tile_a(sbase, OFF_AH, g_Ckh + (size_t)m0*CC, CC, tid);
    ld_tile_a(sbase, OFF_AL, g_Ckl + (size_t)m0*CC, CC, tid);
    ld_tile_a(sbase, OFF_BH, g_U1h + (size_t)n0*CC, CC, tid);
    ld_tile_a(sbase, OFF_BL, g_U1l + (size_t)n0*CC, CC, tid);
    CP_COMMIT();
    for (int it = 0; it < 24; it++){
        int st = (it & 1) * STG;
        if (it + 1 < 24){
            int i2 = it + 1;
            int pr = i2 & 1, kc = i2 >> 1;
            const bf16* Ah = pr ? g_Cqh : g_Ckh;
            const bf16* Al = pr ? g_Cql : g_Ckl;
            const bf16* Bh = pr ? g_U2h : g_U1h;
            const bf16* Bl = pr ? g_U2l : g_U1l;
            int s2 = (i2 & 1) * STG;
            ld_tile_a(sbase, s2 + OFF_AH, Ah + (size_t)m0*CC + kc*64, CC, tid);
            ld_tile_a(sbase, s2 + OFF_AL, Al + (size_t)m0*CC + kc*64, CC, tid);
            ld_tile_a(sbase, s2 + OFF_BH, Bh + (size_t)n0*CC + kc*64, CC, tid);
            ld_tile_a(sbase, s2 + OFF_BL, Bl + (size_t)n0*CC + kc*64, CC, tid);
        }
        CP_COMMIT();
        CP_WAIT1();
        __syncthreads();
        mma_block_chunk(c, sbase+st+OFF_AH, sbase+st+OFF_AL, sbase+st+OFF_BH, sbase+st+OFF_BL, wm0, wn0, lane);
        __syncthreads();
    }
    const int gid = lane >> 2, tg = lane & 3;
#pragma unroll
    for (int ma = 0; ma < 2; ma++)
#pragma unroll
    for (int na = 0; na < 8; na++){
        int row = m0 + wm0 + ma*16 + gid;
        int col = n0 + wn0 + na*8 + tg*2;
        float b0 = bp[col], b1 = bp[col+1];
        *reinterpret_cast<float2*>(out + (size_t)row*CC + col)
            = make_float2(c[ma][na][0] + b0, c[ma][na][1] + b1);
        *reinterpret_cast<float2*>(out + (size_t)(row+8)*CC + col)
            = make_float2(c[ma][na][2] + b0, c[ma][na][3] + b1);
    }
}

// ============================ host ==========================================
extern "C" void kernel_launch(void* const* d_in, const int* in_sizes, int n_in,
                              void* d_out, int out_size)
{
    (void)in_sizes; (void)n_in; (void)out_size;
    const float* x  = (const float*)d_in[0];
    const float* Wq = (const float*)d_in[1];
    const float* Wk = (const float*)d_in[2];
    const float* Wp = (const float*)d_in[3];
    const float* bp = (const float*)d_in[4];
    float* out = (float*)d_out;

    bf16 *xh, *xl, *wqh, *wql, *wkh, *wkl, *wph, *wpl;
    cudaGetSymbolAddress((void**)&xh,  g_xh);  cudaGetSymbolAddress((void**)&xl,  g_xl);
    cudaGetSymbolAddress((void**)&wqh, g_Wqh); cudaGetSymbolAddress((void**)&wql, g_Wql);
    cudaGetSymbolAddress((void**)&wkh, g_Wkh); cudaGetSymbolAddress((void**)&wkl, g_Wkl);
    cudaGetSymbolAddress((void**)&wph, g_Wph); cudaGetSymbolAddress((void**)&wpl, g_Wpl);
    bf16 *u1h, *u1l, *u2h, *u2l, *qh, *ql, *kh, *kl;
    cudaGetSymbolAddress((void**)&u1h, g_U1h); cudaGetSymbolAddress((void**)&u1l, g_U1l);
    cudaGetSymbolAddress((void**)&u2h, g_U2h); cudaGetSymbolAddress((void**)&u2l, g_U2l);
    cudaGetSymbolAddress((void**)&qh,  g_Qh);  cudaGetSymbolAddress((void**)&ql,  g_Ql);
    cudaGetSymbolAddress((void**)&kh,  g_Kh);  cudaGetSymbolAddress((void**)&kl,  g_Kl);

    cudaFuncSetAttribute(k_gemm_w,    cudaFuncAttributeMaxDynamicSharedMemorySize, SMEM_BYTES);
    cudaFuncSetAttribute(k_gemm_proj, cudaFuncAttributeMaxDynamicSharedMemorySize, SMEM_BYTES);
    cudaFuncSetAttribute(k_gemm_out,  cudaFuncAttributeMaxDynamicSharedMemorySize, SMEM_BYTES);
    cudaFuncSetAttribute(k_statsf,    cudaFuncAttributeMaxDynamicSharedMemorySize, ST_BYTES);
    cudaFuncSetAttribute(k_attn_f,    cudaFuncAttributeMaxDynamicSharedMemorySize, AT_BYTES);

    k_conv<<<256, 256>>>(x,  xh,  xl,  BB*NN*CC/4);
    k_conv<<<64,  256>>>(Wq, wqh, wql, CC*CC/4);
    k_conv<<<64,  256>>>(Wk, wkh, wkl, CC*CC/4);
    k_conv<<<64,  256>>>(Wp, wph, wpl, CC*CC/4);

    k_gemm_w<<<dim3(6,6), 256, SMEM_BYTES>>>(wph, wpl, wqh, wql, u1h, u1l);
    k_gemm_w<<<dim3(6,6), 256, SMEM_BYTES>>>(wph, wpl, wkh, wkl, u2h, u2l);

    k_gemm_proj<<<dim3(64,6), 256, SMEM_BYTES>>>(xh, xl, wqh, wql, qh, ql);
    k_gemm_proj<<<dim3(64,6), 256, SMEM_BYTES>>>(xh, xl, wkh, wkl, kh, kl);

    k_statsf<<<dim3(8, BH), 256, ST_BYTES>>>();
    k_attn_f<<<dim3(8, BH), 256, AT_BYTES>>>();

    k_gemm_out<<<dim3(64, 6), 256, SMEM_BYTES>>>(bp, out);
}

// round 8
// speedup vs baseline: 3.2515x; 1.4756x over previous
#include <cuda_runtime.h>
#include <cuda_fp16.h>
#include <cstdint>
#include <math.h>

#define BB 8
#define NN 1024
#define CC 768
#define HH 12
#define ZZ 64
#define BH (BB*HH)
#define SCALE 0.125f
typedef __half h16;

// ---------------- scratch ----------------
__device__ h16 g_xh[BB*NN*CC], g_xl[BB*NN*CC];
__device__ h16 g_Wqh[CC*CC], g_Wql[CC*CC], g_Wkh[CC*CC], g_Wkl[CC*CC];
__device__ h16 g_Wph[CC*CC], g_Wpl[CC*CC];
__device__ h16 g_U1h[CC*CC], g_U2h[CC*CC];
__device__ h16 g_Qh[BH*NN*ZZ], g_Kh[BH*NN*ZZ];
__device__ float g_m[BH*NN], g_il[BH*NN];
__device__ h16 g_Ckh[BB*NN*CC], g_Ckl[BB*NN*CC], g_Cqh[BB*NN*CC], g_Cql[BB*NN*CC];

// ---------------- helpers ----------------
#define SW(o) ((o) ^ (((o)>>3)&0x70))
// 3-term dense kernels (w, proj): 4 tiles/stage
#define OFF_AH 0
#define OFF_AL 16384
#define OFF_BH 32768
#define OFF_BL 49152
#define STG 65536
#define SMEM_BYTES 131072
// 2-term out kernel: 3 tiles/stage
#define O2_AH 0
#define O2_AL 16384
#define O2_BH 32768
#define STG2 49152
#define SMEM2 98304

__device__ __forceinline__ uint32_t smem_u32(const void* p){
    uint32_t a;
    asm("{ .reg .u64 t; cvta.to.shared.u64 t, %1; cvt.u32.u64 %0, t; }" : "=r"(a) : "l"(p));
    return a;
}
__device__ __forceinline__ void ldsm_x4(uint32_t& r0, uint32_t& r1, uint32_t& r2, uint32_t& r3, uint32_t addr){
    asm volatile("ldmatrix.sync.aligned.m8n8.x4.shared.b16 {%0,%1,%2,%3}, [%4];"
        : "=r"(r0), "=r"(r1), "=r"(r2), "=r"(r3) : "r"(addr));
}
__device__ __forceinline__ void ldsm_x4_t(uint32_t& r0, uint32_t& r1, uint32_t& r2, uint32_t& r3, uint32_t addr){
    asm volatile("ldmatrix.sync.aligned.m8n8.x4.trans.shared.b16 {%0,%1,%2,%3}, [%4];"
        : "=r"(r0), "=r"(r1), "=r"(r2), "=r"(r3) : "r"(addr));
}
__device__ __forceinline__ void mma16816(float c[4], const uint32_t a[4], uint32_t b0, uint32_t b1){
    asm volatile("mma.sync.aligned.m16n8k16.row.col.f32.f16.f16.f32 "
        "{%0,%1,%2,%3}, {%4,%5,%6,%7}, {%8,%9}, {%0,%1,%2,%3};"
        : "+f"(c[0]), "+f"(c[1]), "+f"(c[2]), "+f"(c[3])
        : "r"(a[0]), "r"(a[1]), "r"(a[2]), "r"(a[3]), "r"(b0), "r"(b1));
}
__device__ __forceinline__ void cp16(uint32_t saddr, const void* g){
    asm volatile("cp.async.cg.shared.global [%0], [%1], 16;" :: "r"(saddr), "l"(g));
}
#define CP_COMMIT() asm volatile("cp.async.commit_group;" ::: "memory")
#define CP_WAIT1()  asm volatile("cp.async.wait_group 1;" ::: "memory")

__device__ __forceinline__ float fexp(float x){
    float y = x * 1.4426950408889634f;
    float n = rintf(y);
    float f = y - n;
    float p = 1.3333558146428443e-3f;
    p = fmaf(p, f, 9.6181291076284772e-3f);
    p = fmaf(p, f, 5.5504108664821580e-2f);
    p = fmaf(p, f, 2.4022650695910072e-1f);
    p = fmaf(p, f, 6.9314718055994531e-1f);
    p = fmaf(p, f, 1.0f);
    return __int_as_float(__float_as_int(p) + (((int)n) << 23));
}
__device__ __forceinline__ void split2(float v, h16& hi, h16& lo){
    hi = __float2half(v);
    lo = __float2half(v - __half2float(hi));
}
__device__ __forceinline__ void split_pair(float a, float b, uint32_t& hi, uint32_t& lo){
    h16 ah, al, bh_, bl;
    split2(a, ah, al); split2(b, bh_, bl);
    hi = (uint32_t)__half_as_ushort(ah) | ((uint32_t)__half_as_ushort(bh_) << 16);
    lo = (uint32_t)__half_as_ushort(al) | ((uint32_t)__half_as_ushort(bl) << 16);
}
__device__ __forceinline__ uint32_t pack2h(float a, float b){
    return (uint32_t)__half_as_ushort(__float2half(a))
         | ((uint32_t)__half_as_ushort(__float2half(b)) << 16);
}

// sync tile loader: rows x 64 h16 (128B rows), swizzled
__device__ __forceinline__ void ld_tile(char* sm, int off, const h16* __restrict__ g,
                                        int rows, int rstride, int tid){
    for (int i = tid; i < rows*8; i += 256){
        int r = i >> 3, c = i & 7;
        uint4 v = *reinterpret_cast<const uint4*>(g + (size_t)r*rstride + c*8);
        *reinterpret_cast<uint4*>(sm + off + SW(r*128 + c*16)) = v;
    }
}
// async tile loader (128 rows x 64 h16)
__device__ __forceinline__ void ld_tile_a(uint32_t sbase, int off, const h16* __restrict__ g,
                                          int rstride, int tid){
    for (int i = tid; i < 128*8; i += 256){
        int r = i >> 3, c = i & 7;
        cp16(sbase + off + SW(r*128 + c*16), g + (size_t)r*rstride + c*8);
    }
}

// 3-term block MMA (A split x B split): AhBh + AlBh + AhBl
__device__ __forceinline__ void mma_chunk3(float c[2][8][4],
        uint32_t aH, uint32_t aL, uint32_t bH, uint32_t bL, int wm0, int wn0, int lane){
    const int lr = lane & 15, lh = lane >> 4;
#pragma unroll
    for (int ks = 0; ks < 4; ks++){
        uint32_t ah[2][4], al[2][4];
#pragma unroll
        for (int ma = 0; ma < 2; ma++){
            uint32_t off = SW((wm0 + ma*16 + lr)*128 + (ks*2 + lh)*16);
            ldsm_x4(ah[ma][0], ah[ma][1], ah[ma][2], ah[ma][3], aH + off);
            ldsm_x4(al[ma][0], al[ma][1], al[ma][2], al[ma][3], aL + off);
        }
        uint32_t bh[4][4], bl[4][4];
#pragma unroll
        for (int np = 0; np < 4; np++){
            uint32_t off = SW((wn0 + np*16 + lr)*128 + (ks*2 + lh)*16);
            ldsm_x4(bh[np][0], bh[np][1], bh[np][2], bh[np][3], bH + off);
            ldsm_x4(bl[np][0], bl[np][1], bl[np][2], bl[np][3], bL + off);
        }
#pragma unroll
        for (int np = 0; np < 4; np++)
#pragma unroll
        for (int ma = 0; ma < 2; ma++){
            mma16816(c[ma][np*2],   ah[ma], bh[np][0], bh[np][2]);
            mma16816(c[ma][np*2+1], ah[ma], bh[np][1], bh[np][3]);
        }
#pragma unroll
        for (int np = 0; np < 4; np++)
#pragma unroll
        for (int ma = 0; ma < 2; ma++){
            mma16816(c[ma][np*2],   al[ma], bh[np][0], bh[np][2]);
            mma16816(c[ma][np*2+1], al[ma], bh[np][1], bh[np][3]);
        }
#pragma unroll
        for (int np = 0; np < 4; np++)
#pragma unroll
        for (int ma = 0; ma < 2; ma++){
            mma16816(c[ma][np*2],   ah[ma], bl[np][0], bl[np][2]);
            mma16816(c[ma][np*2+1], ah[ma], bl[np][1], bl[np][3]);
        }
    }
}

// 2-term block MMA (A split x B single): AhB + AlB
__device__ __forceinline__ void mma_chunk2(float c[2][8][4],
        uint32_t aH, uint32_t aL, uint32_t bH, int wm0, int wn0, int lane){
    const int lr = lane & 15, lh = lane >> 4;
#pragma unroll
    for (int ks = 0; ks < 4; ks++){
        uint32_t ah[2][4], al[2][4];
#pragma unroll
        for (int ma = 0; ma < 2; ma++){
            uint32_t off = SW((wm0 + ma*16 + lr)*128 + (ks*2 + lh)*16);
            ldsm_x4(ah[ma][0], ah[ma][1], ah[ma][2], ah[ma][3], aH + off);
            ldsm_x4(al[ma][0], al[ma][1], al[ma][2], al[ma][3], aL + off);
        }
        uint32_t bh[4][4];
#pragma unroll
        for (int np = 0; np < 4; np++){
            uint32_t off = SW((wn0 + np*16 + lr)*128 + (ks*2 + lh)*16);
            ldsm_x4(bh[np][0], bh[np][1], bh[np][2], bh[np][3], bH + off);
        }
#pragma unroll
        for (int np = 0; np < 4; np++)
#pragma unroll
        for (int ma = 0; ma < 2; ma++){
            mma16816(c[ma][np*2],   ah[ma], bh[np][0], bh[np][2]);
            mma16816(c[ma][np*2+1], ah[ma], bh[np][1], bh[np][3]);
        }
#pragma unroll
        for (int np = 0; np < 4; np++)
#pragma unroll
        for (int ma = 0; ma < 2; ma++){
            mma16816(c[ma][np*2],   al[ma], bh[np][0], bh[np][2]);
            mma16816(c[ma][np*2+1], al[ma], bh[np][1], bh[np][3]);
        }
    }
}

// 1-term block MMA (both single)
__device__ __forceinline__ void mma_chunk1(float c[2][8][4],
        uint32_t aH, uint32_t bH, int wm0, int wn0, int lane){
    const int lr = lane & 15, lh = lane >> 4;
#pragma unroll
    for (int ks = 0; ks < 4; ks++){
        uint32_t ah[2][4];
#pragma unroll
        for (int ma = 0; ma < 2; ma++){
            uint32_t off = SW((wm0 + ma*16 + lr)*128 + (ks*2 + lh)*16);
            ldsm_x4(ah[ma][0], ah[ma][1], ah[ma][2], ah[ma][3], aH + off);
        }
        uint32_t bh[4][4];
#pragma unroll
        for (int np = 0; np < 4; np++){
            uint32_t off = SW((wn0 + np*16 + lr)*128 + (ks*2 + lh)*16);
            ldsm_x4(bh[np][0], bh[np][1], bh[np][2], bh[np][3], bH + off);
        }
#pragma unroll
        for (int np = 0; np < 4; np++)
#pragma unroll
        for (int ma = 0; ma < 2; ma++){
            mma16816(c[ma][np*2],   ah[ma], bh[np][0], bh[np][2]);
            mma16816(c[ma][np*2+1], ah[ma], bh[np][1], bh[np][3]);
        }
    }
}

#define MMA_PRE() \
    extern __shared__ char sm[]; \
    const int tid = threadIdx.x, wid = tid >> 5, lane = tid & 31; \
    const uint32_t sbase = smem_u32(sm); \
    const int wm0 = (wid & 3) * 32, wn0 = (wid >> 2) * 64; \
    float c[2][8][4]; \
    _Pragma("unroll") for (int i = 0; i < 2; i++) \
    _Pragma("unroll") for (int j = 0; j < 8; j++) \
    _Pragma("unroll") for (int k = 0; k < 4; k++) c[i][j][k] = 0.0f;

// ============================ split-convert =================================
__global__ __launch_bounds__(256) void k_conv(const float* __restrict__ in,
                                              h16* __restrict__ oh, h16* __restrict__ ol, int n4){
    for (int i = blockIdx.x*blockDim.x + threadIdx.x; i < n4; i += gridDim.x*blockDim.x){
        float4 v = reinterpret_cast<const float4*>(in)[i];
        uint32_t h0, l0, h1, l1;
        split_pair(v.x, v.y, h0, l0);
        split_pair(v.z, v.w, h1, l1);
        reinterpret_cast<uint2*>(oh)[i] = make_uint2(h0, h1);
        reinterpret_cast<uint2*>(ol)[i] = make_uint2(l0, l1);
    }
}

// ============================ weight GEMM: U = Wp * W^T (3-term, hi-only out)
__global__ __launch_bounds__(256) void k_gemm_w(
    const h16* __restrict__ Ah, const h16* __restrict__ Al,
    const h16* __restrict__ Bh, const h16* __restrict__ Bl,
    h16* __restrict__ Oh)
{
    MMA_PRE();
    const int m0 = blockIdx.x*128, n0 = blockIdx.y*128;
    ld_tile_a(sbase, OFF_AH, Ah + (size_t)m0*CC, CC, tid);
    ld_tile_a(sbase, OFF_AL, Al + (size_t)m0*CC, CC, tid);
    ld_tile_a(sbase, OFF_BH, Bh + (size_t)n0*CC, CC, tid);
    ld_tile_a(sbase, OFF_BL, Bl + (size_t)n0*CC, CC, tid);
    CP_COMMIT();
    for (int kc = 0; kc < 12; kc++){
        int st = (kc & 1) * STG;
        if (kc + 1 < 12){
            int s2 = ((kc+1) & 1) * STG;
            ld_tile_a(sbase, s2 + OFF_AH, Ah + (size_t)m0*CC + (kc+1)*64, CC, tid);
            ld_tile_a(sbase, s2 + OFF_AL, Al + (size_t)m0*CC + (kc+1)*64, CC, tid);
            ld_tile_a(sbase, s2 + OFF_BH, Bh + (size_t)n0*CC + (kc+1)*64, CC, tid);
            ld_tile_a(sbase, s2 + OFF_BL, Bl + (size_t)n0*CC + (kc+1)*64, CC, tid);
        }
        CP_COMMIT();
        CP_WAIT1();
        __syncthreads();
        mma_chunk3(c, sbase+st+OFF_AH, sbase+st+OFF_AL, sbase+st+OFF_BH, sbase+st+OFF_BL, wm0, wn0, lane);
        __syncthreads();
    }
    const int gid = lane >> 2, tg = lane & 3;
#pragma unroll
    for (int ma = 0; ma < 2; ma++)
#pragma unroll
    for (int na = 0; na < 8; na++){
        int row = m0 + wm0 + ma*16 + gid;
        int col = n0 + wn0 + na*8 + tg*2;
        *reinterpret_cast<uint32_t*>(Oh + (size_t)row*CC + col)
            = pack2h(c[ma][na][0], c[ma][na][1]);
        *reinterpret_cast<uint32_t*>(Oh + (size_t)(row+8)*CC + col)
            = pack2h(c[ma][na][2], c[ma][na][3]);
    }
}

// ============================ projection GEMM (3-term, per-head hi-only out)
__global__ __launch_bounds__(256) void k_gemm_proj(
    const h16* __restrict__ Ah, const h16* __restrict__ Al,
    const h16* __restrict__ Bh, const h16* __restrict__ Bl,
    h16* __restrict__ Oh)
{
    MMA_PRE();
    const int m0 = blockIdx.x*128, n0 = blockIdx.y*128;
    ld_tile_a(sbase, OFF_AH, Ah + (size_t)m0*CC, CC, tid);
    ld_tile_a(sbase, OFF_AL, Al + (size_t)m0*CC, CC, tid);
    ld_tile_a(sbase, OFF_BH, Bh + (size_t)n0*CC, CC, tid);
    ld_tile_a(sbase, OFF_BL, Bl + (size_t)n0*CC, CC, tid);
    CP_COMMIT();
    for (int kc = 0; kc < 12; kc++){
        int st = (kc & 1) * STG;
        if (kc + 1 < 12){
            int s2 = ((kc+1) & 1) * STG;
            ld_tile_a(sbase, s2 + OFF_AH, Ah + (size_t)m0*CC + (kc+1)*64, CC, tid);
            ld_tile_a(sbase, s2 + OFF_AL, Al + (size_t)m0*CC + (kc+1)*64, CC, tid);
            ld_tile_a(sbase, s2 + OFF_BH, Bh + (size_t)n0*CC + (kc+1)*64, CC, tid);
            ld_tile_a(sbase, s2 + OFF_BL, Bl + (size_t)n0*CC + (kc+1)*64, CC, tid);
        }
        CP_COMMIT();
        CP_WAIT1();
        __syncthreads();
        mma_chunk3(c, sbase+st+OFF_AH, sbase+st+OFF_AL, sbase+st+OFF_BH, sbase+st+OFF_BL, wm0, wn0, lane);
        __syncthreads();
    }
    const int gid = lane >> 2, tg = lane & 3;
#pragma unroll
    for (int ma = 0; ma < 2; ma++)
#pragma unroll
    for (int na = 0; na < 8; na++){
        int col = n0 + wn0 + na*8 + tg*2;
        int h = col >> 6, z = col & 63;
#pragma unroll
        for (int half = 0; half < 2; half++){
            int row = m0 + wm0 + ma*16 + gid + half*8;
            int b = row >> 10, tk = row & (NN-1);
            size_t adr = ((size_t)(b*HH + h)*NN + tk)*ZZ + z;
            *reinterpret_cast<uint32_t*>(Oh + adr)
                = pack2h(c[ma][na][half*2], c[ma][na][half*2+1]);
        }
    }
}

// ============================ flash stats (1-term S) ========================
#define ST_QH 0
#define ST_KH 16384
#define ST_MM 32768
#define ST_LL 33792
#define ST_BYTES 34816
__global__ __launch_bounds__(256) void k_statsf(){
    extern __shared__ char sm[];
    const int tid = threadIdx.x, wid = tid >> 5, lane = tid & 31;
    const uint32_t sbase = smem_u32(sm);
    const int bh = blockIdx.y, q0 = blockIdx.x*128;
    const int wq = (wid & 3)*32, wt = (wid >> 2)*64;
    const int gid = lane >> 2, tg = lane & 3;

    ld_tile(sm, ST_QH, g_Qh + ((size_t)bh*NN + q0)*ZZ, 128, ZZ, tid);

    float rm[2][2], rl[2][2];
#pragma unroll
    for (int i = 0; i < 2; i++)
#pragma unroll
    for (int j = 0; j < 2; j++){ rm[i][j] = -1e30f; rl[i][j] = 0.0f; }

    for (int t0 = 0; t0 < NN; t0 += 128){
        __syncthreads();
        ld_tile(sm, ST_KH, g_Kh + ((size_t)bh*NN + t0)*ZZ, 128, ZZ, tid);
        __syncthreads();

        float s[2][8][4];
#pragma unroll
        for (int i = 0; i < 2; i++)
#pragma unroll
        for (int j = 0; j < 8; j++)
#pragma unroll
        for (int k = 0; k < 4; k++) s[i][j][k] = 0.0f;

        mma_chunk1(s, sbase+ST_QH, sbase+ST_KH, wq, wt, lane);

#pragma unroll
        for (int ma = 0; ma < 2; ma++)
#pragma unroll
        for (int half = 0; half < 2; half++){
            float cm = -1e30f;
#pragma unroll
            for (int na = 0; na < 8; na++)
                cm = fmaxf(cm, fmaxf(s[ma][na][half*2], s[ma][na][half*2+1]));
            cm *= SCALE;
            cm = fmaxf(cm, __shfl_xor_sync(0xffffffffu, cm, 1));
            cm = fmaxf(cm, __shfl_xor_sync(0xffffffffu, cm, 2));
            float nm = fmaxf(rm[ma][half], cm);
            float ls = 0.0f;
#pragma unroll
            for (int na = 0; na < 8; na++)
                ls += fexp(s[ma][na][half*2]*SCALE - nm) + fexp(s[ma][na][half*2+1]*SCALE - nm);
            ls += __shfl_xor_sync(0xffffffffu, ls, 1);
            ls += __shfl_xor_sync(0xffffffffu, ls, 2);
            float d = fmaxf(rm[ma][half] - nm, -60.0f);
            rl[ma][half] = rl[ma][half]*fexp(d) + ls;
            rm[ma][half] = nm;
        }
    }
    float* smm = reinterpret_cast<float*>(sm + ST_MM);
    float* sml = reinterpret_cast<float*>(sm + ST_LL);
    __syncthreads();
    if (tg == 0){
#pragma unroll
        for (int ma = 0; ma < 2; ma++)
#pragma unroll
        for (int half = 0; half < 2; half++){
            int q = wq + ma*16 + gid + half*8;
            int wti = wid >> 2;
            smm[wti*128 + q] = rm[ma][half];
            sml[wti*128 + q] = rl[ma][half];
        }
    }
    __syncthreads();
    if (tid < 128){
        float m0 = smm[tid], m1 = smm[128 + tid];
        float l0 = sml[tid], l1 = sml[128 + tid];
        float m = fmaxf(m0, m1);
        float l = l0*fexp(fmaxf(m0 - m, -60.0f)) + l1*fexp(fmaxf(m1 - m, -60.0f));
        g_m [bh*NN + q0 + tid] = m;
        g_il[bh*NN + q0 + tid] = 1.0f / l;
    }
}

// ============================ fused attention pass ==========================
// phase1: S (1-term) -> P split-fp16 in smem; phase2: Ck/Cq += P^T [K|Q] (2-term)
#define AT_KTH 0
#define AT_QCH 16384
#define AT_KCH 24576
#define AT_PH  32768
#define AT_PL  49152
#define AT_MS  65536
#define AT_IL  65792
#define AT_BYTES 66048
__global__ __launch_bounds__(256) void k_attn_f(){
    extern __shared__ char sm[];
    const int tid = threadIdx.x, wid = tid >> 5, lane = tid & 31;
    const uint32_t sbase = smem_u32(sm);
    const int bh = blockIdx.y, t0 = blockIdx.x*128;
    const int gid = lane >> 2, tg = lane & 3;
    const int lr = lane & 15, lh = lane >> 4;
    const int srow_off = (lane & 7) + ((lane & 16) ? 8 : 0);
    const int scol8 = ((lane >> 3) & 1) * 8;
    float* ms = reinterpret_cast<float*>(sm + AT_MS);
    float* il = reinterpret_cast<float*>(sm + AT_IL);

    const int wt2 = (wid & 3)*32, wz = wid >> 2;
    float c[2][8][4];
#pragma unroll
    for (int i = 0; i < 2; i++)
#pragma unroll
    for (int j = 0; j < 8; j++)
#pragma unroll
    for (int k = 0; k < 4; k++) c[i][j][k] = 0.0f;

    ld_tile(sm, AT_KTH, g_Kh + ((size_t)bh*NN + t0)*ZZ, 128, ZZ, tid);

    const int wq1 = (wid & 1)*32, wt1 = (wid >> 1)*32;

    for (int q0c = 0; q0c < NN; q0c += 64){
        __syncthreads();
        ld_tile(sm, AT_QCH, g_Qh + ((size_t)bh*NN + q0c)*ZZ, 64, ZZ, tid);
        ld_tile(sm, AT_KCH, g_Kh + ((size_t)bh*NN + q0c)*ZZ, 64, ZZ, tid);
        if (tid < 64)       ms[tid]      = g_m [bh*NN + q0c + tid];
        else if (tid < 128) il[tid - 64] = g_il[bh*NN + q0c + tid - 64];
        __syncthreads();

        // ---- phase 1: S chunk (1-term) -> P smem (split fp16) ----
        {
            float s1[2][4][4];
#pragma unroll
            for (int i = 0; i < 2; i++)
#pragma unroll
            for (int j = 0; j < 4; j++)
#pragma unroll
            for (int k = 0; k < 4; k++) s1[i][j][k] = 0.0f;
#pragma unroll
            for (int ks = 0; ks < 4; ks++){
                uint32_t ah[2][4];
#pragma unroll
                for (int ma = 0; ma < 2; ma++){
                    uint32_t off = SW((wq1 + ma*16 + lr)*128 + (ks*2 + lh)*16);
                    ldsm_x4(ah[ma][0], ah[ma][1], ah[ma][2], ah[ma][3], sbase + AT_QCH + off);
                }
                uint32_t bh4[2][4];
#pragma unroll
                for (int np = 0; np < 2; np++){
                    uint32_t off = SW((wt1 + np*16 + lr)*128 + (ks*2 + lh)*16);
                    ldsm_x4(bh4[np][0], bh4[np][1], bh4[np][2], bh4[np][3], sbase + AT_KTH + off);
                }
#pragma unroll
                for (int np = 0; np < 2; np++)
#pragma unroll
                for (int ma = 0; ma < 2; ma++){
                    mma16816(s1[ma][np*2],   ah[ma], bh4[np][0], bh4[np][2]);
                    mma16816(s1[ma][np*2+1], ah[ma], bh4[np][1], bh4[np][3]);
                }
            }
#pragma unroll
            for (int ma = 0; ma < 2; ma++)
#pragma unroll
            for (int na = 0; na < 4; na++)
#pragma unroll
            for (int half = 0; half < 2; half++){
                int qloc = wq1 + ma*16 + gid + half*8;
                float M = ms[qloc], I = il[qloc];
                int tloc = wt1 + na*8 + tg*2;
                float p0 = fexp(s1[ma][na][half*2]  *SCALE - M)*I;
                float p1 = fexp(s1[ma][na][half*2+1]*SCALE - M)*I;
                uint32_t hi, lo; split_pair(p0, p1, hi, lo);
                uint32_t off = (uint32_t)(tloc >> 6)*8192 + SW(qloc*128 + (tloc & 63)*2);
                *reinterpret_cast<uint32_t*>(sm + AT_PH + off) = hi;
                *reinterpret_cast<uint32_t*>(sm + AT_PL + off) = lo;
            }
        }
        __syncthreads();

        // ---- phase 2: Ck/Cq += P^T [K|Q]  (2-term A-split) ----
        {
            const int bsh = wz ? AT_QCH : AT_KCH;
#pragma unroll
            for (int ks = 0; ks < 4; ks++){
                int qk = ks*16;
                uint32_t ah[2][4], al[2][4];
#pragma unroll
                for (int ma = 0; ma < 2; ma++){
                    int tcol = wt2 + ma*16;
                    uint32_t off = (uint32_t)(tcol >> 6)*8192
                                 + SW((qk + srow_off)*128 + ((tcol & 63) + scol8)*2);
                    ldsm_x4_t(ah[ma][0], ah[ma][1], ah[ma][2], ah[ma][3], sbase + AT_PH + off);
                    ldsm_x4_t(al[ma][0], al[ma][1], al[ma][2], al[ma][3], sbase + AT_PL + off);
                }
                uint32_t bh4[4][4];
#pragma unroll
                for (int zn = 0; zn < 4; zn++){
                    uint32_t off = SW((qk + srow_off)*128 + (zn*16 + scol8)*2);
                    ldsm_x4_t(bh4[zn][0], bh4[zn][1], bh4[zn][2], bh4[zn][3], sbase + bsh + off);
                }
#pragma unroll
                for (int zn = 0; zn < 4; zn++)
#pragma unroll
                for (int ma = 0; ma < 2; ma++){
                    mma16816(c[ma][zn*2],   ah[ma], bh4[zn][0], bh4[zn][2]);
                    mma16816(c[ma][zn*2+1], ah[ma], bh4[zn][1], bh4[zn][3]);
                }
#pragma unroll
                for (int zn = 0; zn < 4; zn++)
#pragma unroll
                for (int ma = 0; ma < 2; ma++){
                    mma16816(c[ma][zn*2],   al[ma], bh4[zn][0], bh4[zn][2]);
                    mma16816(c[ma][zn*2+1], al[ma], bh4[zn][1], bh4[zn][3]);
                }
            }
        }
    }
    const int b = bh / HH, h = bh - b*HH;
    h16* Oh = wz ? g_Cqh : g_Ckh;
    h16* Ol = wz ? g_Cql : g_Ckl;
#pragma unroll
    for (int ma = 0; ma < 2; ma++)
#pragma unroll
    for (int na = 0; na < 8; na++){
        int z = na*8 + tg*2;
#pragma unroll
        for (int half = 0; half < 2; half++){
            int t = t0 + wt2 + ma*16 + gid + half*8;
            size_t adr = ((size_t)b*NN + t)*CC + h*ZZ + z;
            uint32_t hi, lo;
            split_pair(c[ma][na][half*2], c[ma][na][half*2+1], hi, lo);
            *reinterpret_cast<uint32_t*>(Oh + adr) = hi;
            *reinterpret_cast<uint32_t*>(Ol + adr) = lo;
        }
    }
}

// ============================ out = Ck U1^T + Cq U2^T + bp (2-term) =========
__global__ __launch_bounds__(256) void k_gemm_out(const float* __restrict__ bp,
                                                  float* __restrict__ out){
    MMA_PRE();
    const int m0 = blockIdx.x*128, n0 = blockIdx.y*128;
    ld_tile_a(sbase, O2_AH, g_Ckh + (size_t)m0*CC, CC, tid);
    ld_tile_a(sbase, O2_AL, g_Ckl + (size_t)m0*CC, CC, tid);
    ld_tile_a(sbase, O2_BH, g_U1h + (size_t)n0*CC, CC, tid);
    CP_COMMIT();
    for (int it = 0; it < 24; it++){
        int st = (it & 1) * STG2;
        if (it + 1 < 24){
            int i2 = it + 1;
            int pr = i2 & 1, kc = i2 >> 1;
            const h16* Ah = pr ? g_Cqh : g_Ckh;
            const h16* Al = pr ? g_Cql : g_Ckl;
            const h16* Bh = pr ? g_U2h : g_U1h;
            int s2 = (i2 & 1) * STG2;
            ld_tile_a(sbase, s2 + O2_AH, Ah + (size_t)m0*CC + kc*64, CC, tid);
            ld_tile_a(sbase, s2 + O2_AL, Al + (size_t)m0*CC + kc*64, CC, tid);
            ld_tile_a(sbase, s2 + O2_BH, Bh + (size_t)n0*CC + kc*64, CC, tid);
        }
        CP_COMMIT();
        CP_WAIT1();
        __syncthreads();
        mma_chunk2(c, sbase+st+O2_AH, sbase+st+O2_AL, sbase+st+O2_BH, wm0, wn0, lane);
        __syncthreads();
    }
    const int gid = lane >> 2, tg = lane & 3;
#pragma unroll
    for (int ma = 0; ma < 2; ma++)
#pragma unroll
    for (int na = 0; na < 8; na++){
        int row = m0 + wm0 + ma*16 + gid;
        int col = n0 + wn0 + na*8 + tg*2;
        float b0 = bp[col], b1 = bp[col+1];
        *reinterpret_cast<float2*>(out + (size_t)row*CC + col)
            = make_float2(c[ma][na][0] + b0, c[ma][na][1] + b1);
        *reinterpret_cast<float2*>(out + (size_t)(row+8)*CC + col)
            = make_float2(c[ma][na][2] + b0, c[ma][na][3] + b1);
    }
}

// ============================ host ==========================================
extern "C" void kernel_launch(void* const* d_in, const int* in_sizes, int n_in,
                              void* d_out, int out_size)
{
    (void)in_sizes; (void)n_in; (void)out_size;
    const float* x  = (const float*)d_in[0];
    const float* Wq = (const float*)d_in[1];
    const float* Wk = (const float*)d_in[2];
    const float* Wp = (const float*)d_in[3];
    const float* bp = (const float*)d_in[4];
    float* out = (float*)d_out;

    h16 *xh, *xl, *wqh, *wql, *wkh, *wkl, *wph, *wpl;
    cudaGetSymbolAddress((void**)&xh,  g_xh);  cudaGetSymbolAddress((void**)&xl,  g_xl);
    cudaGetSymbolAddress((void**)&wqh, g_Wqh); cudaGetSymbolAddress((void**)&wql, g_Wql);
    cudaGetSymbolAddress((void**)&wkh, g_Wkh); cudaGetSymbolAddress((void**)&wkl, g_Wkl);
    cudaGetSymbolAddress((void**)&wph, g_Wph); cudaGetSymbolAddress((void**)&wpl, g_Wpl);
    h16 *u1h, *u2h, *qh, *kh;
    cudaGetSymbolAddress((void**)&u1h, g_U1h); cudaGetSymbolAddress((void**)&u2h, g_U2h);
    cudaGetSymbolAddress((void**)&qh,  g_Qh);  cudaGetSymbolAddress((void**)&kh,  g_Kh);

    cudaFuncSetAttribute(k_gemm_w,    cudaFuncAttributeMaxDynamicSharedMemorySize, SMEM_BYTES);
    cudaFuncSetAttribute(k_gemm_proj, cudaFuncAttributeMaxDynamicSharedMemorySize, SMEM_BYTES);
    cudaFuncSetAttribute(k_gemm_out,  cudaFuncAttributeMaxDynamicSharedMemorySize, SMEM2);
    cudaFuncSetAttribute(k_statsf,    cudaFuncAttributeMaxDynamicSharedMemorySize, ST_BYTES);
    cudaFuncSetAttribute(k_attn_f,    cudaFuncAttributeMaxDynamicSharedMemorySize, AT_BYTES);

    k_conv<<<256, 256>>>(x,  xh,  xl,  BB*NN*CC/4);
    k_conv<<<64,  256>>>(Wq, wqh, wql, CC*CC/4);
    k_conv<<<64,  256>>>(Wk, wkh, wkl, CC*CC/4);
    k_conv<<<64,  256>>>(Wp, wph, wpl, CC*CC/4);

    k_gemm_w<<<dim3(6,6), 256, SMEM_BYTES>>>(wph, wpl, wqh, wql, u1h);
    k_gemm_w<<<dim3(6,6), 256, SMEM_BYTES>>>(wph, wpl, wkh, wkl, u2h);

    k_gemm_proj<<<dim3(64,6), 256, SMEM_BYTES>>>(xh, xl, wqh, wql, qh);
    k_gemm_proj<<<dim3(64,6), 256, SMEM_BYTES>>>(xh, xl, wkh, wkl, kh);

    k_statsf<<<dim3(8, BH), 256, ST_BYTES>>>();
    k_attn_f<<<dim3(8, BH), 256, AT_BYTES>>>();

    k_gemm_out<<<dim3(64, 6), 256, SMEM2>>>(bp, out);
}

// round 9
// speedup vs baseline: 3.6980x; 1.1373x over previous
#include <cuda_runtime.h>
#include <cuda_fp16.h>
#include <cstdint>
#include <math.h>

#define BB 8
#define NN 1024
#define CC 768
#define HH 12
#define ZZ 64
#define BH (BB*HH)
#define SCALE 0.125f
typedef __half h16;

// ---------------- scratch ----------------
__device__ h16 g_xh[BB*NN*CC];
__device__ h16 g_Wqh[CC*CC], g_Wql[CC*CC], g_Wkh[CC*CC], g_Wkl[CC*CC];
__device__ h16 g_Wph[CC*CC], g_Wpl[CC*CC];
__device__ h16 g_U1h[CC*CC], g_U2h[CC*CC];
__device__ h16 g_Qh[BH*NN*ZZ], g_Kh[BH*NN*ZZ];
__device__ float g_m[BH*NN], g_il[BH*NN];
__device__ h16 g_Ckh[BB*NN*CC], g_Ckl[BB*NN*CC], g_Cqh[BB*NN*CC], g_Cql[BB*NN*CC];

// ---------------- helpers ----------------
#define SW(o) ((o) ^ (((o)>>3)&0x70))
// 3-term weight kernel: 4 tiles/stage
#define OFF_AH 0
#define OFF_AL 16384
#define OFF_BH 32768
#define OFF_BL 49152
#define STG 65536
#define SMEM_BYTES 131072
// 1-term proj kernel: 2 tiles/stage
#define P1_A 0
#define P1_B 16384
#define STGP 32768
#define SMEMP 65536
// 2-term out kernel: 3 tiles/stage
#define O2_AH 0
#define O2_AL 16384
#define O2_BH 32768
#define STG2 49152
#define SMEM2 98304

__device__ __forceinline__ uint32_t smem_u32(const void* p){
    uint32_t a;
    asm("{ .reg .u64 t; cvta.to.shared.u64 t, %1; cvt.u32.u64 %0, t; }" : "=r"(a) : "l"(p));
    return a;
}
__device__ __forceinline__ void ldsm_x4(uint32_t& r0, uint32_t& r1, uint32_t& r2, uint32_t& r3, uint32_t addr){
    asm volatile("ldmatrix.sync.aligned.m8n8.x4.shared.b16 {%0,%1,%2,%3}, [%4];"
        : "=r"(r0), "=r"(r1), "=r"(r2), "=r"(r3) : "r"(addr));
}
__device__ __forceinline__ void ldsm_x4_t(uint32_t& r0, uint32_t& r1, uint32_t& r2, uint32_t& r3, uint32_t addr){
    asm volatile("ldmatrix.sync.aligned.m8n8.x4.trans.shared.b16 {%0,%1,%2,%3}, [%4];"
        : "=r"(r0), "=r"(r1), "=r"(r2), "=r"(r3) : "r"(addr));
}
__device__ __forceinline__ void mma16816(float c[4], const uint32_t a[4], uint32_t b0, uint32_t b1){
    asm volatile("mma.sync.aligned.m16n8k16.row.col.f32.f16.f16.f32 "
        "{%0,%1,%2,%3}, {%4,%5,%6,%7}, {%8,%9}, {%0,%1,%2,%3};"
        : "+f"(c[0]), "+f"(c[1]), "+f"(c[2]), "+f"(c[3])
        : "r"(a[0]), "r"(a[1]), "r"(a[2]), "r"(a[3]), "r"(b0), "r"(b1));
}
__device__ __forceinline__ void cp16(uint32_t saddr, const void* g){
    asm volatile("cp.async.cg.shared.global [%0], [%1], 16;" :: "r"(saddr), "l"(g));
}
#define CP_COMMIT() asm volatile("cp.async.commit_group;" ::: "memory")
#define CP_WAIT1()  asm volatile("cp.async.wait_group 1;" ::: "memory")

__device__ __forceinline__ float fexp(float x){
    float y = x * 1.4426950408889634f;
    float n = rintf(y);
    float f = y - n;
    float p = 1.3333558146428443e-3f;
    p = fmaf(p, f, 9.6181291076284772e-3f);
    p = fmaf(p, f, 5.5504108664821580e-2f);
    p = fmaf(p, f, 2.4022650695910072e-1f);
    p = fmaf(p, f, 6.9314718055994531e-1f);
    p = fmaf(p, f, 1.0f);
    return __int_as_float(__float_as_int(p) + (((int)n) << 23));
}
__device__ __forceinline__ void split2(float v, h16& hi, h16& lo){
    hi = __float2half(v);
    lo = __float2half(v - __half2float(hi));
}
__device__ __forceinline__ void split_pair(float a, float b, uint32_t& hi, uint32_t& lo){
    h16 ah, al, bh_, bl;
    split2(a, ah, al); split2(b, bh_, bl);
    hi = (uint32_t)__half_as_ushort(ah) | ((uint32_t)__half_as_ushort(bh_) << 16);
    lo = (uint32_t)__half_as_ushort(al) | ((uint32_t)__half_as_ushort(bl) << 16);
}
__device__ __forceinline__ uint32_t pack2h(float a, float b){
    return (uint32_t)__half_as_ushort(__float2half(a))
         | ((uint32_t)__half_as_ushort(__float2half(b)) << 16);
}

// sync tile loader: rows x 64 h16 (128B rows), swizzled
__device__ __forceinline__ void ld_tile(char* sm, int off, const h16* __restrict__ g,
                                        int rows, int rstride, int tid){
    for (int i = tid; i < rows*8; i += 256){
        int r = i >> 3, c = i & 7;
        uint4 v = *reinterpret_cast<const uint4*>(g + (size_t)r*rstride + c*8);
        *reinterpret_cast<uint4*>(sm + off + SW(r*128 + c*16)) = v;
    }
}
// async tile loader (128 rows x 64 h16)
__device__ __forceinline__ void ld_tile_a(uint32_t sbase, int off, const h16* __restrict__ g,
                                          int rstride, int tid){
    for (int i = tid; i < 128*8; i += 256){
        int r = i >> 3, c = i & 7;
        cp16(sbase + off + SW(r*128 + c*16), g + (size_t)r*rstride + c*8);
    }
}

// 3-term block MMA (A split x B split): AhBh + AlBh + AhBl
__device__ __forceinline__ void mma_chunk3(float c[2][8][4],
        uint32_t aH, uint32_t aL, uint32_t bH, uint32_t bL, int wm0, int wn0, int lane){
    const int lr = lane & 15, lh = lane >> 4;
#pragma unroll
    for (int ks = 0; ks < 4; ks++){
        uint32_t ah[2][4], al[2][4];
#pragma unroll
        for (int ma = 0; ma < 2; ma++){
            uint32_t off = SW((wm0 + ma*16 + lr)*128 + (ks*2 + lh)*16);
            ldsm_x4(ah[ma][0], ah[ma][1], ah[ma][2], ah[ma][3], aH + off);
            ldsm_x4(al[ma][0], al[ma][1], al[ma][2], al[ma][3], aL + off);
        }
        uint32_t bh[4][4], bl[4][4];
#pragma unroll
        for (int np = 0; np < 4; np++){
            uint32_t off = SW((wn0 + np*16 + lr)*128 + (ks*2 + lh)*16);
            ldsm_x4(bh[np][0], bh[np][1], bh[np][2], bh[np][3], bH + off);
            ldsm_x4(bl[np][0], bl[np][1], bl[np][2], bl[np][3], bL + off);
        }
#pragma unroll
        for (int np = 0; np < 4; np++)
#pragma unroll
        for (int ma = 0; ma < 2; ma++){
            mma16816(c[ma][np*2],   ah[ma], bh[np][0], bh[np][2]);
            mma16816(c[ma][np*2+1], ah[ma], bh[np][1], bh[np][3]);
        }
#pragma unroll
        for (int np = 0; np < 4; np++)
#pragma unroll
        for (int ma = 0; ma < 2; ma++){
            mma16816(c[ma][np*2],   al[ma], bh[np][0], bh[np][2]);
            mma16816(c[ma][np*2+1], al[ma], bh[np][1], bh[np][3]);
        }
#pragma unroll
        for (int np = 0; np < 4; np++)
#pragma unroll
        for (int ma = 0; ma < 2; ma++){
            mma16816(c[ma][np*2],   ah[ma], bl[np][0], bl[np][2]);
            mma16816(c[ma][np*2+1], ah[ma], bl[np][1], bl[np][3]);
        }
    }
}

// 2-term block MMA (A split x B single): AhB + AlB
__device__ __forceinline__ void mma_chunk2(float c[2][8][4],
        uint32_t aH, uint32_t aL, uint32_t bH, int wm0, int wn0, int lane){
    const int lr = lane & 15, lh = lane >> 4;
#pragma unroll
    for (int ks = 0; ks < 4; ks++){
        uint32_t ah[2][4], al[2][4];
#pragma unroll
        for (int ma = 0; ma < 2; ma++){
            uint32_t off = SW((wm0 + ma*16 + lr)*128 + (ks*2 + lh)*16);
            ldsm_x4(ah[ma][0], ah[ma][1], ah[ma][2], ah[ma][3], aH + off);
            ldsm_x4(al[ma][0], al[ma][1], al[ma][2], al[ma][3], aL + off);
        }
        uint32_t bh[4][4];
#pragma unroll
        for (int np = 0; np < 4; np++){
            uint32_t off = SW((wn0 + np*16 + lr)*128 + (ks*2 + lh)*16);
            ldsm_x4(bh[np][0], bh[np][1], bh[np][2], bh[np][3], bH + off);
        }
#pragma unroll
        for (int np = 0; np < 4; np++)
#pragma unroll
        for (int ma = 0; ma < 2; ma++){
            mma16816(c[ma][np*2],   ah[ma], bh[np][0], bh[np][2]);
            mma16816(c[ma][np*2+1], ah[ma], bh[np][1], bh[np][3]);
        }
#pragma unroll
        for (int np = 0; np < 4; np++)
#pragma unroll
        for (int ma = 0; ma < 2; ma++){
            mma16816(c[ma][np*2],   al[ma], bh[np][0], bh[np][2]);
            mma16816(c[ma][np*2+1], al[ma], bh[np][1], bh[np][3]);
        }
    }
}

// 1-term block MMA (both single)
__device__ __forceinline__ void mma_chunk1(float c[2][8][4],
        uint32_t aH, uint32_t bH, int wm0, int wn0, int lane){
    const int lr = lane & 15, lh = lane >> 4;
#pragma unroll
    for (int ks = 0; ks < 4; ks++){
        uint32_t ah[2][4];
#pragma unroll
        for (int ma = 0; ma < 2; ma++){
            uint32_t off = SW((wm0 + ma*16 + lr)*128 + (ks*2 + lh)*16);
            ldsm_x4(ah[ma][0], ah[ma][1], ah[ma][2], ah[ma][3], aH + off);
        }
        uint32_t bh[4][4];
#pragma unroll
        for (int np = 0; np < 4; np++){
            uint32_t off = SW((wn0 + np*16 + lr)*128 + (ks*2 + lh)*16);
            ldsm_x4(bh[np][0], bh[np][1], bh[np][2], bh[np][3], bH + off);
        }
#pragma unroll
        for (int np = 0; np < 4; np++)
#pragma unroll
        for (int ma = 0; ma < 2; ma++){
            mma16816(c[ma][np*2],   ah[ma], bh[np][0], bh[np][2]);
            mma16816(c[ma][np*2+1], ah[ma], bh[np][1], bh[np][3]);
        }
    }
}

#define MMA_PRE() \
    extern __shared__ char sm[]; \
    const int tid = threadIdx.x, wid = tid >> 5, lane = tid & 31; \
    const uint32_t sbase = smem_u32(sm); \
    const int wm0 = (wid & 3) * 32, wn0 = (wid >> 2) * 64; \
    float c[2][8][4]; \
    _Pragma("unroll") for (int i = 0; i < 2; i++) \
    _Pragma("unroll") for (int j = 0; j < 8; j++) \
    _Pragma("unroll") for (int k = 0; k < 4; k++) c[i][j][k] = 0.0f;

// ============================ converters ====================================
__global__ __launch_bounds__(256) void k_conv(const float* __restrict__ in,
                                              h16* __restrict__ oh, h16* __restrict__ ol, int n4){
    for (int i = blockIdx.x*blockDim.x + threadIdx.x; i < n4; i += gridDim.x*blockDim.x){
        float4 v = reinterpret_cast<const float4*>(in)[i];
        uint32_t h0, l0, h1, l1;
        split_pair(v.x, v.y, h0, l0);
        split_pair(v.z, v.w, h1, l1);
        reinterpret_cast<uint2*>(oh)[i] = make_uint2(h0, h1);
        reinterpret_cast<uint2*>(ol)[i] = make_uint2(l0, l1);
    }
}
__global__ __launch_bounds__(256) void k_conv1(const float* __restrict__ in,
                                               h16* __restrict__ oh, int n4){
    for (int i = blockIdx.x*blockDim.x + threadIdx.x; i < n4; i += gridDim.x*blockDim.x){
        float4 v = reinterpret_cast<const float4*>(in)[i];
        reinterpret_cast<uint2*>(oh)[i] = make_uint2(pack2h(v.x, v.y), pack2h(v.z, v.w));
    }
}

// ============================ weight GEMM: U = Wp * W^T (3-term) ============
__global__ __launch_bounds__(256) void k_gemm_w(
    const h16* __restrict__ Ah, const h16* __restrict__ Al,
    const h16* __restrict__ Bh, const h16* __restrict__ Bl,
    h16* __restrict__ Oh)
{
    MMA_PRE();
    const int m0 = blockIdx.x*128, n0 = blockIdx.y*128;
    ld_tile_a(sbase, OFF_AH, Ah + (size_t)m0*CC, CC, tid);
    ld_tile_a(sbase, OFF_AL, Al + (size_t)m0*CC, CC, tid);
    ld_tile_a(sbase, OFF_BH, Bh + (size_t)n0*CC, CC, tid);
    ld_tile_a(sbase, OFF_BL, Bl + (size_t)n0*CC, CC, tid);
    CP_COMMIT();
    for (int kc = 0; kc < 12; kc++){
        int st = (kc & 1) * STG;
        if (kc + 1 < 12){
            int s2 = ((kc+1) & 1) * STG;
            ld_tile_a(sbase, s2 + OFF_AH, Ah + (size_t)m0*CC + (kc+1)*64, CC, tid);
            ld_tile_a(sbase, s2 + OFF_AL, Al + (size_t)m0*CC + (kc+1)*64, CC, tid);
            ld_tile_a(sbase, s2 + OFF_BH, Bh + (size_t)n0*CC + (kc+1)*64, CC, tid);
            ld_tile_a(sbase, s2 + OFF_BL, Bl + (size_t)n0*CC + (kc+1)*64, CC, tid);
        }
        CP_COMMIT();
        CP_WAIT1();
        __syncthreads();
        mma_chunk3(c, sbase+st+OFF_AH, sbase+st+OFF_AL, sbase+st+OFF_BH, sbase+st+OFF_BL, wm0, wn0, lane);
        __syncthreads();
    }
    const int gid = lane >> 2, tg = lane & 3;
#pragma unroll
    for (int ma = 0; ma < 2; ma++)
#pragma unroll
    for (int na = 0; na < 8; na++){
        int row = m0 + wm0 + ma*16 + gid;
        int col = n0 + wn0 + na*8 + tg*2;
        *reinterpret_cast<uint32_t*>(Oh + (size_t)row*CC + col)
            = pack2h(c[ma][na][0], c[ma][na][1]);
        *reinterpret_cast<uint32_t*>(Oh + (size_t)(row+8)*CC + col)
            = pack2h(c[ma][na][2], c[ma][na][3]);
    }
}

// ============================ projection GEMM (1-term, per-head out) ========
__global__ __launch_bounds__(256) void k_gemm_proj(
    const h16* __restrict__ A, const h16* __restrict__ B,
    h16* __restrict__ Oh)
{
    MMA_PRE();
    const int m0 = blockIdx.x*128, n0 = blockIdx.y*128;
    ld_tile_a(sbase, P1_A, A + (size_t)m0*CC, CC, tid);
    ld_tile_a(sbase, P1_B, B + (size_t)n0*CC, CC, tid);
    CP_COMMIT();
    for (int kc = 0; kc < 12; kc++){
        int st = (kc & 1) * STGP;
        if (kc + 1 < 12){
            int s2 = ((kc+1) & 1) * STGP;
            ld_tile_a(sbase, s2 + P1_A, A + (size_t)m0*CC + (kc+1)*64, CC, tid);
            ld_tile_a(sbase, s2 + P1_B, B + (size_t)n0*CC + (kc+1)*64, CC, tid);
        }
        CP_COMMIT();
        CP_WAIT1();
        __syncthreads();
        mma_chunk1(c, sbase+st+P1_A, sbase+st+P1_B, wm0, wn0, lane);
        __syncthreads();
    }
    const int gid = lane >> 2, tg = lane & 3;
#pragma unroll
    for (int ma = 0; ma < 2; ma++)
#pragma unroll
    for (int na = 0; na < 8; na++){
        int col = n0 + wn0 + na*8 + tg*2;
        int h = col >> 6, z = col & 63;
#pragma unroll
        for (int half = 0; half < 2; half++){
            int row = m0 + wm0 + ma*16 + gid + half*8;
            int b = row >> 10, tk = row & (NN-1);
            size_t adr = ((size_t)(b*HH + h)*NN + tk)*ZZ + z;
            *reinterpret_cast<uint32_t*>(Oh + adr)
                = pack2h(c[ma][na][half*2], c[ma][na][half*2+1]);
        }
    }
}

// ============================ flash stats (1-term S) ========================
#define ST_QH 0
#define ST_KH 16384
#define ST_MM 32768
#define ST_LL 33792
#define ST_BYTES 34816
__global__ __launch_bounds__(256) void k_statsf(){
    extern __shared__ char sm[];
    const int tid = threadIdx.x, wid = tid >> 5, lane = tid & 31;
    const uint32_t sbase = smem_u32(sm);
    const int bh = blockIdx.y, q0 = blockIdx.x*128;
    const int wq = (wid & 3)*32, wt = (wid >> 2)*64;
    const int gid = lane >> 2, tg = lane & 3;

    ld_tile(sm, ST_QH, g_Qh + ((size_t)bh*NN + q0)*ZZ, 128, ZZ, tid);

    float rm[2][2], rl[2][2];
#pragma unroll
    for (int i = 0; i < 2; i++)
#pragma unroll
    for (int j = 0; j < 2; j++){ rm[i][j] = -1e30f; rl[i][j] = 0.0f; }

    for (int t0 = 0; t0 < NN; t0 += 128){
        __syncthreads();
        ld_tile(sm, ST_KH, g_Kh + ((size_t)bh*NN + t0)*ZZ, 128, ZZ, tid);
        __syncthreads();

        float s[2][8][4];
#pragma unroll
        for (int i = 0; i < 2; i++)
#pragma unroll
        for (int j = 0; j < 8; j++)
#pragma unroll
        for (int k = 0; k < 4; k++) s[i][j][k] = 0.0f;

        mma_chunk1(s, sbase+ST_QH, sbase+ST_KH, wq, wt, lane);

#pragma unroll
        for (int ma = 0; ma < 2; ma++)
#pragma unroll
        for (int half = 0; half < 2; half++){
            float cm = -1e30f;
#pragma unroll
            for (int na = 0; na < 8; na++)
                cm = fmaxf(cm, fmaxf(s[ma][na][half*2], s[ma][na][half*2+1]));
            cm *= SCALE;
            cm = fmaxf(cm, __shfl_xor_sync(0xffffffffu, cm, 1));
            cm = fmaxf(cm, __shfl_xor_sync(0xffffffffu, cm, 2));
            float nm = fmaxf(rm[ma][half], cm);
            float ls = 0.0f;
#pragma unroll
            for (int na = 0; na < 8; na++)
                ls += fexp(s[ma][na][half*2]*SCALE - nm) + fexp(s[ma][na][half*2+1]*SCALE - nm);
            ls += __shfl_xor_sync(0xffffffffu, ls, 1);
            ls += __shfl_xor_sync(0xffffffffu, ls, 2);
            float d = fmaxf(rm[ma][half] - nm, -60.0f);
            rl[ma][half] = rl[ma][half]*fexp(d) + ls;
            rm[ma][half] = nm;
        }
    }
    float* smm = reinterpret_cast<float*>(sm + ST_MM);
    float* sml = reinterpret_cast<float*>(sm + ST_LL);
    __syncthreads();
    if (tg == 0){
#pragma unroll
        for (int ma = 0; ma < 2; ma++)
#pragma unroll
        for (int half = 0; half < 2; half++){
            int q = wq + ma*16 + gid + half*8;
            int wti = wid >> 2;
            smm[wti*128 + q] = rm[ma][half];
            sml[wti*128 + q] = rl[ma][half];
        }
    }
    __syncthreads();
    if (tid < 128){
        float m0 = smm[tid], m1 = smm[128 + tid];
        float l0 = sml[tid], l1 = sml[128 + tid];
        float m = fmaxf(m0, m1);
        float l = l0*fexp(fmaxf(m0 - m, -60.0f)) + l1*fexp(fmaxf(m1 - m, -60.0f));
        g_m [bh*NN + q0 + tid] = m;
        g_il[bh*NN + q0 + tid] = 1.0f / l;
    }
}

// ============================ fused attention pass ==========================
#define AT_KTH 0
#define AT_QCH 16384
#define AT_KCH 24576
#define AT_PH  32768
#define AT_PL  49152
#define AT_MS  65536
#define AT_IL  65792
#define AT_BYTES 66048
__global__ __launch_bounds__(256) void k_attn_f(){
    extern __shared__ char sm[];
    const int tid = threadIdx.x, wid = tid >> 5, lane = tid & 31;
    const uint32_t sbase = smem_u32(sm);
    const int bh = blockIdx.y, t0 = blockIdx.x*128;
    const int gid = lane >> 2, tg = lane & 3;
    const int lr = lane & 15, lh = lane >> 4;
    const int srow_off = (lane & 7) + ((lane & 16) ? 8 : 0);
    const int scol8 = ((lane >> 3) & 1) * 8;
    float* ms = reinterpret_cast<float*>(sm + AT_MS);
    float* il = reinterpret_cast<float*>(sm + AT_IL);

    const int wt2 = (wid & 3)*32, wz = wid >> 2;
    float c[2][8][4];
#pragma unroll
    for (int i = 0; i < 2; i++)
#pragma unroll
    for (int j = 0; j < 8; j++)
#pragma unroll
    for (int k = 0; k < 4; k++) c[i][j][k] = 0.0f;

    ld_tile(sm, AT_KTH, g_Kh + ((size_t)bh*NN + t0)*ZZ, 128, ZZ, tid);

    const int wq1 = (wid & 1)*32, wt1 = (wid >> 1)*32;

    for (int q0c = 0; q0c < NN; q0c += 64){
        __syncthreads();
        ld_tile(sm, AT_QCH, g_Qh + ((size_t)bh*NN + q0c)*ZZ, 64, ZZ, tid);
        ld_tile(sm, AT_KCH, g_Kh + ((size_t)bh*NN + q0c)*ZZ, 64, ZZ, tid);
        if (tid < 64)       ms[tid]      = g_m [bh*NN + q0c + tid];
        else if (tid < 128) il[tid - 64] = g_il[bh*NN + q0c + tid - 64];
        __syncthreads();

        // ---- phase 1: S chunk (1-term) -> P smem (split fp16) ----
        {
            float s1[2][4][4];
#pragma unroll
            for (int i = 0; i < 2; i++)
#pragma unroll
            for (int j = 0; j < 4; j++)
#pragma unroll
            for (int k = 0; k < 4; k++) s1[i][j][k] = 0.0f;
#pragma unroll
            for (int ks = 0; ks < 4; ks++){
                uint32_t ah[2][4];
#pragma unroll
                for (int ma = 0; ma < 2; ma++){
                    uint32_t off = SW((wq1 + ma*16 + lr)*128 + (ks*2 + lh)*16);
                    ldsm_x4(ah[ma][0], ah[ma][1], ah[ma][2], ah[ma][3], sbase + AT_QCH + off);
                }
                uint32_t bh4[2][4];
#pragma unroll
                for (int np = 0; np < 2; np++){
                    uint32_t off = SW((wt1 + np*16 + lr)*128 + (ks*2 + lh)*16);
                    ldsm_x4(bh4[np][0], bh4[np][1], bh4[np][2], bh4[np][3], sbase + AT_KTH + off);
                }
#pragma unroll
                for (int np = 0; np < 2; np++)
#pragma unroll
                for (int ma = 0; ma < 2; ma++){
                    mma16816(s1[ma][np*2],   ah[ma], bh4[np][0], bh4[np][2]);
                    mma16816(s1[ma][np*2+1], ah[ma], bh4[np][1], bh4[np][3]);
                }
            }
#pragma unroll
            for (int ma = 0; ma < 2; ma++)
#pragma unroll
            for (int na = 0; na < 4; na++)
#pragma unroll
            for (int half = 0; half < 2; half++){
                int qloc = wq1 + ma*16 + gid + half*8;
                float M = ms[qloc], I = il[qloc];
                int tloc = wt1 + na*8 + tg*2;
                float p0 = fexp(s1[ma][na][half*2]  *SCALE - M)*I;
                float p1 = fexp(s1[ma][na][half*2+1]*SCALE - M)*I;
                uint32_t hi, lo; split_pair(p0, p1, hi, lo);
                uint32_t off = (uint32_t)(tloc >> 6)*8192 + SW(qloc*128 + (tloc & 63)*2);
                *reinterpret_cast<uint32_t*>(sm + AT_PH + off) = hi;
                *reinterpret_cast<uint32_t*>(sm + AT_PL + off) = lo;
            }
        }
        __syncthreads();

        // ---- phase 2: Ck/Cq += P^T [K|Q]  (2-term A-split) ----
        {
            const int bsh = wz ? AT_QCH : AT_KCH;
#pragma unroll
            for (int ks = 0; ks < 4; ks++){
                int qk = ks*16;
                uint32_t ah[2][4], al[2][4];
#pragma unroll
                for (int ma = 0; ma < 2; ma++){
                    int tcol = wt2 + ma*16;
                    uint32_t off = (uint32_t)(tcol >> 6)*8192
                                 + SW((qk + srow_off)*128 + ((tcol & 63) + scol8)*2);
                    ldsm_x4_t(ah[ma][0], ah[ma][1], ah[ma][2], ah[ma][3], sbase + AT_PH + off);
                    ldsm_x4_t(al[ma][0], al[ma][1], al[ma][2], al[ma][3], sbase + AT_PL + off);
                }
                uint32_t bh4[4][4];
#pragma unroll
                for (int zn = 0; zn < 4; zn++){
                    uint32_t off = SW((qk + srow_off)*128 + (zn*16 + scol8)*2);
                    ldsm_x4_t(bh4[zn][0], bh4[zn][1], bh4[zn][2], bh4[zn][3], sbase + bsh + off);
                }
#pragma unroll
                for (int zn = 0; zn < 4; zn++)
#pragma unroll
                for (int ma = 0; ma < 2; ma++){
                    mma16816(c[ma][zn*2],   ah[ma], bh4[zn][0], bh4[zn][2]);
                    mma16816(c[ma][zn*2+1], ah[ma], bh4[zn][1], bh4[zn][3]);
                }
#pragma unroll
                for (int zn = 0; zn < 4; zn++)
#pragma unroll
                for (int ma = 0; ma < 2; ma++){
                    mma16816(c[ma][zn*2],   al[ma], bh4[zn][0], bh4[zn][2]);
                    mma16816(c[ma][zn*2+1], al[ma], bh4[zn][1], bh4[zn][3]);
                }
            }
        }
    }
    const int b = bh / HH, h = bh - b*HH;
    h16* Oh = wz ? g_Cqh : g_Ckh;
    h16* Ol = wz ? g_Cql : g_Ckl;
#pragma unroll
    for (int ma = 0; ma < 2; ma++)
#pragma unroll
    for (int na = 0; na < 8; na++){
        int z = na*8 + tg*2;
#pragma unroll
        for (int half = 0; half < 2; half++){
            int t = t0 + wt2 + ma*16 + gid + half*8;
            size_t adr = ((size_t)b*NN + t)*CC + h*ZZ + z;
            uint32_t hi, lo;
            split_pair(c[ma][na][half*2], c[ma][na][half*2+1], hi, lo);
            *reinterpret_cast<uint32_t*>(Oh + adr) = hi;
            *reinterpret_cast<uint32_t*>(Ol + adr) = lo;
        }
    }
}

// ============================ out = Ck U1^T + Cq U2^T + bp (2-term) =========
__global__ __launch_bounds__(256) void k_gemm_out(const float* __restrict__ bp,
                                                  float* __restrict__ out){
    MMA_PRE();
    const int m0 = blockIdx.x*128, n0 = blockIdx.y*128;
    ld_tile_a(sbase, O2_AH, g_Ckh + (size_t)m0*CC, CC, tid);
    ld_tile_a(sbase, O2_AL, g_Ckl + (size_t)m0*CC, CC, tid);
    ld_tile_a(sbase, O2_BH, g_U1h + (size_t)n0*CC, CC, tid);
    CP_COMMIT();
    for (int it = 0; it < 24; it++){
        int st = (it & 1) * STG2;
        if (it + 1 < 24){
            int i2 = it + 1;
            int pr = i2 & 1, kc = i2 >> 1;
            const h16* Ah = pr ? g_Cqh : g_Ckh;
            const h16* Al = pr ? g_Cql : g_Ckl;
            const h16* Bh = pr ? g_U2h : g_U1h;
            int s2 = (i2 & 1) * STG2;
            ld_tile_a(sbase, s2 + O2_AH, Ah + (size_t)m0*CC + kc*64, CC, tid);
            ld_tile_a(sbase, s2 + O2_AL, Al + (size_t)m0*CC + kc*64, CC, tid);
            ld_tile_a(sbase, s2 + O2_BH, Bh + (size_t)n0*CC + kc*64, CC, tid);
        }
        CP_COMMIT();
        CP_WAIT1();
        __syncthreads();
        mma_chunk2(c, sbase+st+O2_AH, sbase+st+O2_AL, sbase+st+O2_BH, wm0, wn0, lane);
        __syncthreads();
    }
    const int gid = lane >> 2, tg = lane & 3;
#pragma unroll
    for (int ma = 0; ma < 2; ma++)
#pragma unroll
    for (int na = 0; na < 8; na++){
        int row = m0 + wm0 + ma*16 + gid;
        int col = n0 + wn0 + na*8 + tg*2;
        float b0 = bp[col], b1 = bp[col+1];
        *reinterpret_cast<float2*>(out + (size_t)row*CC + col)
            = make_float2(c[ma][na][0] + b0, c[ma][na][1] + b1);
        *reinterpret_cast<float2*>(out + (size_t)(row+8)*CC + col)
            = make_float2(c[ma][na][2] + b0, c[ma][na][3] + b1);
    }
}

// ============================ host ==========================================
extern "C" void kernel_launch(void* const* d_in, const int* in_sizes, int n_in,
                              void* d_out, int out_size)
{
    (void)in_sizes; (void)n_in; (void)out_size;
    const float* x  = (const float*)d_in[0];
    const float* Wq = (const float*)d_in[1];
    const float* Wk = (const float*)d_in[2];
    const float* Wp = (const float*)d_in[3];
    const float* bp = (const float*)d_in[4];
    float* out = (float*)d_out;

    h16 *xh, *wqh, *wql, *wkh, *wkl, *wph, *wpl;
    cudaGetSymbolAddress((void**)&xh,  g_xh);
    cudaGetSymbolAddress((void**)&wqh, g_Wqh); cudaGetSymbolAddress((void**)&wql, g_Wql);
    cudaGetSymbolAddress((void**)&wkh, g_Wkh); cudaGetSymbolAddress((void**)&wkl, g_Wkl);
    cudaGetSymbolAddress((void**)&wph, g_Wph); cudaGetSymbolAddress((void**)&wpl, g_Wpl);
    h16 *u1h, *u2h, *qh, *kh;
    cudaGetSymbolAddress((void**)&u1h, g_U1h); cudaGetSymbolAddress((void**)&u2h, g_U2h);
    cudaGetSymbolAddress((void**)&qh,  g_Qh);  cudaGetSymbolAddress((void**)&kh,  g_Kh);

    cudaFuncSetAttribute(k_gemm_w,    cudaFuncAttributeMaxDynamicSharedMemorySize, SMEM_BYTES);
    cudaFuncSetAttribute(k_gemm_proj, cudaFuncAttributeMaxDynamicSharedMemorySize, SMEMP);
    cudaFuncSetAttribute(k_gemm_out,  cudaFuncAttributeMaxDynamicSharedMemorySize, SMEM2);
    cudaFuncSetAttribute(k_statsf,    cudaFuncAttributeMaxDynamicSharedMemorySize, ST_BYTES);
    cudaFuncSetAttribute(k_attn_f,    cudaFuncAttributeMaxDynamicSharedMemorySize, AT_BYTES);

    k_conv1<<<256, 256>>>(x, xh, BB*NN*CC/4);
    k_conv<<<64, 256>>>(Wq, wqh, wql, CC*CC/4);
    k_conv<<<64, 256>>>(Wk, wkh, wkl, CC*CC/4);
    k_conv<<<64, 256>>>(Wp, wph, wpl, CC*CC/4);

    k_gemm_w<<<dim3(6,6), 256, SMEM_BYTES>>>(wph, wpl, wqh, wql, u1h);
    k_gemm_w<<<dim3(6,6), 256, SMEM_BYTES>>>(wph, wpl, wkh, wkl, u2h);

    k_gemm_proj<<<dim3(64,6), 256, SMEMP>>>(xh, wqh, qh);
    k_gemm_proj<<<dim3(64,6), 256, SMEMP>>>(xh, wkh, kh);

    k_statsf<<<dim3(8, BH), 256, ST_BYTES>>>();
    k_attn_f<<<dim3(8, BH), 256, AT_BYTES>>>();

    k_gemm_out<<<dim3(64, 6), 256, SMEM2>>>(bp, out);
}

// round 12
// speedup vs baseline: 4.8747x; 1.3182x over previous
#include <cuda_runtime.h>
#include <cuda_fp16.h>
#include <cstdint>
#include <math.h>

#define BB 8
#define NN 1024
#define CC 768
#define HH 12
#define ZZ 64
#define BH (BB*HH)
#define SCALE 0.125f
typedef __half h16;

// ---------------- scratch ----------------
__device__ h16 g_xh[BB*NN*CC];
__device__ h16 g_Wqh[CC*CC], g_Wkh[CC*CC];
__device__ h16 g_Wph[CC*CC], g_Wpl[CC*CC];
__device__ h16 g_U1h[CC*CC], g_U2h[CC*CC];
__device__ h16 g_Qh[BH*NN*ZZ], g_Kh[BH*NN*ZZ];
__device__ float g_m[BH*NN], g_il[BH*NN];
__device__ h16 g_Ckh[BB*NN*CC], g_Cqh[BB*NN*CC];

// ---------------- helpers ----------------
#define SW(o) ((o) ^ (((o)>>3)&0x70))
// 2-term w kernel: 3 tiles/stage
#define W2_AH 0
#define W2_AL 16384
#define W2_BH 32768
#define STGW 49152
#define SMEMW 98304
// 1-term kernels (proj, out): 2 tiles/stage
#define P1_A 0
#define P1_B 16384
#define STGP 32768
#define SMEMP 65536

__device__ __forceinline__ uint32_t smem_u32(const void* p){
    uint32_t a;
    asm("{ .reg .u64 t; cvta.to.shared.u64 t, %1; cvt.u32.u64 %0, t; }" : "=r"(a) : "l"(p));
    return a;
}
__device__ __forceinline__ void ldsm_x4(uint32_t& r0, uint32_t& r1, uint32_t& r2, uint32_t& r3, uint32_t addr){
    asm volatile("ldmatrix.sync.aligned.m8n8.x4.shared.b16 {%0,%1,%2,%3}, [%4];"
        : "=r"(r0), "=r"(r1), "=r"(r2), "=r"(r3) : "r"(addr));
}
__device__ __forceinline__ void ldsm_x4_t(uint32_t& r0, uint32_t& r1, uint32_t& r2, uint32_t& r3, uint32_t addr){
    asm volatile("ldmatrix.sync.aligned.m8n8.x4.trans.shared.b16 {%0,%1,%2,%3}, [%4];"
        : "=r"(r0), "=r"(r1), "=r"(r2), "=r"(r3) : "r"(addr));
}
__device__ __forceinline__ void mma16816(float c[4], const uint32_t a[4], uint32_t b0, uint32_t b1){
    asm volatile("mma.sync.aligned.m16n8k16.row.col.f32.f16.f16.f32 "
        "{%0,%1,%2,%3}, {%4,%5,%6,%7}, {%8,%9}, {%0,%1,%2,%3};"
        : "+f"(c[0]), "+f"(c[1]), "+f"(c[2]), "+f"(c[3])
        : "r"(a[0]), "r"(a[1]), "r"(a[2]), "r"(a[3]), "r"(b0), "r"(b1));
}
__device__ __forceinline__ void cp16(uint32_t saddr, const void* g){
    asm volatile("cp.async.cg.shared.global [%0], [%1], 16;" :: "r"(saddr), "l"(g));
}
#define CP_COMMIT() asm volatile("cp.async.commit_group;" ::: "memory")
#define CP_WAIT1()  asm volatile("cp.async.wait_group 1;" ::: "memory")

__device__ __forceinline__ float fexp(float x){
    float y = x * 1.4426950408889634f;
    float n = rintf(y);
    float f = y - n;
    float p = 1.3333558146428443e-3f;
    p = fmaf(p, f, 9.6181291076284772e-3f);
    p = fmaf(p, f, 5.5504108664821580e-2f);
    p = fmaf(p, f, 2.4022650695910072e-1f);
    p = fmaf(p, f, 6.9314718055994531e-1f);
    p = fmaf(p, f, 1.0f);
    return __int_as_float(__float_as_int(p) + (((int)n) << 23));
}
__device__ __forceinline__ void split2(float v, h16& hi, h16& lo){
    hi = __float2half(v);
    lo = __float2half(v - __half2float(hi));
}
__device__ __forceinline__ void split_pair(float a, float b, uint32_t& hi, uint32_t& lo){
    h16 ah, al, bh_, bl;
    split2(a, ah, al); split2(b, bh_, bl);
    hi = (uint32_t)__half_as_ushort(ah) | ((uint32_t)__half_as_ushort(bh_) << 16);
    lo = (uint32_t)__half_as_ushort(al) | ((uint32_t)__half_as_ushort(bl) << 16);
}
__device__ __forceinline__ uint32_t pack2h(float a, float b){
    return (uint32_t)__half_as_ushort(__float2half(a))
         | ((uint32_t)__half_as_ushort(__float2half(b)) << 16);
}

// sync tile loader: rows x 64 h16 (128B rows), swizzled
__device__ __forceinline__ void ld_tile(char* sm, int off, const h16* __restrict__ g,
                                        int rows, int rstride, int tid){
    for (int i = tid; i < rows*8; i += 256){
        int r = i >> 3, c = i & 7;
        uint4 v = *reinterpret_cast<const uint4*>(g + (size_t)r*rstride + c*8);
        *reinterpret_cast<uint4*>(sm + off + SW(r*128 + c*16)) = v;
    }
}
// async tile loader (128 rows x 64 h16)
__device__ __forceinline__ void ld_tile_a(uint32_t sbase, int off, const h16* __restrict__ g,
                                          int rstride, int tid){
    for (int i = tid; i < 128*8; i += 256){
        int r = i >> 3, c = i & 7;
        cp16(sbase + off + SW(r*128 + c*16), g + (size_t)r*rstride + c*8);
    }
}

// 2-term block MMA (A split x B single): AhB + AlB
__device__ __forceinline__ void mma_chunk2(float c[2][8][4],
        uint32_t aH, uint32_t aL, uint32_t bH, int wm0, int wn0, int lane){
    const int lr = lane & 15, lh = lane >> 4;
#pragma unroll
    for (int ks = 0; ks < 4; ks++){
        uint32_t ah[2][4], al[2][4];
#pragma unroll
        for (int ma = 0; ma < 2; ma++){
            uint32_t off = SW((wm0 + ma*16 + lr)*128 + (ks*2 + lh)*16);
            ldsm_x4(ah[ma][0], ah[ma][1], ah[ma][2], ah[ma][3], aH + off);
            ldsm_x4(al[ma][0], al[ma][1], al[ma][2], al[ma][3], aL + off);
        }
        uint32_t bh[4][4];
#pragma unroll
        for (int np = 0; np < 4; np++){
            uint32_t off = SW((wn0 + np*16 + lr)*128 + (ks*2 + lh)*16);
            ldsm_x4(bh[np][0], bh[np][1], bh[np][2], bh[np][3], bH + off);
        }
#pragma unroll
        for (int np = 0; np < 4; np++)
#pragma unroll
        for (int ma = 0; ma < 2; ma++){
            mma16816(c[ma][np*2],   ah[ma], bh[np][0], bh[np][2]);
            mma16816(c[ma][np*2+1], ah[ma], bh[np][1], bh[np][3]);
        }
#pragma unroll
        for (int np = 0; np < 4; np++)
#pragma unroll
        for (int ma = 0; ma < 2; ma++){
            mma16816(c[ma][np*2],   al[ma], bh[np][0], bh[np][2]);
            mma16816(c[ma][np*2+1], al[ma], bh[np][1], bh[np][3]);
        }
    }
}

// 1-term block MMA (both single)
__device__ __forceinline__ void mma_chunk1(float c[2][8][4],
        uint32_t aH, uint32_t bH, int wm0, int wn0, int lane){
    const int lr = lane & 15, lh = lane >> 4;
#pragma unroll
    for (int ks = 0; ks < 4; ks++){
        uint32_t ah[2][4];
#pragma unroll
        for (int ma = 0; ma < 2; ma++){
            uint32_t off = SW((wm0 + ma*16 + lr)*128 + (ks*2 + lh)*16);
            ldsm_x4(ah[ma][0], ah[ma][1], ah[ma][2], ah[ma][3], aH + off);
        }
        uint32_t bh[4][4];
#pragma unroll
        for (int np = 0; np < 4; np++){
            uint32_t off = SW((wn0 + np*16 + lr)*128 + (ks*2 + lh)*16);
            ldsm_x4(bh[np][0], bh[np][1], bh[np][2], bh[np][3], bH + off);
        }
#pragma unroll
        for (int np = 0; np < 4; np++)
#pragma unroll
        for (int ma = 0; ma < 2; ma++){
            mma16816(c[ma][np*2],   ah[ma], bh[np][0], bh[np][2]);
            mma16816(c[ma][np*2+1], ah[ma], bh[np][1], bh[np][3]);
        }
    }
}

#define MMA_PRE() \
    extern __shared__ char sm[]; \
    const int tid = threadIdx.x, wid = tid >> 5, lane = tid & 31; \
    const uint32_t sbase = smem_u32(sm); \
    const int wm0 = (wid & 3) * 32, wn0 = (wid >> 2) * 64; \
    float c[2][8][4]; \
    _Pragma("unroll") for (int i = 0; i < 2; i++) \
    _Pragma("unroll") for (int j = 0; j < 8; j++) \
    _Pragma("unroll") for (int k = 0; k < 4; k++) c[i][j][k] = 0.0f;

// ============================ converters ====================================
__global__ __launch_bounds__(256) void k_conv(const float* __restrict__ in,
                                              h16* __restrict__ oh, h16* __restrict__ ol, int n4){
    for (int i = blockIdx.x*blockDim.x + threadIdx.x; i < n4; i += gridDim.x*blockDim.x){
        float4 v = reinterpret_cast<const float4*>(in)[i];
        uint32_t h0, l0, h1, l1;
        split_pair(v.x, v.y, h0, l0);
        split_pair(v.z, v.w, h1, l1);
        reinterpret_cast<uint2*>(oh)[i] = make_uint2(h0, h1);
        reinterpret_cast<uint2*>(ol)[i] = make_uint2(l0, l1);
    }
}
__global__ __launch_bounds__(256) void k_conv1(const float* __restrict__ in,
                                               h16* __restrict__ oh, int n4){
    for (int i = blockIdx.x*blockDim.x + threadIdx.x; i < n4; i += gridDim.x*blockDim.x){
        float4 v = reinterpret_cast<const float4*>(in)[i];
        reinterpret_cast<uint2*>(oh)[i] = make_uint2(pack2h(v.x, v.y), pack2h(v.z, v.w));
    }
}

// ============== weight GEMM: U[z] = Wp * W[z]^T (2-term, z picks Wq/Wk) =====
__global__ __launch_bounds__(256) void k_gemm_w(){
    MMA_PRE();
    const h16* Bh = blockIdx.z ? g_Wkh : g_Wqh;
    h16* Oh      = blockIdx.z ? g_U2h : g_U1h;
    const int m0 = blockIdx.x*128, n0 = blockIdx.y*128;
    ld_tile_a(sbase, W2_AH, g_Wph + (size_t)m0*CC, CC, tid);
    ld_tile_a(sbase, W2_AL, g_Wpl + (size_t)m0*CC, CC, tid);
    ld_tile_a(sbase, W2_BH, Bh + (size_t)n0*CC, CC, tid);
    CP_COMMIT();
    for (int kc = 0; kc < 12; kc++){
        int st = (kc & 1) * STGW;
        if (kc + 1 < 12){
            int s2 = ((kc+1) & 1) * STGW;
            ld_tile_a(sbase, s2 + W2_AH, g_Wph + (size_t)m0*CC + (kc+1)*64, CC, tid);
            ld_tile_a(sbase, s2 + W2_AL, g_Wpl + (size_t)m0*CC + (kc+1)*64, CC, tid);
            ld_tile_a(sbase, s2 + W2_BH, Bh + (size_t)n0*CC + (kc+1)*64, CC, tid);
        }
        CP_COMMIT();
        CP_WAIT1();
        __syncthreads();
        mma_chunk2(c, sbase+st+W2_AH, sbase+st+W2_AL, sbase+st+W2_BH, wm0, wn0, lane);
        __syncthreads();
    }
    const int gid = lane >> 2, tg = lane & 3;
#pragma unroll
    for (int ma = 0; ma < 2; ma++)
#pragma unroll
    for (int na = 0; na < 8; na++){
        int row = m0 + wm0 + ma*16 + gid;
        int col = n0 + wn0 + na*8 + tg*2;
        *reinterpret_cast<uint32_t*>(Oh + (size_t)row*CC + col)
            = pack2h(c[ma][na][0], c[ma][na][1]);
        *reinterpret_cast<uint32_t*>(Oh + (size_t)(row+8)*CC + col)
            = pack2h(c[ma][na][2], c[ma][na][3]);
    }
}

// ====== projection GEMM (1-term, per-head out; z picks Wq->Q / Wk->K) =======
__global__ __launch_bounds__(256) void k_gemm_proj(){
    MMA_PRE();
    const h16* B = blockIdx.z ? g_Wkh : g_Wqh;
    h16* Oh      = blockIdx.z ? g_Kh  : g_Qh;
    const int m0 = blockIdx.x*128, n0 = blockIdx.y*128;
    ld_tile_a(sbase, P1_A, g_xh + (size_t)m0*CC, CC, tid);
    ld_tile_a(sbase, P1_B, B + (size_t)n0*CC, CC, tid);
    CP_COMMIT();
    for (int kc = 0; kc < 12; kc++){
        int st = (kc & 1) * STGP;
        if (kc + 1 < 12){
            int s2 = ((kc+1) & 1) * STGP;
            ld_tile_a(sbase, s2 + P1_A, g_xh + (size_t)m0*CC + (kc+1)*64, CC, tid);
            ld_tile_a(sbase, s2 + P1_B, B + (size_t)n0*CC + (kc+1)*64, CC, tid);
        }
        CP_COMMIT();
        CP_WAIT1();
        __syncthreads();
        mma_chunk1(c, sbase+st+P1_A, sbase+st+P1_B, wm0, wn0, lane);
        __syncthreads();
    }
    const int gid = lane >> 2, tg = lane & 3;
#pragma unroll
    for (int ma = 0; ma < 2; ma++)
#pragma unroll
    for (int na = 0; na < 8; na++){
        int col = n0 + wn0 + na*8 + tg*2;
        int h = col >> 6, z = col & 63;
#pragma unroll
        for (int half = 0; half < 2; half++){
            int row = m0 + wm0 + ma*16 + gid + half*8;
            int b = row >> 10, tk = row & (NN-1);
            size_t adr = ((size_t)(b*HH + h)*NN + tk)*ZZ + z;
            *reinterpret_cast<uint32_t*>(Oh + adr)
                = pack2h(c[ma][na][half*2], c[ma][na][half*2+1]);
        }
    }
}

// ============================ flash stats (1-term S) ========================
#define ST_QH 0
#define ST_KH 16384
#define ST_MM 32768
#define ST_LL 33792
#define ST_BYTES 34816
__global__ __launch_bounds__(256) void k_statsf(){
    extern __shared__ char sm[];
    const int tid = threadIdx.x, wid = tid >> 5, lane = tid & 31;
    const uint32_t sbase = smem_u32(sm);
    const int bh = blockIdx.y, q0 = blockIdx.x*128;
    const int wq = (wid & 3)*32, wt = (wid >> 2)*64;
    const int gid = lane >> 2, tg = lane & 3;

    ld_tile(sm, ST_QH, g_Qh + ((size_t)bh*NN + q0)*ZZ, 128, ZZ, tid);

    float rm[2][2], rl[2][2];
#pragma unroll
    for (int i = 0; i < 2; i++)
#pragma unroll
    for (int j = 0; j < 2; j++){ rm[i][j] = -1e30f; rl[i][j] = 0.0f; }

    for (int t0 = 0; t0 < NN; t0 += 128){
        __syncthreads();
        ld_tile(sm, ST_KH, g_Kh + ((size_t)bh*NN + t0)*ZZ, 128, ZZ, tid);
        __syncthreads();

        float s[2][8][4];
#pragma unroll
        for (int i = 0; i < 2; i++)
#pragma unroll
        for (int j = 0; j < 8; j++)
#pragma unroll
        for (int k = 0; k < 4; k++) s[i][j][k] = 0.0f;

        mma_chunk1(s, sbase+ST_QH, sbase+ST_KH, wq, wt, lane);

#pragma unroll
        for (int ma = 0; ma < 2; ma++)
#pragma unroll
        for (int half = 0; half < 2; half++){
            float cm = -1e30f;
#pragma unroll
            for (int na = 0; na < 8; na++)
                cm = fmaxf(cm, fmaxf(s[ma][na][half*2], s[ma][na][half*2+1]));
            cm *= SCALE;
            cm = fmaxf(cm, __shfl_xor_sync(0xffffffffu, cm, 1));
            cm = fmaxf(cm, __shfl_xor_sync(0xffffffffu, cm, 2));
            float nm = fmaxf(rm[ma][half], cm);
            float ls = 0.0f;
#pragma unroll
            for (int na = 0; na < 8; na++)
                ls += fexp(s[ma][na][half*2]*SCALE - nm) + fexp(s[ma][na][half*2+1]*SCALE - nm);
            ls += __shfl_xor_sync(0xffffffffu, ls, 1);
            ls += __shfl_xor_sync(0xffffffffu, ls, 2);
            float d = fmaxf(rm[ma][half] - nm, -60.0f);
            rl[ma][half] = rl[ma][half]*fexp(d) + ls;
            rm[ma][half] = nm;
        }
    }
    float* smm = reinterpret_cast<float*>(sm + ST_MM);
    float* sml = reinterpret_cast<float*>(sm + ST_LL);
    __syncthreads();
    if (tg == 0){
#pragma unroll
        for (int ma = 0; ma < 2; ma++)
#pragma unroll
        for (int half = 0; half < 2; half++){
            int q = wq + ma*16 + gid + half*8;
            int wti = wid >> 2;
            smm[wti*128 + q] = rm[ma][half];
            sml[wti*128 + q] = rl[ma][half];
        }
    }
    __syncthreads();
    if (tid < 128){
        float m0 = smm[tid], m1 = smm[128 + tid];
        float l0 = sml[tid], l1 = sml[128 + tid];
        float m = fmaxf(m0, m1);
        float l = l0*fexp(fmaxf(m0 - m, -60.0f)) + l1*fexp(fmaxf(m1 - m, -60.0f));
        g_m [bh*NN + q0 + tid] = m;
        g_il[bh*NN + q0 + tid] = 1.0f / l;
    }
}

// ============================ fused attention pass ==========================
// phase1: S (1-term) -> P fp16 (hi-only) smem; phase2: Ck/Cq += P^T [K|Q] (1-term)
#define AT_KTH 0
#define AT_QCH 16384
#define AT_KCH 24576
#define AT_PH  32768
#define AT_MS  49152
#define AT_IL  49408
#define AT_BYTES 49664
__global__ __launch_bounds__(256) void k_attn_f(){
    extern __shared__ char sm[];
    const int tid = threadIdx.x, wid = tid >> 5, lane = tid & 31;
    const uint32_t sbase = smem_u32(sm);
    const int bh = blockIdx.y, t0 = blockIdx.x*128;
    const int gid = lane >> 2, tg = lane & 3;
    const int lr = lane & 15, lh = lane >> 4;
    const int srow_off = (lane & 7) + ((lane & 16) ? 8 : 0);
    const int scol8 = ((lane >> 3) & 1) * 8;
    float* ms = reinterpret_cast<float*>(sm + AT_MS);
    float* il = reinterpret_cast<float*>(sm + AT_IL);

    const int wt2 = (wid & 3)*32, wz = wid >> 2;
    float c[2][8][4];
#pragma unroll
    for (int i = 0; i < 2; i++)
#pragma unroll
    for (int j = 0; j < 8; j++)
#pragma unroll
    for (int k = 0; k < 4; k++) c[i][j][k] = 0.0f;

    ld_tile(sm, AT_KTH, g_Kh + ((size_t)bh*NN + t0)*ZZ, 128, ZZ, tid);

    const int wq1 = (wid & 1)*32, wt1 = (wid >> 1)*32;

    for (int q0c = 0; q0c < NN; q0c += 64){
        __syncthreads();
        ld_tile(sm, AT_QCH, g_Qh + ((size_t)bh*NN + q0c)*ZZ, 64, ZZ, tid);
        ld_tile(sm, AT_KCH, g_Kh + ((size_t)bh*NN + q0c)*ZZ, 64, ZZ, tid);
        if (tid < 64)       ms[tid]      = g_m [bh*NN + q0c + tid];
        else if (tid < 128) il[tid - 64] = g_il[bh*NN + q0c + tid - 64];
        __syncthreads();

        // ---- phase 1: S chunk (1-term) -> P smem (hi fp16) ----
        {
            float s1[2][4][4];
#pragma unroll
            for (int i = 0; i < 2; i++)
#pragma unroll
            for (int j = 0; j < 4; j++)
#pragma unroll
            for (int k = 0; k < 4; k++) s1[i][j][k] = 0.0f;
#pragma unroll
            for (int ks = 0; ks < 4; ks++){
                uint32_t ah[2][4];
#pragma unroll
                for (int ma = 0; ma < 2; ma++){
                    uint32_t off = SW((wq1 + ma*16 + lr)*128 + (ks*2 + lh)*16);
                    ldsm_x4(ah[ma][0], ah[ma][1], ah[ma][2], ah[ma][3], sbase + AT_QCH + off);
                }
                uint32_t bh4[2][4];
#pragma unroll
                for (int np = 0; np < 2; np++){
                    uint32_t off = SW((wt1 + np*16 + lr)*128 + (ks*2 + lh)*16);
                    ldsm_x4(bh4[np][0], bh4[np][1], bh4[np][2], bh4[np][3], sbase + AT_KTH + off);
                }
#pragma unroll
                for (int np = 0; np < 2; np++)
#pragma unroll
                for (int ma = 0; ma < 2; ma++){
                    mma16816(s1[ma][np*2],   ah[ma], bh4[np][0], bh4[np][2]);
                    mma16816(s1[ma][np*2+1], ah[ma], bh4[np][1], bh4[np][3]);
                }
            }
#pragma unroll
            for (int ma = 0; ma < 2; ma++)
#pragma unroll
            for (int na = 0; na < 4; na++)
#pragma unroll
            for (int half = 0; half < 2; half++){
                int qloc = wq1 + ma*16 + gid + half*8;
                float M = ms[qloc], I = il[qloc];
                int tloc = wt1 + na*8 + tg*2;
                float p0 = fexp(s1[ma][na][half*2]  *SCALE - M)*I;
                float p1 = fexp(s1[ma][na][half*2+1]*SCALE - M)*I;
                uint32_t off = (uint32_t)(tloc >> 6)*8192 + SW(qloc*128 + (tloc & 63)*2);
                *reinterpret_cast<uint32_t*>(sm + AT_PH + off) = pack2h(p0, p1);
            }
        }
        __syncthreads();

        // ---- phase 2: Ck/Cq += P^T [K|Q]  (1-term) ----
        {
            const int bsh = wz ? AT_QCH : AT_KCH;
#pragma unroll
            for (int ks = 0; ks < 4; ks++){
                int qk = ks*16;
                uint32_t ah[2][4];
#pragma unroll
                for (int ma = 0; ma < 2; ma++){
                    int tcol = wt2 + ma*16;
                    uint32_t off = (uint32_t)(tcol >> 6)*8192
                                 + SW((qk + srow_off)*128 + ((tcol & 63) + scol8)*2);
                    ldsm_x4_t(ah[ma][0], ah[ma][1], ah[ma][2], ah[ma][3], sbase + AT_PH + off);
                }
                uint32_t bh4[4][4];
#pragma unroll
                for (int zn = 0; zn < 4; zn++){
                    uint32_t off = SW((qk + srow_off)*128 + (zn*16 + scol8)*2);
                    ldsm_x4_t(bh4[zn][0], bh4[zn][1], bh4[zn][2], bh4[zn][3], sbase + bsh + off);
                }
#pragma unroll
                for (int zn = 0; zn < 4; zn++)
#pragma unroll
                for (int ma = 0; ma < 2; ma++){
                    mma16816(c[ma][zn*2],   ah[ma], bh4[zn][0], bh4[zn][2]);
                    mma16816(c[ma][zn*2+1], ah[ma], bh4[zn][1], bh4[zn][3]);
                }
            }
        }
    }
    const int b = bh / HH, h = bh - b*HH;
    h16* Oh = wz ? g_Cqh : g_Ckh;
#pragma unroll
    for (int ma = 0; ma < 2; ma++)
#pragma unroll
    for (int na = 0; na < 8; na++){
        int z = na*8 + tg*2;
#pragma unroll
        for (int half = 0; half < 2; half++){
            int t = t0 + wt2 + ma*16 + gid + half*8;
            size_t adr = ((size_t)b*NN + t)*CC + h*ZZ + z;
            *reinterpret_cast<uint32_t*>(Oh + adr)
                = pack2h(c[ma][na][half*2], c[ma][na][half*2+1]);
        }
    }
}

// ============================ out = Ck U1^T + Cq U2^T + bp (1-term) =========
__global__ __launch_bounds__(256) void k_gemm_out(const float* __restrict__ bp,
                                                  float* __restrict__ out){
    MMA_PRE();
    const int m0 = blockIdx.x*128, n0 = blockIdx.y*128;
    ld_tile_a(sbase, P1_A, g_Ckh + (size_t)m0*CC, CC, tid);
    ld_tile_a(sbase, P1_B, g_U1h + (size_t)n0*CC, CC, tid);
    CP_COMMIT();
    for (int it = 0; it < 24; it++){
        int st = (it & 1) * STGP;
        if (it + 1 < 24){
            int i2 = it + 1;
            int pr = i2 & 1, kc = i2 >> 1;
            const h16* A = pr ? g_Cqh : g_Ckh;
            const h16* B = pr ? g_U2h : g_U1h;
            int s2 = (i2 & 1) * STGP;
            ld_tile_a(sbase, s2 + P1_A, A + (size_t)m0*CC + kc*64, CC, tid);
            ld_tile_a(sbase, s2 + P1_B, B + (size_t)n0*CC + kc*64, CC, tid);
        }
        CP_COMMIT();
        CP_WAIT1();
        __syncthreads();
        mma_chunk1(c, sbase+st+P1_A, sbase+st+P1_B, wm0, wn0, lane);
        __syncthreads();
    }
    const int gid = lane >> 2, tg = lane & 3;
#pragma unroll
    for (int ma = 0; ma < 2; ma++)
#pragma unroll
    for (int na = 0; na < 8; na++){
        int row = m0 + wm0 + ma*16 + gid;
        int col = n0 + wn0 + na*8 + tg*2;
        float b0 = bp[col], b1 = bp[col+1];
        *reinterpret_cast<float2*>(out + (size_t)row*CC + col)
            = make_float2(c[ma][na][0] + b0, c[ma][na][1] + b1);
        *reinterpret_cast<float2*>(out + (size_t)(row+8)*CC + col)
            = make_float2(c[ma][na][2] + b0, c[ma][na][3] + b1);
    }
}

// ============================ host ==========================================
extern "C" void kernel_launch(void* const* d_in, const int* in_sizes, int n_in,
                              void* d_out, int out_size)
{
    (void)in_sizes; (void)n_in; (void)out_size;
    const float* x  = (const float*)d_in[0];
    const float* Wq = (const float*)d_in[1];
    const float* Wk = (const float*)d_in[2];
    const float* Wp = (const float*)d_in[3];
    const float* bp = (const float*)d_in[4];
    float* out = (float*)d_out;

    h16 *xh, *wqh, *wkh, *wph, *wpl;
    cudaGetSymbolAddress((void**)&xh,  g_xh);
    cudaGetSymbolAddress((void**)&wqh, g_Wqh);
    cudaGetSymbolAddress((void**)&wkh, g_Wkh);
    cudaGetSymbolAddress((void**)&wph, g_Wph); cudaGetSymbolAddress((void**)&wpl, g_Wpl);

    cudaFuncSetAttribute(k_gemm_w,    cudaFuncAttributeMaxDynamicSharedMemorySize, SMEMW);
    cudaFuncSetAttribute(k_gemm_proj, cudaFuncAttributeMaxDynamicSharedMemorySize, SMEMP);
    cudaFuncSetAttribute(k_gemm_out,  cudaFuncAttributeMaxDynamicSharedMemorySize, SMEMP);
    cudaFuncSetAttribute(k_statsf,    cudaFuncAttributeMaxDynamicSharedMemorySize, ST_BYTES);
    cudaFuncSetAttribute(k_attn_f,    cudaFuncAttributeMaxDynamicSharedMemorySize, AT_BYTES);

    k_conv1<<<256, 256>>>(x,  xh,  BB*NN*CC/4);
    k_conv1<<<64, 256>>>(Wq, wqh, CC*CC/4);
    k_conv1<<<64, 256>>>(Wk, wkh, CC*CC/4);
    k_conv<<<64, 256>>>(Wp, wph, wpl, CC*CC/4);

    k_gemm_w<<<dim3(6,6,2), 256, SMEMW>>>();
    k_gemm_proj<<<dim3(64,6,2), 256, SMEMP>>>();

    k_statsf<<<dim3(8, BH), 256, ST_BYTES>>>();
    k_attn_f<<<dim3(8, BH), 256, AT_BYTES>>>();

    k_gemm_out<<<dim3(64, 6), 256, SMEMP>>>(bp, out);
}

// round 14
// speedup vs baseline: 6.0401x; 1.2391x over previous
#include <cuda_runtime.h>
#include <cuda_fp16.h>
#include <cstdint>
#include <math.h>

#define BB 8
#define NN 1024
#define CC 768
#define HH 12
#define ZZ 64
#define BH (BB*HH)
#define SCALE 0.125f
typedef __half h16;

// ---------------- scratch ----------------
__device__ h16 g_xh[BB*NN*CC];
__device__ h16 g_Wqh[CC*CC], g_Wkh[CC*CC], g_Wph[CC*CC];
__device__ h16 g_U1h[CC*CC], g_U2h[CC*CC];
__device__ h16 g_Qh[BH*NN*ZZ], g_Kh[BH*NN*ZZ];
__device__ float g_m[BH*NN], g_il[BH*NN];
__device__ h16 g_Ckh[BB*NN*CC], g_Cqh[BB*NN*CC];

// ---------------- helpers ----------------
#define SW(o) ((o) ^ (((o)>>3)&0x70))
#define P1_A 0
#define P1_B 16384
#define STGP 32768
#define SMEMP 65536

__device__ __forceinline__ uint32_t smem_u32(const void* p){
    uint32_t a;
    asm("{ .reg .u64 t; cvta.to.shared.u64 t, %1; cvt.u32.u64 %0, t; }" : "=r"(a) : "l"(p));
    return a;
}
__device__ __forceinline__ void ldsm_x4(uint32_t& r0, uint32_t& r1, uint32_t& r2, uint32_t& r3, uint32_t addr){
    asm volatile("ldmatrix.sync.aligned.m8n8.x4.shared.b16 {%0,%1,%2,%3}, [%4];"
        : "=r"(r0), "=r"(r1), "=r"(r2), "=r"(r3) : "r"(addr));
}
__device__ __forceinline__ void ldsm_x4_t(uint32_t& r0, uint32_t& r1, uint32_t& r2, uint32_t& r3, uint32_t addr){
    asm volatile("ldmatrix.sync.aligned.m8n8.x4.trans.shared.b16 {%0,%1,%2,%3}, [%4];"
        : "=r"(r0), "=r"(r1), "=r"(r2), "=r"(r3) : "r"(addr));
}
__device__ __forceinline__ void mma16816(float c[4], const uint32_t a[4], uint32_t b0, uint32_t b1){
    asm volatile("mma.sync.aligned.m16n8k16.row.col.f32.f16.f16.f32 "
        "{%0,%1,%2,%3}, {%4,%5,%6,%7}, {%8,%9}, {%0,%1,%2,%3};"
        : "+f"(c[0]), "+f"(c[1]), "+f"(c[2]), "+f"(c[3])
        : "r"(a[0]), "r"(a[1]), "r"(a[2]), "r"(a[3]), "r"(b0), "r"(b1));
}
__device__ __forceinline__ void cp16(uint32_t saddr, const void* g){
    asm volatile("cp.async.cg.shared.global [%0], [%1], 16;" :: "r"(saddr), "l"(g));
}
#define CP_COMMIT() asm volatile("cp.async.commit_group;" ::: "memory")
#define CP_WAIT0()  asm volatile("cp.async.wait_group 0;" ::: "memory")

__device__ __forceinline__ float fexp(float x){
    float y = x * 1.4426950408889634f;
    float n = rintf(y);
    float f = y - n;
    float p = 1.3333558146428443e-3f;
    p = fmaf(p, f, 9.6181291076284772e-3f);
    p = fmaf(p, f, 5.5504108664821580e-2f);
    p = fmaf(p, f, 2.4022650695910072e-1f);
    p = fmaf(p, f, 6.9314718055994531e-1f);
    p = fmaf(p, f, 1.0f);
    return __int_as_float(__float_as_int(p) + (((int)n) << 23));
}
__device__ __forceinline__ uint32_t pack2h(float a, float b){
    return (uint32_t)__half_as_ushort(__float2half(a))
         | ((uint32_t)__half_as_ushort(__float2half(b)) << 16);
}

// async tile loader: rows x 64 h16 (128B rows), swizzled
__device__ __forceinline__ void ld_tile_a(uint32_t sbase, int off, const h16* __restrict__ g,
                                          int rows, int rstride, int tid){
    for (int i = tid; i < rows*8; i += 256){
        int r = i >> 3, c = i & 7;
        cp16(sbase + off + SW(r*128 + c*16), g + (size_t)r*rstride + c*8);
    }
}

// 1-term block MMA (both single): block 128x128, warp 32x64
__device__ __forceinline__ void mma_chunk1(float c[2][8][4],
        uint32_t aH, uint32_t bH, int wm0, int wn0, int lane){
    const int lr = lane & 15, lh = lane >> 4;
#pragma unroll
    for (int ks = 0; ks < 4; ks++){
        uint32_t ah[2][4];
#pragma unroll
        for (int ma = 0; ma < 2; ma++){
            uint32_t off = SW((wm0 + ma*16 + lr)*128 + (ks*2 + lh)*16);
            ldsm_x4(ah[ma][0], ah[ma][1], ah[ma][2], ah[ma][3], aH + off);
        }
        uint32_t bh[4][4];
#pragma unroll
        for (int np = 0; np < 4; np++){
            uint32_t off = SW((wn0 + np*16 + lr)*128 + (ks*2 + lh)*16);
            ldsm_x4(bh[np][0], bh[np][1], bh[np][2], bh[np][3], bH + off);
        }
#pragma unroll
        for (int np = 0; np < 4; np++)
#pragma unroll
        for (int ma = 0; ma < 2; ma++){
            mma16816(c[ma][np*2],   ah[ma], bh[np][0], bh[np][2]);
            mma16816(c[ma][np*2+1], ah[ma], bh[np][1], bh[np][3]);
        }
    }
}

#define MMA_PRE() \
    extern __shared__ char sm[]; \
    const int tid = threadIdx.x, wid = tid >> 5, lane = tid & 31; \
    const uint32_t sbase = smem_u32(sm); \
    const int wm0 = (wid & 3) * 32, wn0 = (wid >> 2) * 64; \
    float c[2][8][4]; \
    _Pragma("unroll") for (int i = 0; i < 2; i++) \
    _Pragma("unroll") for (int j = 0; j < 8; j++) \
    _Pragma("unroll") for (int k = 0; k < 4; k++) c[i][j][k] = 0.0f;

// ============================ fused converter ===============================
#define X4 (BB*NN*CC/4)
#define W4 (CC*CC/4)
__global__ __launch_bounds__(256) void k_conv_all(
    const float* __restrict__ x,  const float* __restrict__ Wq,
    const float* __restrict__ Wk, const float* __restrict__ Wp)
{
    const int total = X4 + 3*W4;
    for (int i = blockIdx.x*blockDim.x + threadIdx.x; i < total; i += gridDim.x*blockDim.x){
        const float* src; h16* dst; int off;
        if (i < X4)            { src = x;  dst = g_xh;  off = i; }
        else if (i < X4+W4)    { src = Wq; dst = g_Wqh; off = i - X4; }
        else if (i < X4+2*W4)  { src = Wk; dst = g_Wkh; off = i - X4 - W4; }
        else                   { src = Wp; dst = g_Wph; off = i - X4 - 2*W4; }
        float4 v = reinterpret_cast<const float4*>(src)[off];
        reinterpret_cast<uint2*>(dst)[off] = make_uint2(pack2h(v.x, v.y), pack2h(v.z, v.w));
    }
}

// ========= fused proj + weight GEMM (all 1-term, single-sync pipeline) ======
__global__ __launch_bounds__(256) void k_gemm_fused(){
    const int zid = blockIdx.z;
    const bool isw = (zid == 2);
    if (isw && blockIdx.x >= 12) return;
    MMA_PRE();
    const int n0 = blockIdx.y*128;
    int m0, sel = 0;
    const h16 *A, *B;
    if (!isw){
        m0 = blockIdx.x*128;
        A = g_xh + (size_t)m0*CC;
        B = (zid ? g_Wkh : g_Wqh) + (size_t)n0*CC;
    } else {
        sel = blockIdx.x >= 6;
        m0 = (blockIdx.x - (sel ? 6 : 0))*128;
        A = g_Wph + (size_t)m0*CC;
        B = (sel ? g_Wkh : g_Wqh) + (size_t)n0*CC;
    }
    ld_tile_a(sbase, P1_A, A, 128, CC, tid);
    ld_tile_a(sbase, P1_B, B, 128, CC, tid);
    CP_COMMIT();
    for (int kc = 0; kc < 12; kc++){
        CP_WAIT0();
        __syncthreads();
        if (kc + 1 < 12){
            int s2 = ((kc+1) & 1) * STGP;
            ld_tile_a(sbase, s2 + P1_A, A + (kc+1)*64, 128, CC, tid);
            ld_tile_a(sbase, s2 + P1_B, B + (kc+1)*64, 128, CC, tid);
            CP_COMMIT();
        }
        int st = (kc & 1) * STGP;
        mma_chunk1(c, sbase+st+P1_A, sbase+st+P1_B, wm0, wn0, lane);
    }
    const int gid = lane >> 2, tg = lane & 3;
    if (!isw){
        h16* Oh = zid ? g_Kh : g_Qh;
#pragma unroll
        for (int ma = 0; ma < 2; ma++)
#pragma unroll
        for (int na = 0; na < 8; na++){
            int col = n0 + wn0 + na*8 + tg*2;
            int h = col >> 6, z = col & 63;
#pragma unroll
            for (int half = 0; half < 2; half++){
                int row = m0 + wm0 + ma*16 + gid + half*8;
                int b = row >> 10, tk = row & (NN-1);
                size_t adr = ((size_t)(b*HH + h)*NN + tk)*ZZ + z;
                *reinterpret_cast<uint32_t*>(Oh + adr)
                    = pack2h(c[ma][na][half*2], c[ma][na][half*2+1]);
            }
        }
    } else {
        h16* Oh = sel ? g_U2h : g_U1h;
#pragma unroll
        for (int ma = 0; ma < 2; ma++)
#pragma unroll
        for (int na = 0; na < 8; na++){
            int row = m0 + wm0 + ma*16 + gid;
            int col = n0 + wn0 + na*8 + tg*2;
            *reinterpret_cast<uint32_t*>(Oh + (size_t)row*CC + col)
                = pack2h(c[ma][na][0], c[ma][na][1]);
            *reinterpret_cast<uint32_t*>(Oh + (size_t)(row+8)*CC + col)
                = pack2h(c[ma][na][2], c[ma][na][3]);
        }
    }
}

// ============================ flash stats (1-term S, cp.async K) ============
#define ST_QH 0
#define ST_KH0 16384
#define ST_KH1 32768
#define ST_MM 49152
#define ST_LL 50176
#define ST_BYTES 51200
__global__ __launch_bounds__(256) void k_statsf(){
    extern __shared__ char sm[];
    const int tid = threadIdx.x, wid = tid >> 5, lane = tid & 31;
    const uint32_t sbase = smem_u32(sm);
    const int bh = blockIdx.y, q0 = blockIdx.x*128;
    const int wq = (wid & 3)*32, wt = (wid >> 2)*64;
    const int gid = lane >> 2, tg = lane & 3;

    ld_tile_a(sbase, ST_QH,  g_Qh + ((size_t)bh*NN + q0)*ZZ, 128, ZZ, tid);
    ld_tile_a(sbase, ST_KH0, g_Kh + (size_t)bh*NN*ZZ,        128, ZZ, tid);
    CP_COMMIT();

    float rm[2][2], rl[2][2];
#pragma unroll
    for (int i = 0; i < 2; i++)
#pragma unroll
    for (int j = 0; j < 2; j++){ rm[i][j] = -1e30f; rl[i][j] = 0.0f; }

    for (int it = 0; it < 8; it++){
        CP_WAIT0();
        __syncthreads();
        if (it + 1 < 8){
            int kb = ((it+1) & 1) ? ST_KH1 : ST_KH0;
            ld_tile_a(sbase, kb, g_Kh + ((size_t)bh*NN + (it+1)*128)*ZZ, 128, ZZ, tid);
            CP_COMMIT();
        }
        int kcur = (it & 1) ? ST_KH1 : ST_KH0;

        float s[2][8][4];
#pragma unroll
        for (int i = 0; i < 2; i++)
#pragma unroll
        for (int j = 0; j < 8; j++)
#pragma unroll
        for (int k = 0; k < 4; k++) s[i][j][k] = 0.0f;

        mma_chunk1(s, sbase+ST_QH, sbase+kcur, wq, wt, lane);

#pragma unroll
        for (int ma = 0; ma < 2; ma++)
#pragma unroll
        for (int half = 0; half < 2; half++){
            float cm = -1e30f;
#pragma unroll
            for (int na = 0; na < 8; na++)
                cm = fmaxf(cm, fmaxf(s[ma][na][half*2], s[ma][na][half*2+1]));
            cm *= SCALE;
            cm = fmaxf(cm, __shfl_xor_sync(0xffffffffu, cm, 1));
            cm = fmaxf(cm, __shfl_xor_sync(0xffffffffu, cm, 2));
            float nm = fmaxf(rm[ma][half], cm);
            float ls = 0.0f;
#pragma unroll
            for (int na = 0; na < 8; na++)
                ls += fexp(s[ma][na][half*2]*SCALE - nm) + fexp(s[ma][na][half*2+1]*SCALE - nm);
            ls += __shfl_xor_sync(0xffffffffu, ls, 1);
            ls += __shfl_xor_sync(0xffffffffu, ls, 2);
            float d = fmaxf(rm[ma][half] - nm, -60.0f);
            rl[ma][half] = rl[ma][half]*fexp(d) + ls;
            rm[ma][half] = nm;
        }
    }
    float* smm = reinterpret_cast<float*>(sm + ST_MM);
    float* sml = reinterpret_cast<float*>(sm + ST_LL);
    __syncthreads();
    if (tg == 0){
#pragma unroll
        for (int ma = 0; ma < 2; ma++)
#pragma unroll
        for (int half = 0; half < 2; half++){
            int q = wq + ma*16 + gid + half*8;
            int wti = wid >> 2;
            smm[wti*128 + q] = rm[ma][half];
            sml[wti*128 + q] = rl[ma][half];
        }
    }
    __syncthreads();
    if (tid < 128){
        float m0 = smm[tid], m1 = smm[128 + tid];
        float l0 = sml[tid], l1 = sml[128 + tid];
        float m = fmaxf(m0, m1);
        float l = l0*fexp(fmaxf(m0 - m, -60.0f)) + l1*fexp(fmaxf(m1 - m, -60.0f));
        g_m [bh*NN + q0 + tid] = m;
        g_il[bh*NN + q0 + tid] = 1.0f / l;
    }
}

// ============================ fused attention pass ==========================
#define AT_KTH 0
#define AT_QC0 16384
#define AT_KC0 24576
#define AT_QC1 32768
#define AT_KC1 40960
#define AT_PH  49152
#define AT_MS  65536
#define AT_IL  66048
#define AT_BYTES 66560
__global__ __launch_bounds__(256) void k_attn_f(){
    extern __shared__ char sm[];
    const int tid = threadIdx.x, wid = tid >> 5, lane = tid & 31;
    const uint32_t sbase = smem_u32(sm);
    const int bh = blockIdx.y, t0 = blockIdx.x*128;
    const int gid = lane >> 2, tg = lane & 3;
    const int lr = lane & 15, lh = lane >> 4;
    const int srow_off = (lane & 7) + ((lane & 16) ? 8 : 0);
    const int scol8 = ((lane >> 3) & 1) * 8;
    float* ms = reinterpret_cast<float*>(sm + AT_MS);
    float* il = reinterpret_cast<float*>(sm + AT_IL);

    const int wt2 = (wid & 3)*32, wz = wid >> 2;
    float c[2][8][4];
#pragma unroll
    for (int i = 0; i < 2; i++)
#pragma unroll
    for (int j = 0; j < 8; j++)
#pragma unroll
    for (int k = 0; k < 4; k++) c[i][j][k] = 0.0f;

    const int wq1 = (wid & 1)*32, wt1 = (wid >> 1)*32;

    ld_tile_a(sbase, AT_KTH, g_Kh + ((size_t)bh*NN + t0)*ZZ, 128, ZZ, tid);
    ld_tile_a(sbase, AT_QC0, g_Qh + (size_t)bh*NN*ZZ, 64, ZZ, tid);
    ld_tile_a(sbase, AT_KC0, g_Kh + (size_t)bh*NN*ZZ, 64, ZZ, tid);
    if (tid < 64)       ms[tid]      = g_m [bh*NN + tid];
    else if (tid < 128) il[tid - 64] = g_il[bh*NN + tid - 64];
    CP_COMMIT();

    for (int j = 0; j < 16; j++){
        const int nb = j & 1;
        const int qcb = nb ? AT_QC1 : AT_QC0;
        const int kcb = nb ? AT_KC1 : AT_KC0;
        CP_WAIT0();
        __syncthreads();
        if (j + 1 < 16){
            int q2 = (j+1)*64, b2 = (j+1) & 1;
            ld_tile_a(sbase, b2 ? AT_QC1 : AT_QC0, g_Qh + ((size_t)bh*NN + q2)*ZZ, 64, ZZ, tid);
            ld_tile_a(sbase, b2 ? AT_KC1 : AT_KC0, g_Kh + ((size_t)bh*NN + q2)*ZZ, 64, ZZ, tid);
            if (tid < 64)       ms[b2*64 + tid]      = g_m [bh*NN + q2 + tid];
            else if (tid < 128) il[b2*64 + tid - 64] = g_il[bh*NN + q2 + tid - 64];
            CP_COMMIT();
        }

        // ---- phase 1: S chunk (1-term) -> P smem (hi fp16) ----
        {
            float s1[2][4][4];
#pragma unroll
            for (int i = 0; i < 2; i++)
#pragma unroll
            for (int jj = 0; jj < 4; jj++)
#pragma unroll
            for (int k = 0; k < 4; k++) s1[i][jj][k] = 0.0f;
#pragma unroll
            for (int ks = 0; ks < 4; ks++){
                uint32_t ah[2][4];
#pragma unroll
                for (int ma = 0; ma < 2; ma++){
                    uint32_t off = SW((wq1 + ma*16 + lr)*128 + (ks*2 + lh)*16);
                    ldsm_x4(ah[ma][0], ah[ma][1], ah[ma][2], ah[ma][3], sbase + qcb + off);
                }
                uint32_t bh4[2][4];
#pragma unroll
                for (int np = 0; np < 2; np++){
                    uint32_t off = SW((wt1 + np*16 + lr)*128 + (ks*2 + lh)*16);
                    ldsm_x4(bh4[np][0], bh4[np][1], bh4[np][2], bh4[np][3], sbase + AT_KTH + off);
                }
#pragma unroll
                for (int np = 0; np < 2; np++)
#pragma unroll
                for (int ma = 0; ma < 2; ma++){
                    mma16816(s1[ma][np*2],   ah[ma], bh4[np][0], bh4[np][2]);
                    mma16816(s1[ma][np*2+1], ah[ma], bh4[np][1], bh4[np][3]);
                }
            }
#pragma unroll
            for (int ma = 0; ma < 2; ma++)
#pragma unroll
            for (int na = 0; na < 4; na++)
#pragma unroll
            for (int half = 0; half < 2; half++){
                int qloc = wq1 + ma*16 + gid + half*8;
                float M = ms[nb*64 + qloc], I = il[nb*64 + qloc];
                int tloc = wt1 + na*8 + tg*2;
                float p0 = fexp(s1[ma][na][half*2]  *SCALE - M)*I;
                float p1 = fexp(s1[ma][na][half*2+1]*SCALE - M)*I;
                uint32_t off = (uint32_t)(tloc >> 6)*8192 + SW(qloc*128 + (tloc & 63)*2);
                *reinterpret_cast<uint32_t*>(sm + AT_PH + off) = pack2h(p0, p1);
            }
        }
        __syncthreads();

        // ---- phase 2: Ck/Cq += P^T [K|Q]  (1-term) ----
        {
            const int bsh = wz ? qcb : kcb;
#pragma unroll
            for (int ks = 0; ks < 4; ks++){
                int qk = ks*16;
                uint32_t ah[2][4];
#pragma unroll
                for (int ma = 0; ma < 2; ma++){
                    int tcol = wt2 + ma*16;
                    uint32_t off = (uint32_t)(tcol >> 6)*8192
                                 + SW((qk + srow_off)*128 + ((tcol & 63) + scol8)*2);
                    ldsm_x4_t(ah[ma][0], ah[ma][1], ah[ma][2], ah[ma][3], sbase + AT_PH + off);
                }
                uint32_t bh4[4][4];
#pragma unroll
                for (int zn = 0; zn < 4; zn++){
                    uint32_t off = SW((qk + srow_off)*128 + (zn*16 + scol8)*2);
                    ldsm_x4_t(bh4[zn][0], bh4[zn][1], bh4[zn][2], bh4[zn][3], sbase + bsh + off);
                }
#pragma unroll
                for (int zn = 0; zn < 4; zn++)
#pragma unroll
                for (int ma = 0; ma < 2; ma++){
                    mma16816(c[ma][zn*2],   ah[ma], bh4[zn][0], bh4[zn][2]);
                    mma16816(c[ma][zn*2+1], ah[ma], bh4[zn][1], bh4[zn][3]);
                }
            }
        }
    }
    const int b = bh / HH, h = bh - b*HH;
    h16* Oh = wz ? g_Cqh : g_Ckh;
#pragma unroll
    for (int ma = 0; ma < 2; ma++)
#pragma unroll
    for (int na = 0; na < 8; na++){
        int z = na*8 + tg*2;
#pragma unroll
        for (int half = 0; half < 2; half++){
            int t = t0 + wt2 + ma*16 + gid + half*8;
            size_t adr = ((size_t)b*NN + t)*CC + h*ZZ + z;
            *reinterpret_cast<uint32_t*>(Oh + adr)
                = pack2h(c[ma][na][half*2], c[ma][na][half*2+1]);
        }
    }
}

// ============================ out = Ck U1^T + Cq U2^T + bp (1-term) =========
__global__ __launch_bounds__(256) void k_gemm_out(const float* __restrict__ bp,
                                                  float* __restrict__ out){
    MMA_PRE();
    const int m0 = blockIdx.x*128, n0 = blockIdx.y*128;
    ld_tile_a(sbase, P1_A, g_Ckh + (size_t)m0*CC, 128, CC, tid);
    ld_tile_a(sbase, P1_B, g_U1h + (size_t)n0*CC, 128, CC, tid);
    CP_COMMIT();
    for (int it = 0; it < 24; it++){
        CP_WAIT0();
        __syncthreads();
        if (it + 1 < 24){
            int i2 = it + 1;
            int pr = i2 & 1, kc = i2 >> 1;
            const h16* A = pr ? g_Cqh : g_Ckh;
            const h16* B = pr ? g_U2h : g_U1h;
            int s2 = (i2 & 1) * STGP;
            ld_tile_a(sbase, s2 + P1_A, A + (size_t)m0*CC + kc*64, 128, CC, tid);
            ld_tile_a(sbase, s2 + P1_B, B + (size_t)n0*CC + kc*64, 128, CC, tid);
            CP_COMMIT();
        }
        int st = (it & 1) * STGP;
        mma_chunk1(c, sbase+st+P1_A, sbase+st+P1_B, wm0, wn0, lane);
    }
    const int gid = lane >> 2, tg = lane & 3;
#pragma unroll
    for (int ma = 0; ma < 2; ma++)
#pragma unroll
    for (int na = 0; na < 8; na++){
        int row = m0 + wm0 + ma*16 + gid;
        int col = n0 + wn0 + na*8 + tg*2;
        float b0 = bp[col], b1 = bp[col+1];
        *reinterpret_cast<float2*>(out + (size_t)row*CC + col)
            = make_float2(c[ma][na][0] + b0, c[ma][na][1] + b1);
        *reinterpret_cast<float2*>(out + (size_t)(row+8)*CC + col)
            = make_float2(c[ma][na][2] + b0, c[ma][na][3] + b1);
    }
}

// ============================ host ==========================================
extern "C" void kernel_launch(void* const* d_in, const int* in_sizes, int n_in,
                              void* d_out, int out_size)
{
    (void)in_sizes; (void)n_in; (void)out_size;
    const float* x  = (const float*)d_in[0];
    const float* Wq = (const float*)d_in[1];
    const float* Wk = (const float*)d_in[2];
    const float* Wp = (const float*)d_in[3];
    const float* bp = (const float*)d_in[4];
    float* out = (float*)d_out;

    cudaFuncSetAttribute(k_gemm_fused, cudaFuncAttributeMaxDynamicSharedMemorySize, SMEMP);
    cudaFuncSetAttribute(k_gemm_out,   cudaFuncAttributeMaxDynamicSharedMemorySize, SMEMP);
    cudaFuncSetAttribute(k_statsf,     cudaFuncAttributeMaxDynamicSharedMemorySize, ST_BYTES);
    cudaFuncSetAttribute(k_attn_f,     cudaFuncAttributeMaxDynamicSharedMemorySize, AT_BYTES);

    k_conv_all<<<288, 256>>>(x, Wq, Wk, Wp);
    k_gemm_fused<<<dim3(64, 6, 3), 256, SMEMP>>>();
    k_statsf<<<dim3(8, BH), 256, ST_BYTES>>>();
    k_attn_f<<<dim3(8, BH), 256, AT_BYTES>>>();
    k_gemm_out<<<dim3(64, 6), 256, SMEMP>>>(bp, out);
}

// round 15
// speedup vs baseline: 6.5293x; 1.0810x over previous
#include <cuda_runtime.h>
#include <cuda_fp16.h>
#include <cstdint>
#include <math.h>

#define BB 8
#define NN 1024
#define CC 768
#define HH 12
#define ZZ 64
#define BH (BB*HH)
#define SCALE 0.125f
typedef __half h16;

// ---------------- scratch ----------------
__device__ h16 g_xh[BB*NN*CC];
__device__ h16 g_Wqh[CC*CC], g_Wkh[CC*CC], g_Wph[CC*CC];
__device__ h16 g_U1h[CC*CC], g_U2h[CC*CC];
__device__ h16 g_Qh[BH*NN*ZZ], g_Kh[BH*NN*ZZ];
__device__ float g_m[BH*NN], g_il[BH*NN];
__device__ h16 g_Ckh[BB*NN*CC], g_Cqh[BB*NN*CC];

// ---------------- helpers ----------------
#define SW(o) ((o) ^ (((o)>>3)&0x70))
#define P1_A 0
#define P1_B 16384
#define STGP 32768
#define SMEMP 65536

__device__ __forceinline__ uint32_t smem_u32(const void* p){
    uint32_t a;
    asm("{ .reg .u64 t; cvta.to.shared.u64 t, %1; cvt.u32.u64 %0, t; }" : "=r"(a) : "l"(p));
    return a;
}
__device__ __forceinline__ void ldsm_x4(uint32_t& r0, uint32_t& r1, uint32_t& r2, uint32_t& r3, uint32_t addr){
    asm volatile("ldmatrix.sync.aligned.m8n8.x4.shared.b16 {%0,%1,%2,%3}, [%4];"
        : "=r"(r0), "=r"(r1), "=r"(r2), "=r"(r3) : "r"(addr));
}
__device__ __forceinline__ void ldsm_x4_t(uint32_t& r0, uint32_t& r1, uint32_t& r2, uint32_t& r3, uint32_t addr){
    asm volatile("ldmatrix.sync.aligned.m8n8.x4.trans.shared.b16 {%0,%1,%2,%3}, [%4];"
        : "=r"(r0), "=r"(r1), "=r"(r2), "=r"(r3) : "r"(addr));
}
__device__ __forceinline__ void mma16816(float c[4], const uint32_t a[4], uint32_t b0, uint32_t b1){
    asm volatile("mma.sync.aligned.m16n8k16.row.col.f32.f16.f16.f32 "
        "{%0,%1,%2,%3}, {%4,%5,%6,%7}, {%8,%9}, {%0,%1,%2,%3};"
        : "+f"(c[0]), "+f"(c[1]), "+f"(c[2]), "+f"(c[3])
        : "r"(a[0]), "r"(a[1]), "r"(a[2]), "r"(a[3]), "r"(b0), "r"(b1));
}
__device__ __forceinline__ void cp16(uint32_t saddr, const void* g){
    asm volatile("cp.async.cg.shared.global [%0], [%1], 16;" :: "r"(saddr), "l"(g));
}
#define CP_COMMIT() asm volatile("cp.async.commit_group;" ::: "memory")
#define CP_WAIT0()  asm volatile("cp.async.wait_group 0;" ::: "memory")

__device__ __forceinline__ float fexp(float x){
    float y = x * 1.4426950408889634f;
    float n = rintf(y);
    float f = y - n;
    float p = 1.3333558146428443e-3f;
    p = fmaf(p, f, 9.6181291076284772e-3f);
    p = fmaf(p, f, 5.5504108664821580e-2f);
    p = fmaf(p, f, 2.4022650695910072e-1f);
    p = fmaf(p, f, 6.9314718055994531e-1f);
    p = fmaf(p, f, 1.0f);
    return __int_as_float(__float_as_int(p) + (((int)n) << 23));
}
__device__ __forceinline__ uint32_t pack2h(float a, float b){
    return (uint32_t)__half_as_ushort(__float2half(a))
         | ((uint32_t)__half_as_ushort(__float2half(b)) << 16);
}

// async tile loader: rows x 64 h16 (128B rows), swizzled; nthr cooperating threads
__device__ __forceinline__ void ld_tile_a(uint32_t sbase, int off, const h16* __restrict__ g,
                                          int rows, int rstride, int tid, int nthr){
    for (int i = tid; i < rows*8; i += nthr){
        int r = i >> 3, c = i & 7;
        cp16(sbase + off + SW(r*128 + c*16), g + (size_t)r*rstride + c*8);
    }
}

// 1-term block MMA (both single): block 128x128, warp 32x64 (8 warps)
__device__ __forceinline__ void mma_chunk1(float c[2][8][4],
        uint32_t aH, uint32_t bH, int wm0, int wn0, int lane){
    const int lr = lane & 15, lh = lane >> 4;
#pragma unroll
    for (int ks = 0; ks < 4; ks++){
        uint32_t ah[2][4];
#pragma unroll
        for (int ma = 0; ma < 2; ma++){
            uint32_t off = SW((wm0 + ma*16 + lr)*128 + (ks*2 + lh)*16);
            ldsm_x4(ah[ma][0], ah[ma][1], ah[ma][2], ah[ma][3], aH + off);
        }
        uint32_t bh[4][4];
#pragma unroll
        for (int np = 0; np < 4; np++){
            uint32_t off = SW((wn0 + np*16 + lr)*128 + (ks*2 + lh)*16);
            ldsm_x4(bh[np][0], bh[np][1], bh[np][2], bh[np][3], bH + off);
        }
#pragma unroll
        for (int np = 0; np < 4; np++)
#pragma unroll
        for (int ma = 0; ma < 2; ma++){
            mma16816(c[ma][np*2],   ah[ma], bh[np][0], bh[np][2]);
            mma16816(c[ma][np*2+1], ah[ma], bh[np][1], bh[np][3]);
        }
    }
}

#define MMA_PRE() \
    extern __shared__ char sm[]; \
    const int tid = threadIdx.x, wid = tid >> 5, lane = tid & 31; \
    const uint32_t sbase = smem_u32(sm); \
    const int wm0 = (wid & 3) * 32, wn0 = (wid >> 2) * 64; \
    float c[2][8][4]; \
    _Pragma("unroll") for (int i = 0; i < 2; i++) \
    _Pragma("unroll") for (int j = 0; j < 8; j++) \
    _Pragma("unroll") for (int k = 0; k < 4; k++) c[i][j][k] = 0.0f;

// ============================ fused converter ===============================
#define X4 (BB*NN*CC/4)
#define W4 (CC*CC/4)
__global__ __launch_bounds__(256) void k_conv_all(
    const float* __restrict__ x,  const float* __restrict__ Wq,
    const float* __restrict__ Wk, const float* __restrict__ Wp)
{
    const int total = X4 + 3*W4;
    for (int i = blockIdx.x*blockDim.x + threadIdx.x; i < total; i += gridDim.x*blockDim.x){
        const float* src; h16* dst; int off;
        if (i < X4)            { src = x;  dst = g_xh;  off = i; }
        else if (i < X4+W4)    { src = Wq; dst = g_Wqh; off = i - X4; }
        else if (i < X4+2*W4)  { src = Wk; dst = g_Wkh; off = i - X4 - W4; }
        else                   { src = Wp; dst = g_Wph; off = i - X4 - 2*W4; }
        float4 v = reinterpret_cast<const float4*>(src)[off];
        reinterpret_cast<uint2*>(dst)[off] = make_uint2(pack2h(v.x, v.y), pack2h(v.z, v.w));
    }
}

// ========= fused proj + weight GEMM (all 1-term, single-sync pipeline) ======
__global__ __launch_bounds__(256) void k_gemm_fused(){
    const int zid = blockIdx.z;
    const bool isw = (zid == 2);
    if (isw && blockIdx.x >= 12) return;
    MMA_PRE();
    const int n0 = blockIdx.y*128;
    int m0, sel = 0;
    const h16 *A, *B;
    if (!isw){
        m0 = blockIdx.x*128;
        A = g_xh + (size_t)m0*CC;
        B = (zid ? g_Wkh : g_Wqh) + (size_t)n0*CC;
    } else {
        sel = blockIdx.x >= 6;
        m0 = (blockIdx.x - (sel ? 6 : 0))*128;
        A = g_Wph + (size_t)m0*CC;
        B = (sel ? g_Wkh : g_Wqh) + (size_t)n0*CC;
    }
    ld_tile_a(sbase, P1_A, A, 128, CC, tid, 256);
    ld_tile_a(sbase, P1_B, B, 128, CC, tid, 256);
    CP_COMMIT();
    for (int kc = 0; kc < 12; kc++){
        CP_WAIT0();
        __syncthreads();
        if (kc + 1 < 12){
            int s2 = ((kc+1) & 1) * STGP;
            ld_tile_a(sbase, s2 + P1_A, A + (kc+1)*64, 128, CC, tid, 256);
            ld_tile_a(sbase, s2 + P1_B, B + (kc+1)*64, 128, CC, tid, 256);
            CP_COMMIT();
        }
        int st = (kc & 1) * STGP;
        mma_chunk1(c, sbase+st+P1_A, sbase+st+P1_B, wm0, wn0, lane);
    }
    const int gid = lane >> 2, tg = lane & 3;
    if (!isw){
        h16* Oh = zid ? g_Kh : g_Qh;
#pragma unroll
        for (int ma = 0; ma < 2; ma++)
#pragma unroll
        for (int na = 0; na < 8; na++){
            int col = n0 + wn0 + na*8 + tg*2;
            int h = col >> 6, z = col & 63;
#pragma unroll
            for (int half = 0; half < 2; half++){
                int row = m0 + wm0 + ma*16 + gid + half*8;
                int b = row >> 10, tk = row & (NN-1);
                size_t adr = ((size_t)(b*HH + h)*NN + tk)*ZZ + z;
                *reinterpret_cast<uint32_t*>(Oh + adr)
                    = pack2h(c[ma][na][half*2], c[ma][na][half*2+1]);
            }
        }
    } else {
        h16* Oh = sel ? g_U2h : g_U1h;
#pragma unroll
        for (int ma = 0; ma < 2; ma++)
#pragma unroll
        for (int na = 0; na < 8; na++){
            int row = m0 + wm0 + ma*16 + gid;
            int col = n0 + wn0 + na*8 + tg*2;
            *reinterpret_cast<uint32_t*>(Oh + (size_t)row*CC + col)
                = pack2h(c[ma][na][0], c[ma][na][1]);
            *reinterpret_cast<uint32_t*>(Oh + (size_t)(row+8)*CC + col)
                = pack2h(c[ma][na][2], c[ma][na][3]);
        }
    }
}

// ============================ flash stats (1-term S, cp.async K) ============
#define ST_QH 0
#define ST_KH0 16384
#define ST_KH1 32768
#define ST_MM 49152
#define ST_LL 50176
#define ST_BYTES 51200
__global__ __launch_bounds__(256) void k_statsf(){
    extern __shared__ char sm[];
    const int tid = threadIdx.x, wid = tid >> 5, lane = tid & 31;
    const uint32_t sbase = smem_u32(sm);
    const int bh = blockIdx.y, q0 = blockIdx.x*128;
    const int wq = (wid & 3)*32, wt = (wid >> 2)*64;
    const int gid = lane >> 2, tg = lane & 3;

    ld_tile_a(sbase, ST_QH,  g_Qh + ((size_t)bh*NN + q0)*ZZ, 128, ZZ, tid, 256);
    ld_tile_a(sbase, ST_KH0, g_Kh + (size_t)bh*NN*ZZ,        128, ZZ, tid, 256);
    CP_COMMIT();

    float rm[2][2], rl[2][2];
#pragma unroll
    for (int i = 0; i < 2; i++)
#pragma unroll
    for (int j = 0; j < 2; j++){ rm[i][j] = -1e30f; rl[i][j] = 0.0f; }

    for (int it = 0; it < 8; it++){
        CP_WAIT0();
        __syncthreads();
        if (it + 1 < 8){
            int kb = ((it+1) & 1) ? ST_KH1 : ST_KH0;
            ld_tile_a(sbase, kb, g_Kh + ((size_t)bh*NN + (it+1)*128)*ZZ, 128, ZZ, tid, 256);
            CP_COMMIT();
        }
        int kcur = (it & 1) ? ST_KH1 : ST_KH0;

        float s[2][8][4];
#pragma unroll
        for (int i = 0; i < 2; i++)
#pragma unroll
        for (int j = 0; j < 8; j++)
#pragma unroll
        for (int k = 0; k < 4; k++) s[i][j][k] = 0.0f;

        mma_chunk1(s, sbase+ST_QH, sbase+kcur, wq, wt, lane);

#pragma unroll
        for (int ma = 0; ma < 2; ma++)
#pragma unroll
        for (int half = 0; half < 2; half++){
            float cm = -1e30f;
#pragma unroll
            for (int na = 0; na < 8; na++)
                cm = fmaxf(cm, fmaxf(s[ma][na][half*2], s[ma][na][half*2+1]));
            cm *= SCALE;
            cm = fmaxf(cm, __shfl_xor_sync(0xffffffffu, cm, 1));
            cm = fmaxf(cm, __shfl_xor_sync(0xffffffffu, cm, 2));
            float nm = fmaxf(rm[ma][half], cm);
            float ls = 0.0f;
#pragma unroll
            for (int na = 0; na < 8; na++)
                ls += fexp(s[ma][na][half*2]*SCALE - nm) + fexp(s[ma][na][half*2+1]*SCALE - nm);
            ls += __shfl_xor_sync(0xffffffffu, ls, 1);
            ls += __shfl_xor_sync(0xffffffffu, ls, 2);
            float d = fmaxf(rm[ma][half] - nm, -60.0f);
            rl[ma][half] = rl[ma][half]*fexp(d) + ls;
            rm[ma][half] = nm;
        }
    }
    float* smm = reinterpret_cast<float*>(sm + ST_MM);
    float* sml = reinterpret_cast<float*>(sm + ST_LL);
    __syncthreads();
    if (tg == 0){
#pragma unroll
        for (int ma = 0; ma < 2; ma++)
#pragma unroll
        for (int half = 0; half < 2; half++){
            int q = wq + ma*16 + gid + half*8;
            int wti = wid >> 2;
            smm[wti*128 + q] = rm[ma][half];
            sml[wti*128 + q] = rl[ma][half];
        }
    }
    __syncthreads();
    if (tid < 128){
        float m0 = smm[tid], m1 = smm[128 + tid];
        float l0 = sml[tid], l1 = sml[128 + tid];
        float m = fmaxf(m0, m1);
        float l = l0*fexp(fmaxf(m0 - m, -60.0f)) + l1*fexp(fmaxf(m1 - m, -60.0f));
        g_m [bh*NN + q0 + tid] = m;
        g_il[bh*NN + q0 + tid] = 1.0f / l;
    }
}

// ============================ fused attention pass (512 threads) ============
// phase1: 16 warps = 2 q-warps x 8 t-warps, each 32q x 16t
// phase2: 16 warps = 2 out x 8 t-warps, each 16t x 64z (c[8][4] = 32 regs)
#define AT_KTH 0
#define AT_QC0 16384
#define AT_KC0 24576
#define AT_QC1 32768
#define AT_KC1 40960
#define AT_PH  49152
#define AT_MS  65536
#define AT_IL  66048
#define AT_BYTES 66560
__global__ __launch_bounds__(512) void k_attn_f(){
    extern __shared__ char sm[];
    const int tid = threadIdx.x, wid = tid >> 5, lane = tid & 31;
    const uint32_t sbase = smem_u32(sm);
    const int bh = blockIdx.y, t0 = blockIdx.x*128;
    const int gid = lane >> 2, tg = lane & 3;
    const int lr = lane & 15, lh = lane >> 4;
    const int srow_off = (lane & 7) + ((lane & 16) ? 8 : 0);
    const int scol8 = ((lane >> 3) & 1) * 8;
    float* ms = reinterpret_cast<float*>(sm + AT_MS);
    float* il = reinterpret_cast<float*>(sm + AT_IL);

    // phase2 mapping: warps 0-7 -> Ck (wz=0), 8-15 -> Cq; 16 t-rows each
    const int wz = wid >> 3, wt2 = (wid & 7)*16;
    float c[8][4];
#pragma unroll
    for (int j = 0; j < 8; j++)
#pragma unroll
    for (int k = 0; k < 4; k++) c[j][k] = 0.0f;

    // phase1 mapping: 2 q-warps x 8 t-warps
    const int wq1 = (wid & 1)*32, wt1 = (wid >> 1)*16;

    ld_tile_a(sbase, AT_KTH, g_Kh + ((size_t)bh*NN + t0)*ZZ, 128, ZZ, tid, 512);
    ld_tile_a(sbase, AT_QC0, g_Qh + (size_t)bh*NN*ZZ, 64, ZZ, tid, 512);
    ld_tile_a(sbase, AT_KC0, g_Kh + (size_t)bh*NN*ZZ, 64, ZZ, tid, 512);
    if (tid < 64)       ms[tid]      = g_m [bh*NN + tid];
    else if (tid < 128) il[tid - 64] = g_il[bh*NN + tid - 64];
    CP_COMMIT();

    for (int j = 0; j < 16; j++){
        const int nb = j & 1;
        const int qcb = nb ? AT_QC1 : AT_QC0;
        const int kcb = nb ? AT_KC1 : AT_KC0;
        CP_WAIT0();
        __syncthreads();
        if (j + 1 < 16){
            int q2 = (j+1)*64, b2 = (j+1) & 1;
            ld_tile_a(sbase, b2 ? AT_QC1 : AT_QC0, g_Qh + ((size_t)bh*NN + q2)*ZZ, 64, ZZ, tid, 512);
            ld_tile_a(sbase, b2 ? AT_KC1 : AT_KC0, g_Kh + ((size_t)bh*NN + q2)*ZZ, 64, ZZ, tid, 512);
            if (tid < 64)       ms[b2*64 + tid]      = g_m [bh*NN + q2 + tid];
            else if (tid < 128) il[b2*64 + tid - 64] = g_il[bh*NN + q2 + tid - 64];
            CP_COMMIT();
        }

        // ---- phase 1: S chunk (1-term) -> P smem (hi fp16); warp 32q x 16t ----
        {
            float s1[2][2][4];
#pragma unroll
            for (int i = 0; i < 2; i++)
#pragma unroll
            for (int jj = 0; jj < 2; jj++)
#pragma unroll
            for (int k = 0; k < 4; k++) s1[i][jj][k] = 0.0f;
#pragma unroll
            for (int ks = 0; ks < 4; ks++){
                uint32_t ah[2][4];
#pragma unroll
                for (int ma = 0; ma < 2; ma++){
                    uint32_t off = SW((wq1 + ma*16 + lr)*128 + (ks*2 + lh)*16);
                    ldsm_x4(ah[ma][0], ah[ma][1], ah[ma][2], ah[ma][3], sbase + qcb + off);
                }
                uint32_t bh4[4];
                {
                    uint32_t off = SW((wt1 + lr)*128 + (ks*2 + lh)*16);
                    ldsm_x4(bh4[0], bh4[1], bh4[2], bh4[3], sbase + AT_KTH + off);
                }
#pragma unroll
                for (int ma = 0; ma < 2; ma++){
                    mma16816(s1[ma][0], ah[ma], bh4[0], bh4[2]);
                    mma16816(s1[ma][1], ah[ma], bh4[1], bh4[3]);
                }
            }
#pragma unroll
            for (int ma = 0; ma < 2; ma++)
#pragma unroll
            for (int na = 0; na < 2; na++)
#pragma unroll
            for (int half = 0; half < 2; half++){
                int qloc = wq1 + ma*16 + gid + half*8;
                float M = ms[nb*64 + qloc], I = il[nb*64 + qloc];
                int tloc = wt1 + na*8 + tg*2;
                float p0 = fexp(s1[ma][na][half*2]  *SCALE - M)*I;
                float p1 = fexp(s1[ma][na][half*2+1]*SCALE - M)*I;
                uint32_t off = (uint32_t)(tloc >> 6)*8192 + SW(qloc*128 + (tloc & 63)*2);
                *reinterpret_cast<uint32_t*>(sm + AT_PH + off) = pack2h(p0, p1);
            }
        }
        __syncthreads();

        // ---- phase 2: Ck/Cq += P^T [K|Q]; warp 16t x 64z ----
        {
            const int bsh = wz ? qcb : kcb;
#pragma unroll
            for (int ks = 0; ks < 4; ks++){
                int qk = ks*16;
                uint32_t ah[4];
                {
                    uint32_t off = (uint32_t)(wt2 >> 6)*8192
                                 + SW((qk + srow_off)*128 + ((wt2 & 63) + scol8)*2);
                    ldsm_x4_t(ah[0], ah[1], ah[2], ah[3], sbase + AT_PH + off);
                }
                uint32_t bh4[4][4];
#pragma unroll
                for (int zn = 0; zn < 4; zn++){
                    uint32_t off = SW((qk + srow_off)*128 + (zn*16 + scol8)*2);
                    ldsm_x4_t(bh4[zn][0], bh4[zn][1], bh4[zn][2], bh4[zn][3], sbase + bsh + off);
                }
#pragma unroll
                for (int zn = 0; zn < 4; zn++){
                    mma16816(c[zn*2],   ah, bh4[zn][0], bh4[zn][2]);
                    mma16816(c[zn*2+1], ah, bh4[zn][1], bh4[zn][3]);
                }
            }
        }
    }
    const int b = bh / HH, h = bh - b*HH;
    h16* Oh = wz ? g_Cqh : g_Ckh;
#pragma unroll
    for (int na = 0; na < 8; na++){
        int z = na*8 + tg*2;
#pragma unroll
        for (int half = 0; half < 2; half++){
            int t = t0 + wt2 + gid + half*8;
            size_t adr = ((size_t)b*NN + t)*CC + h*ZZ + z;
            *reinterpret_cast<uint32_t*>(Oh + adr)
                = pack2h(c[na][half*2], c[na][half*2+1]);
        }
    }
}

// ============================ out = Ck U1^T + Cq U2^T + bp (1-term) =========
__global__ __launch_bounds__(256) void k_gemm_out(const float* __restrict__ bp,
                                                  float* __restrict__ out){
    MMA_PRE();
    const int m0 = blockIdx.x*128, n0 = blockIdx.y*128;
    ld_tile_a(sbase, P1_A, g_Ckh + (size_t)m0*CC, 128, CC, tid, 256);
    ld_tile_a(sbase, P1_B, g_U1h + (size_t)n0*CC, 128, CC, tid, 256);
    CP_COMMIT();
    for (int it = 0; it < 24; it++){
        CP_WAIT0();
        __syncthreads();
        if (it + 1 < 24){
            int i2 = it + 1;
            int pr = i2 & 1, kc = i2 >> 1;
            const h16* A = pr ? g_Cqh : g_Ckh;
            const h16* B = pr ? g_U2h : g_U1h;
            int s2 = (i2 & 1) * STGP;
            ld_tile_a(sbase, s2 + P1_A, A + (size_t)m0*CC + kc*64, 128, CC, tid, 256);
            ld_tile_a(sbase, s2 + P1_B, B + (size_t)n0*CC + kc*64, 128, CC, tid, 256);
            CP_COMMIT();
        }
        int st = (it & 1) * STGP;
        mma_chunk1(c, sbase+st+P1_A, sbase+st+P1_B, wm0, wn0, lane);
    }
    const int gid = lane >> 2, tg = lane & 3;
#pragma unroll
    for (int ma = 0; ma < 2; ma++)
#pragma unroll
    for (int na = 0; na < 8; na++){
        int row = m0 + wm0 + ma*16 + gid;
        int col = n0 + wn0 + na*8 + tg*2;
        float b0 = bp[col], b1 = bp[col+1];
        *reinterpret_cast<float2*>(out + (size_t)row*CC + col)
            = make_float2(c[ma][na][0] + b0, c[ma][na][1] + b1);
        *reinterpret_cast<float2*>(out + (size_t)(row+8)*CC + col)
            = make_float2(c[ma][na][2] + b0, c[ma][na][3] + b1);
    }
}

// ============================ host ==========================================
extern "C" void kernel_launch(void* const* d_in, const int* in_sizes, int n_in,
                              void* d_out, int out_size)
{
    (void)in_sizes; (void)n_in; (void)out_size;
    const float* x  = (const float*)d_in[0];
    const float* Wq = (const float*)d_in[1];
    const float* Wk = (const float*)d_in[2];
    const float* Wp = (const float*)d_in[3];
    const float* bp = (const float*)d_in[4];
    float* out = (float*)d_out;

    cudaFuncSetAttribute(k_gemm_fused, cudaFuncAttributeMaxDynamicSharedMemorySize, SMEMP);
    cudaFuncSetAttribute(k_gemm_out,   cudaFuncAttributeMaxDynamicSharedMemorySize, SMEMP);
    cudaFuncSetAttribute(k_statsf,     cudaFuncAttributeMaxDynamicSharedMemorySize, ST_BYTES);
    cudaFuncSetAttribute(k_attn_f,     cudaFuncAttributeMaxDynamicSharedMemorySize, AT_BYTES);

    k_conv_all<<<288, 256>>>(x, Wq, Wk, Wp);
    k_gemm_fused<<<dim3(64, 6, 3), 256, SMEMP>>>();
    k_statsf<<<dim3(8, BH), 256, ST_BYTES>>>();
    k_attn_f<<<dim3(8, BH), 512, AT_BYTES>>>();
    k_gemm_out<<<dim3(64, 6), 256, SMEMP>>>(bp, out);
}